// round 12
// baseline (speedup 1.0000x reference)
#include <cuda_runtime.h>
#include <cuda_fp16.h>
#include <math.h>
#include <stdint.h>

// Problem constants
#define TT   243
#define PP   17
#define LL   4
#define CC   128
#define HH   8
#define NPT  4
#define DHH  16
#define BB   2
#define LQ   (TT*PP*LL)        // 16524
#define BLQ  (BB*LQ)           // 33048
#define NLVL 5
#define BTP  (BB*TT*PP)        // 8262
#define TOK  (BTP*NLVL)        // 41310
#define SS   (PP*NLVL)         // 85

// ---------------- scratch (device globals; no allocations) ----------------
__device__ float  g_XCAT [(size_t)TOK*CC];
__device__ float  g_XCAT2[(size_t)TOK*CC];
__device__ __half g_OFFAWh[(size_t)BLQ*384];
__device__ __half g_Qh   [(size_t)BLQ*CC];
__device__ __half g_XNh  [(size_t)BLQ*CC];
__device__ __half g_VALh [(size_t)BLQ*CC];
__device__ __half g_Oh   [(size_t)BLQ*CC];
__device__ __half g_XN2h [(size_t)TOK*CC];
__device__ __half g_QKVh [(size_t)TOK*384];
__device__ __half g_ATTOh[(size_t)TOK*CC];
__device__ __half g_XN3h [(size_t)TOK*CC];
__device__ __half g_HIDh [(size_t)TOK*512];
#define WOFF_OFF   0
#define WOFF_ATTN  32768
#define WOFF_VAL   49152
#define WOFF_OUT   65536
#define WOFF_IN    81920
#define WOFF_OUTW  131072
#define WOFF_FC1   147456
#define WOFF_FC2   212992
#define WTOTAL     278528
__device__ __half g_Wh[WTOTAL];
__device__ float  g_Bcat[384];

// ---------------- PTX helpers ----------------------------------------------
__device__ __forceinline__ void cpa16(uint32_t dst, const void* src, bool valid) {
    int sz = valid ? 16 : 0;
    asm volatile("cp.async.cg.shared.global [%0], [%1], 16, %2;\n"
                 :: "r"(dst), "l"(src), "r"(sz));
}
#define CP_COMMIT() asm volatile("cp.async.commit_group;\n" ::: "memory")
#define CP_WAIT(n)  asm volatile("cp.async.wait_group %0;\n" :: "n"(n) : "memory")

__device__ __forceinline__ void ldm4(uint32_t* r, uint32_t addr) {
    asm volatile("ldmatrix.sync.aligned.m8n8.x4.shared.b16 {%0,%1,%2,%3}, [%4];\n"
                 : "=r"(r[0]), "=r"(r[1]), "=r"(r[2]), "=r"(r[3]) : "r"(addr));
}
__device__ __forceinline__ void mma16(float* c, const uint32_t* a, const uint32_t* b) {
    asm volatile("mma.sync.aligned.m16n8k16.row.col.f32.f16.f16.f32 "
                 "{%0,%1,%2,%3},{%4,%5,%6,%7},{%8,%9},{%0,%1,%2,%3};\n"
                 : "+f"(c[0]), "+f"(c[1]), "+f"(c[2]), "+f"(c[3])
                 : "r"(a[0]), "r"(a[1]), "r"(a[2]), "r"(a[3]), "r"(b[0]), "r"(b[1]));
}

// PDL device primitives (sm_90+)
__device__ __forceinline__ void pdl_wait()    { cudaGridDependencySynchronize(); }
__device__ __forceinline__ void pdl_trigger() { cudaTriggerProgrammaticLaunchCompletion(); }

// permuted destination row for the xcat concat (also the x source row!)
__device__ __forceinline__ int xcat_row(int gm) {
    int b = gm / LQ;
    int rem = gm - b * LQ;
    return (b * (TT * PP) + (rem >> 2)) * 5 + (rem & 3) + 1;
}

// ============================================================================
// BIG GEMM: BM=128, BN=128, BK=64, 256 threads (QKV / FC1 / FC2).
// W loads of stage 0 issued BEFORE griddepsync (g_Wh written >=2 kernels back).
// ============================================================================
#define BIG_STG  32768
#define BIG_SMEM 65536

__device__ __forceinline__ void big_load_W(
    const __half* __restrict__ W, uint32_t sb, int st, int kt, int col0, int K, int tid)
{
    const int r0 = tid >> 3, ck = tid & 7;
    const uint32_t base = sb + st * BIG_STG + 16384;
#pragma unroll
    for (int i = 0; i < 4; i++) {
        int r = r0 + i * 32;
        uint32_t swoff = (uint32_t)(r * 128 + ((ck ^ (r & 7)) * 16));
        cpa16(base + swoff, W + (size_t)(col0 + r) * K + (size_t)kt * 64 + ck * 8, true);
    }
}
__device__ __forceinline__ void big_load_A(
    const __half* __restrict__ A, uint32_t sb, int st, int kt, int row0, int M, int K, int tid)
{
    const int r0 = tid >> 3, ck = tid & 7;
    const uint32_t base = sb + st * BIG_STG;
#pragma unroll
    for (int i = 0; i < 4; i++) {
        int r = r0 + i * 32;
        uint32_t swoff = (uint32_t)(r * 128 + ((ck ^ (r & 7)) * 16));
        int gm = row0 + r;
        cpa16(base + swoff, A + (size_t)gm * K + (size_t)kt * 64 + ck * 8, gm < M);
    }
}

__global__ __launch_bounds__(256, 2) void k_gemm_big(
    const __half* __restrict__ A, const __half* __restrict__ W,
    const float* __restrict__ bias, const float* __restrict__ res,
    void* __restrict__ outp, int M, int N, int K, int epi, int outHalf)
{
    extern __shared__ __align__(1024) char sm[];
    uint32_t sb = (uint32_t)__cvta_generic_to_shared(sm);
    const int tid = threadIdx.x, lane = tid & 31, warp = tid >> 5;
    const int g = lane >> 2, t = lane & 3;
    const int wm = (warp >> 1) * 32, wn = (warp & 1) * 64;
    const int row0 = blockIdx.y * 128, col0 = blockIdx.x * 128;
    const int KT = K >> 6;

    float acc[2][8][4];
#pragma unroll
    for (int mi = 0; mi < 2; mi++)
#pragma unroll
        for (int ni = 0; ni < 8; ni++)
#pragma unroll
            for (int r = 0; r < 4; r++) acc[mi][ni][r] = 0.f;

    big_load_W(W, sb, 0, 0, col0, K, tid);   // independent of predecessor
    pdl_wait();                               // wait for predecessor outputs
    big_load_A(A, sb, 0, 0, row0, M, K, tid);
    CP_COMMIT();

    for (int kt = 0; kt < KT; kt++) {
        const int s = kt & 1;
        if (kt + 1 < KT) {
            big_load_A(A, sb, s ^ 1, kt + 1, row0, M, K, tid);
            big_load_W(W, sb, s ^ 1, kt + 1, col0, K, tid);
            CP_COMMIT();
            CP_WAIT(1);
        } else {
            CP_WAIT(0);
        }
        __syncthreads();

        const uint32_t aS = sb + s * BIG_STG;
        const uint32_t bS = aS + 16384;
        const int rlow = lane & 15, hi = lane >> 4;
#pragma unroll
        for (int kk = 0; kk < 4; kk++) {
            uint32_t af[2][4];
#pragma unroll
            for (int mi = 0; mi < 2; mi++) {
                int r = wm + mi * 16 + rlow;
                int ck = kk * 2 + hi;
                ldm4(af[mi], aS + (uint32_t)(r * 128 + ((ck ^ (r & 7)) * 16)));
            }
            uint32_t bf[8][2];
#pragma unroll
            for (int nj = 0; nj < 4; nj++) {
                int r = wn + nj * 16 + rlow;
                int ck = kk * 2 + hi;
                uint32_t q[4];
                ldm4(q, bS + (uint32_t)(r * 128 + ((ck ^ (r & 7)) * 16)));
                bf[nj * 2 + 0][0] = q[0]; bf[nj * 2 + 0][1] = q[2];
                bf[nj * 2 + 1][0] = q[1]; bf[nj * 2 + 1][1] = q[3];
            }
#pragma unroll
            for (int mi = 0; mi < 2; mi++)
#pragma unroll
                for (int ni = 0; ni < 8; ni++)
                    mma16(acc[mi][ni], af[mi], bf[ni]);
        }
        __syncthreads();
    }

#pragma unroll
    for (int mi = 0; mi < 2; mi++) {
#pragma unroll
        for (int r = 0; r < 2; r++) {
            const int gm = row0 + wm + mi * 16 + g + r * 8;
            if (gm >= M) continue;
            const float* rp = res + (size_t)gm * N;
#pragma unroll
            for (int ni = 0; ni < 8; ni++) {
                const int gn = col0 + wn + ni * 8 + 2 * t;
                float v0 = acc[mi][ni][r * 2 + 0] + bias[gn];
                float v1 = acc[mi][ni][r * 2 + 1] + bias[gn + 1];
                if (epi == 1) {
                    v0 += rp[gn];
                    v1 += rp[gn + 1];
                } else if (epi == 2) {
                    v0 = 0.5f * v0 * (1.0f + erff(v0 * 0.7071067811865475f));
                    v1 = 0.5f * v1 * (1.0f + erff(v1 * 0.7071067811865475f));
                }
                if (outHalf) {
                    *(__half2*)((__half*)outp + (size_t)gm * N + gn) = __floats2half2_rn(v0, v1);
                } else {
                    *(float2*)((float*)outp + (size_t)gm * N + gn) = make_float2(v0, v1);
                }
            }
        }
    }
    pdl_trigger();
}

// ============================================================================
// SMALL GEMM: BM=64, BN=128, BK=64, 128 threads; epi3 = residual + LN fusion.
// ============================================================================
#define STG 24576
#define SREDOFF 49152
#define GEMM_SMEM 50176

__device__ __forceinline__ void small_load_W(
    const __half* __restrict__ W, uint32_t sb, int st, int kt, int col0, int K, int tid)
{
    const int r0 = tid >> 3, ck = tid & 7;
    const uint32_t base = sb + st * STG + 8192;
#pragma unroll
    for (int i = 0; i < 8; i++) {
        int r = r0 + i * 16;
        uint32_t swoff = (uint32_t)(r * 128 + ((ck ^ (r & 7)) * 16));
        cpa16(base + swoff, W + (size_t)(col0 + r) * K + (size_t)kt * 64 + ck * 8, true);
    }
}
__device__ __forceinline__ void small_load_A(
    const __half* __restrict__ A, uint32_t sb, int st, int kt, int row0, int M, int K, int tid)
{
    const int r0 = tid >> 3, ck = tid & 7;
    const uint32_t base = sb + st * STG;
#pragma unroll
    for (int i = 0; i < 4; i++) {
        int r = r0 + i * 16;
        uint32_t swoff = (uint32_t)(r * 128 + ((ck ^ (r & 7)) * 16));
        int gm = row0 + r;
        cpa16(base + swoff, A + (size_t)gm * K + (size_t)kt * 64 + ck * 8, gm < M);
    }
}

// waitFirst: 1 -> griddepsync before anything (used by k_projs path via k_gemm_h? no; kept simple)
__global__ __launch_bounds__(128, 4) void k_gemm_h(
    const __half* __restrict__ A, const __half* __restrict__ W,
    const float* __restrict__ bias, const float* __restrict__ res,
    void* __restrict__ outp, int M, int N, int K, int epi, int outHalf, int perm,
    const float* __restrict__ lnG, const float* __restrict__ lnB,
    __half* __restrict__ out2)
{
    extern __shared__ __align__(1024) char sm[];
    uint32_t sb = (uint32_t)__cvta_generic_to_shared(sm);
    float* sred = (float*)(sm + SREDOFF);
    const int tid = threadIdx.x, lane = tid & 31, warp = tid >> 5;
    const int g = lane >> 2, t = lane & 3;
    const int wm = (warp >> 1) * 32, wn = (warp & 1) * 64;
    const int row0 = blockIdx.y * 64, col0 = blockIdx.x * 128;
    const int KT = K >> 6;

    float acc[2][8][4];
#pragma unroll
    for (int mi = 0; mi < 2; mi++)
#pragma unroll
        for (int ni = 0; ni < 8; ni++)
#pragma unroll
            for (int r = 0; r < 4; r++) acc[mi][ni][r] = 0.f;

    small_load_W(W, sb, 0, 0, col0, K, tid);  // g_Wh written >=2 kernels back
    pdl_wait();
    small_load_A(A, sb, 0, 0, row0, M, K, tid);
    CP_COMMIT();

    for (int kt = 0; kt < KT; kt++) {
        const int s = kt & 1;
        if (kt + 1 < KT) {
            small_load_A(A, sb, s ^ 1, kt + 1, row0, M, K, tid);
            small_load_W(W, sb, s ^ 1, kt + 1, col0, K, tid);
            CP_COMMIT();
            CP_WAIT(1);
        } else {
            CP_WAIT(0);
        }
        __syncthreads();

        const uint32_t aS = sb + s * STG;
        const uint32_t bS = aS + 8192;
        const int rlow = lane & 15, hi = lane >> 4;
#pragma unroll
        for (int kk = 0; kk < 4; kk++) {
            uint32_t af[2][4];
#pragma unroll
            for (int mi = 0; mi < 2; mi++) {
                int r = wm + mi * 16 + rlow;
                int ck = kk * 2 + hi;
                ldm4(af[mi], aS + (uint32_t)(r * 128 + ((ck ^ (r & 7)) * 16)));
            }
            uint32_t bf[8][2];
#pragma unroll
            for (int nj = 0; nj < 4; nj++) {
                int r = wn + nj * 16 + rlow;
                int ck = kk * 2 + hi;
                uint32_t q[4];
                ldm4(q, bS + (uint32_t)(r * 128 + ((ck ^ (r & 7)) * 16)));
                bf[nj * 2 + 0][0] = q[0]; bf[nj * 2 + 0][1] = q[2];
                bf[nj * 2 + 1][0] = q[1]; bf[nj * 2 + 1][1] = q[3];
            }
#pragma unroll
            for (int mi = 0; mi < 2; mi++)
#pragma unroll
                for (int ni = 0; ni < 8; ni++)
                    mma16(acc[mi][ni], af[mi], bf[ni]);
        }
        __syncthreads();
    }

#pragma unroll
    for (int mi = 0; mi < 2; mi++) {
#pragma unroll
        for (int r = 0; r < 2; r++) {
            const int gm = row0 + wm + mi * 16 + g + r * 8;
            float psum = 0.f, psq = 0.f;
            if (gm < M) {
                const size_t orow = (epi == 3 && perm) ? (size_t)xcat_row(gm) : (size_t)gm;
                const float* rp = res + orow * N;
#pragma unroll
                for (int ni = 0; ni < 8; ni++) {
                    const int gn = col0 + wn + ni * 8 + 2 * t;
                    float v0 = acc[mi][ni][r * 2 + 0] + bias[gn];
                    float v1 = acc[mi][ni][r * 2 + 1] + bias[gn + 1];
                    if (epi == 1 || epi == 3) {
                        v0 += rp[gn];
                        v1 += rp[gn + 1];
                    } else if (epi == 2) {
                        v0 = 0.5f * v0 * (1.0f + erff(v0 * 0.7071067811865475f));
                        v1 = 0.5f * v1 * (1.0f + erff(v1 * 0.7071067811865475f));
                    }
                    if (outHalf) {
                        *(__half2*)((__half*)outp + orow * N + gn) = __floats2half2_rn(v0, v1);
                    } else {
                        *(float2*)((float*)outp + orow * N + gn) = make_float2(v0, v1);
                    }
                    acc[mi][ni][r * 2 + 0] = v0;
                    acc[mi][ni][r * 2 + 1] = v1;
                    psum += v0 + v1;
                    psq  += v0 * v0 + v1 * v1;
                }
            }
            if (epi == 3) {
                psum += __shfl_xor_sync(0xffffffffu, psum, 1);
                psum += __shfl_xor_sync(0xffffffffu, psum, 2);
                psq  += __shfl_xor_sync(0xffffffffu, psq, 1);
                psq  += __shfl_xor_sync(0xffffffffu, psq, 2);
                if (t == 0) {
                    int lr = wm + mi * 16 + g + r * 8;
                    sred[lr * 4 + (warp & 1) * 2 + 0] = psum;
                    sred[lr * 4 + (warp & 1) * 2 + 1] = psq;
                }
            }
        }
    }
    if (epi == 3) {
        __syncthreads();
#pragma unroll
        for (int mi = 0; mi < 2; mi++) {
#pragma unroll
            for (int r = 0; r < 2; r++) {
                const int gm = row0 + wm + mi * 16 + g + r * 8;
                if (gm >= M) continue;
                const size_t orow = perm ? (size_t)xcat_row(gm) : (size_t)gm;
                const int lr = wm + mi * 16 + g + r * 8;
                float sum = sred[lr * 4 + 0] + sred[lr * 4 + 2];
                float sq  = sred[lr * 4 + 1] + sred[lr * 4 + 3];
                float mean = sum * (1.f / 128.f);
                float var = sq * (1.f / 128.f) - mean * mean;
                float rstd = rsqrtf(var + 1e-5f);
#pragma unroll
                for (int ni = 0; ni < 8; ni++) {
                    const int gn = col0 + wn + ni * 8 + 2 * t;
                    float a0 = (acc[mi][ni][r * 2 + 0] - mean) * rstd * lnG[gn] + lnB[gn];
                    float a1 = (acc[mi][ni][r * 2 + 1] - mean) * rstd * lnG[gn + 1] + lnB[gn + 1];
                    *(__half2*)(out2 + orow * 128 + gn) = __floats2half2_rn(a0, a1);
                }
            }
        }
    }
    pdl_trigger();
}

// ============================================================================
// Merged projection GEMM: offaw (N=384, cols 0-2) + val (N=128, col 3).
// Predecessor is k_pre (writes g_Wh AND A) -> full sync at top.
// ============================================================================
__global__ __launch_bounds__(128, 4) void k_projs(const float* __restrict__ b_val)
{
    extern __shared__ __align__(1024) char sm[];
    uint32_t sb = (uint32_t)__cvta_generic_to_shared(sm);
    const int tid = threadIdx.x, lane = tid & 31, warp = tid >> 5;
    const int g = lane >> 2, t = lane & 3;
    const int wm = (warp >> 1) * 32, wn = (warp & 1) * 64;
    const int row0 = blockIdx.y * 64;

    const __half* A; const __half* W; const float* bias; __half* outp; int N; int col0;
    if (blockIdx.x < 3) {
        A = g_Qh;  W = g_Wh + WOFF_OFF; bias = g_Bcat; outp = g_OFFAWh;
        N = 384; col0 = blockIdx.x * 128;
    } else {
        A = g_XNh; W = g_Wh + WOFF_VAL; bias = b_val;  outp = g_VALh;
        N = 128; col0 = 0;
    }
    const int M = BLQ, K = CC, KT = 2;

    pdl_wait();   // everything depends on k_pre

    float acc[2][8][4];
#pragma unroll
    for (int mi = 0; mi < 2; mi++)
#pragma unroll
        for (int ni = 0; ni < 8; ni++)
#pragma unroll
            for (int r = 0; r < 4; r++) acc[mi][ni][r] = 0.f;

    small_load_W(W, sb, 0, 0, col0, K, tid);
    small_load_A(A, sb, 0, 0, row0, M, K, tid);
    CP_COMMIT();

    for (int kt = 0; kt < KT; kt++) {
        const int s = kt & 1;
        if (kt + 1 < KT) {
            small_load_A(A, sb, s ^ 1, kt + 1, row0, M, K, tid);
            small_load_W(W, sb, s ^ 1, kt + 1, col0, K, tid);
            CP_COMMIT();
            CP_WAIT(1);
        } else {
            CP_WAIT(0);
        }
        __syncthreads();

        const uint32_t aS = sb + s * STG;
        const uint32_t bS = aS + 8192;
        const int rlow = lane & 15, hi = lane >> 4;
#pragma unroll
        for (int kk = 0; kk < 4; kk++) {
            uint32_t af[2][4];
#pragma unroll
            for (int mi = 0; mi < 2; mi++) {
                int r = wm + mi * 16 + rlow;
                int ck = kk * 2 + hi;
                ldm4(af[mi], aS + (uint32_t)(r * 128 + ((ck ^ (r & 7)) * 16)));
            }
            uint32_t bf[8][2];
#pragma unroll
            for (int nj = 0; nj < 4; nj++) {
                int r = wn + nj * 16 + rlow;
                int ck = kk * 2 + hi;
                uint32_t q[4];
                ldm4(q, bS + (uint32_t)(r * 128 + ((ck ^ (r & 7)) * 16)));
                bf[nj * 2 + 0][0] = q[0]; bf[nj * 2 + 0][1] = q[2];
                bf[nj * 2 + 1][0] = q[1]; bf[nj * 2 + 1][1] = q[3];
            }
#pragma unroll
            for (int mi = 0; mi < 2; mi++)
#pragma unroll
                for (int ni = 0; ni < 8; ni++)
                    mma16(acc[mi][ni], af[mi], bf[ni]);
        }
        __syncthreads();
    }

#pragma unroll
    for (int mi = 0; mi < 2; mi++) {
#pragma unroll
        for (int r = 0; r < 2; r++) {
            const int gm = row0 + wm + mi * 16 + g + r * 8;
            if (gm >= M) continue;
#pragma unroll
            for (int ni = 0; ni < 8; ni++) {
                const int gn = col0 + wn + ni * 8 + 2 * t;
                float v0 = acc[mi][ni][r * 2 + 0] + bias[gn];
                float v1 = acc[mi][ni][r * 2 + 1] + bias[gn + 1];
                *(__half2*)(outp + (size_t)gm * N + gn) = __floats2half2_rn(v0, v1);
            }
        }
    }
    pdl_trigger();
}

// ============================================================================
// Merged prologue: ln1 (BLQ blocks) + lvl0 (BTP blocks) + weight cvt (272).
// ============================================================================
__global__ __launch_bounds__(128) void k_pre(
    const float* __restrict__ x, const float* __restrict__ pe,
    const float* __restrict__ lp,
    const float* __restrict__ g1, const float* __restrict__ be1,
    const float* __restrict__ g2, const float* __restrict__ be2,
    const float* __restrict__ w0, const float* __restrict__ w1,
    const float* __restrict__ w2, const float* __restrict__ w3,
    const float* __restrict__ w4, const float* __restrict__ w5,
    const float* __restrict__ w6, const float* __restrict__ w7,
    const float* __restrict__ b_off, const float* __restrict__ b_attn)
{
    const int bid = blockIdx.x;
    const int c = threadIdx.x;

    if (bid < BLQ) {
        int row = bid;
        int b = row / LQ; int lq = row - b * LQ;
        int l = lq & 3; int tp = lq >> 2;
        size_t xi = ((size_t)(b * TT * PP + tp) * NLVL + (l + 1)) * CC + c;
        float v = x[xi];

        __shared__ float sh[8];
        float s = v;
        for (int o = 16; o > 0; o >>= 1) s += __shfl_xor_sync(0xffffffffu, s, o);
        if ((c & 31) == 0) sh[c >> 5] = s;
        __syncthreads();
        float mean = (sh[0] + sh[1] + sh[2] + sh[3]) * (1.f / CC);
        float dv = v - mean;
        float q2 = dv * dv;
        for (int o = 16; o > 0; o >>= 1) q2 += __shfl_xor_sync(0xffffffffu, q2, o);
        if ((c & 31) == 0) sh[4 + (c >> 5)] = q2;
        __syncthreads();
        float var = (sh[4] + sh[5] + sh[6] + sh[7]) * (1.f / CC);
        float xn = dv * rsqrtf(var + 1e-5f) * g1[c] + be1[c];
        g_XNh[(size_t)row * CC + c] = __float2half_rn(xn);
        g_Qh [(size_t)row * CC + c] = __float2half_rn(xn + pe[(size_t)lq * CC + c] + lp[(size_t)lq * CC + c]);
    } else if (bid < BLQ + BTP) {
        int btp = bid - BLQ;
        size_t rowoff = (size_t)btp * NLVL * CC;
        float v = x[rowoff + c];
        g_XCAT[rowoff + c] = v;

        __shared__ float sh2[8];
        float s = v;
        for (int o = 16; o > 0; o >>= 1) s += __shfl_xor_sync(0xffffffffu, s, o);
        if ((c & 31) == 0) sh2[c >> 5] = s;
        __syncthreads();
        float mean = (sh2[0] + sh2[1] + sh2[2] + sh2[3]) * (1.f / CC);
        float dv = v - mean;
        float q2 = dv * dv;
        for (int o = 16; o > 0; o >>= 1) q2 += __shfl_xor_sync(0xffffffffu, q2, o);
        if ((c & 31) == 0) sh2[4 + (c >> 5)] = q2;
        __syncthreads();
        float var = (sh2[4] + sh2[5] + sh2[6] + sh2[7]) * (1.f / CC);
        g_XN2h[rowoff + c] = __float2half_rn(dv * rsqrtf(var + 1e-5f) * g2[c] + be2[c]);
    } else {
        int wb = bid - BLQ - BTP;             // 0..271
        if (wb == 0 && c < 128) {
            g_Bcat[c]       = b_off[c];
            g_Bcat[c + 128] = b_off[c + 128];
            g_Bcat[c + 256] = b_attn[c];
        }
        for (int idx = wb * 128 + c; idx < WTOTAL; idx += 272 * 128) {
            const float* src; int off;
            if      (idx < WOFF_ATTN) { src = w0; off = idx; }
            else if (idx < WOFF_VAL ) { src = w1; off = idx - WOFF_ATTN; }
            else if (idx < WOFF_OUT ) { src = w2; off = idx - WOFF_VAL; }
            else if (idx < WOFF_IN  ) { src = w3; off = idx - WOFF_OUT; }
            else if (idx < WOFF_OUTW) { src = w4; off = idx - WOFF_IN; }
            else if (idx < WOFF_FC1 ) { src = w5; off = idx - WOFF_OUTW; }
            else if (idx < WOFF_FC2 ) { src = w6; off = idx - WOFF_FC1; }
            else                      { src = w7; off = idx - WOFF_FC2; }
            g_Wh[idx] = __float2half_rn(src[off]);
        }
    }
    pdl_trigger();
}

// ---------------- deformable sampling: 16 threads/row, 16B gathers ---------
#define DEF_RPB 8
__device__ __forceinline__ void ld8h(float* dst, const __half* p, bool valid) {
    if (valid) {
        uint4 q = *(const uint4*)p;
        const __half2* hp = (const __half2*)&q;
#pragma unroll
        for (int j = 0; j < 4; j++) {
            float2 f = __half22float2(hp[j]);
            dst[2 * j] = f.x; dst[2 * j + 1] = f.y;
        }
    } else {
#pragma unroll
        for (int j = 0; j < 8; j++) dst[j] = 0.f;
    }
}

__global__ __launch_bounds__(128) void k_deform(const float* __restrict__ refp)
{
    __shared__ float sOFF[DEF_RPB][384];
    const int row0 = blockIdx.x * DEF_RPB;
    const int tid = threadIdx.x;

    pdl_wait();   // OFFAWh / VALh from predecessor

    for (int idx = tid; idx < DEF_RPB * 192; idx += 128) {
        int rr = idx / 192, c2 = idx - rr * 192;
        float2 v = __half22float2(*(const __half2*)(g_OFFAWh + (size_t)(row0 + rr) * 384 + c2 * 2));
        sOFF[rr][c2 * 2 + 0] = v.x;
        sOFF[rr][c2 * 2 + 1] = v.y;
    }
    __syncthreads();

    const int rr = tid >> 4;
    const int s = tid & 15;
    const int row = row0 + rr;
    const int b = row / LQ; const int lq = row - b * LQ;
    const int tp = lq >> 2; const int p = tp % PP; const int t = tp / PP;
    const int h = s >> 1, dq = s & 1;
    const float refx = refp[(((size_t)b * TT + t) * PP + p) * 2 + 0];
    const float refy = refp[(((size_t)b * TT + t) * PP + p) * 2 + 1];

    const float* awp = &sOFF[rr][256 + h * 16];
    float w[16], mx = -1e30f;
#pragma unroll
    for (int i = 0; i < 16; i++) { w[i] = awp[i]; mx = fmaxf(mx, w[i]); }
    float den = 0.f;
#pragma unroll
    for (int i = 0; i < 16; i++) { w[i] = expf(w[i] - mx); den += w[i]; }
    float inv = 1.f / den;

    const float*  offp  = &sOFF[rr][h * 32];
    const __half* vbase = g_VALh + (size_t)b * LQ * CC + h * 16 + dq * 8;
    float acc[8];
#pragma unroll
    for (int j = 0; j < 8; j++) acc[j] = 0.f;

#pragma unroll
    for (int l = 0; l < LL; l++) {
#pragma unroll
        for (int pt = 0; pt < NPT; pt++) {
            float ox = offp[(l * 4 + pt) * 2 + 0];
            float oy = offp[(l * 4 + pt) * 2 + 1];
            float fx = refx * PP + ox - 0.5f;
            float fy = refy * TT + oy - 0.5f;
            float x0f = floorf(fx), y0f = floorf(fy);
            int x0 = (int)x0f, y0 = (int)y0f;
            float wx1 = fx - x0f, wy1 = fy - y0f;
            float wx0 = 1.f - wx1, wy0 = 1.f - wy1;
            bool xi0 = (x0 >= 0) && (x0 < PP);
            bool xi1 = (x0 + 1 >= 0) && (x0 + 1 < PP);
            bool yi0 = (y0 >= 0) && (y0 < TT);
            bool yi1 = (y0 + 1 >= 0) && (y0 + 1 < TT);
            float v00[8], v01[8], v10[8], v11[8];
            ld8h(v00, vbase + ((size_t)(y0 * PP + x0) * LL + l) * CC,           yi0 && xi0);
            ld8h(v01, vbase + ((size_t)(y0 * PP + x0 + 1) * LL + l) * CC,       yi0 && xi1);
            ld8h(v10, vbase + ((size_t)((y0 + 1) * PP + x0) * LL + l) * CC,     yi1 && xi0);
            ld8h(v11, vbase + ((size_t)((y0 + 1) * PP + x0 + 1) * LL + l) * CC, yi1 && xi1);
            float w00 = wy0 * wx0, w01 = wy0 * wx1, w10 = wy1 * wx0, w11 = wy1 * wx1;
            float ww = w[l * 4 + pt];
#pragma unroll
            for (int j = 0; j < 8; j++) {
                float sv = v00[j] * w00 + v01[j] * w01 + v10[j] * w10 + v11[j] * w11;
                acc[j] = fmaf(sv, ww, acc[j]);
            }
        }
    }
    __half2 ho[4];
#pragma unroll
    for (int j = 0; j < 4; j++)
        ho[j] = __floats2half2_rn(acc[2 * j] * inv, acc[2 * j + 1] * inv);
    *(uint4*)(g_Oh + (size_t)row * CC + h * 16 + dq * 8) = *(uint4*)ho;
    pdl_trigger();
}

// ---------------- per-(bt,head) self-attention (fp16 QKV) ------------------
__global__ void k_attn()
{
    int bt = blockIdx.x, h = blockIdx.y;
    __shared__ float Qs[SS][DHH], Ks[SS][DHH], Vs[SS][DHH];
    int tid = threadIdx.x;
    pdl_wait();   // QKVh from predecessor
    for (int i = tid; i < SS * DHH; i += 128) {
        int s = i >> 4, d = i & 15;
        const __half* base = g_QKVh + ((size_t)bt * SS + s) * 384 + h * 16 + d;
        Qs[s][d] = __half2float(base[0]);
        Ks[s][d] = __half2float(base[128]);
        Vs[s][d] = __half2float(base[256]);
    }
    __syncthreads();
    if (tid < SS) {
        float qv[16];
#pragma unroll
        for (int d = 0; d < 16; d++) qv[d] = Qs[tid][d];
        float mx = -1e30f;
        for (int k = 0; k < SS; k++) {
            float sdot = 0.f;
#pragma unroll
            for (int d = 0; d < 16; d++) sdot = fmaf(qv[d], Ks[k][d], sdot);
            mx = fmaxf(mx, sdot * 0.25f);
        }
        float den = 0.f, o[16];
#pragma unroll
        for (int d = 0; d < 16; d++) o[d] = 0.f;
        for (int k = 0; k < SS; k++) {
            float sdot = 0.f;
#pragma unroll
            for (int d = 0; d < 16; d++) sdot = fmaf(qv[d], Ks[k][d], sdot);
            float e = expf(sdot * 0.25f - mx);
            den += e;
#pragma unroll
            for (int d = 0; d < 16; d++) o[d] = fmaf(e, Vs[k][d], o[d]);
        }
        float inv = 1.f / den;
        __half* outp = g_ATTOh + ((size_t)bt * SS + tid) * CC + h * 16;
#pragma unroll
        for (int d = 0; d < 16; d++) outp[d] = __float2half_rn(o[d] * inv);
    }
    pdl_trigger();
}

// ---------------- host launch (PDL-enabled) ---------------------------------
static cudaLaunchAttribute g_pdlAttr;

static inline void launch_small_pdl(const __half* A, const __half* W, const float* bias,
                                    const float* res, void* out, int M, int N, int K,
                                    int epi, int outHalf, int perm,
                                    const float* lnG, const float* lnB, __half* out2)
{
    cudaLaunchConfig_t cfg = {};
    cfg.gridDim = dim3(N / 128, (M + 63) / 64);
    cfg.blockDim = dim3(128);
    cfg.dynamicSmemBytes = GEMM_SMEM;
    cfg.stream = 0;
    cfg.attrs = &g_pdlAttr;
    cfg.numAttrs = 1;
    cudaLaunchKernelEx(&cfg, k_gemm_h, A, W, bias, res ? res : (const float*)A,
                       out, M, N, K, epi, outHalf, perm, lnG, lnB, out2);
}
static inline void launch_big_pdl(const __half* A, const __half* W, const float* bias,
                                  const float* res, void* out, int M, int N, int K,
                                  int epi, int outHalf)
{
    cudaLaunchConfig_t cfg = {};
    cfg.gridDim = dim3(N / 128, (M + 127) / 128);
    cfg.blockDim = dim3(256);
    cfg.dynamicSmemBytes = BIG_SMEM;
    cfg.stream = 0;
    cfg.attrs = &g_pdlAttr;
    cfg.numAttrs = 1;
    cudaLaunchKernelEx(&cfg, k_gemm_big, A, W, bias, res ? res : (const float*)A,
                       out, M, N, K, epi, outHalf);
}

extern "C" void kernel_launch(void* const* d_in, const int* in_sizes, int n_in,
                              void* d_out, int out_size)
{
    (void)in_sizes; (void)n_in; (void)out_size;
    const float* x        = (const float*)d_in[0];
    const float* refp     = (const float*)d_in[1];
    const float* pe_buf   = (const float*)d_in[2];
    const float* learn_pos= (const float*)d_in[3];
    const float* w_off    = (const float*)d_in[4];
    const float* b_off    = (const float*)d_in[5];
    const float* w_attn   = (const float*)d_in[6];
    const float* b_attn   = (const float*)d_in[7];
    const float* w_val    = (const float*)d_in[8];
    const float* b_val    = (const float*)d_in[9];
    const float* w_out    = (const float*)d_in[10];
    const float* b_out    = (const float*)d_in[11];
    const float* in_w     = (const float*)d_in[12];
    const float* in_b     = (const float*)d_in[13];
    const float* out_w    = (const float*)d_in[14];
    const float* b_out2   = (const float*)d_in[15];
    const float* fc1_w    = (const float*)d_in[16];
    const float* fc1_b    = (const float*)d_in[17];
    const float* fc2_w    = (const float*)d_in[18];
    const float* fc2_b    = (const float*)d_in[19];
    const float* g1       = (const float*)d_in[20];
    const float* be1      = (const float*)d_in[21];
    const float* g2       = (const float*)d_in[22];
    const float* be2      = (const float*)d_in[23];
    const float* g3       = (const float*)d_in[24];
    const float* be3      = (const float*)d_in[25];
    float* out = (float*)d_out;

    g_pdlAttr.id = cudaLaunchAttributeProgrammaticStreamSerialization;
    g_pdlAttr.val.programmaticStreamSerializationAllowed = 1;

    cudaFuncSetAttribute(k_gemm_h,   cudaFuncAttributeMaxDynamicSharedMemorySize, GEMM_SMEM);
    cudaFuncSetAttribute(k_projs,    cudaFuncAttributeMaxDynamicSharedMemorySize, GEMM_SMEM);
    cudaFuncSetAttribute(k_gemm_big, cudaFuncAttributeMaxDynamicSharedMemorySize, BIG_SMEM);

    float *pXCAT, *pXCAT2;
    __half *pOh, *pXN2h, *pQKVh, *pATTOh, *pXN3h, *pHIDh, *pWh;
    cudaGetSymbolAddress((void**)&pXCAT,  g_XCAT);
    cudaGetSymbolAddress((void**)&pXCAT2, g_XCAT2);
    cudaGetSymbolAddress((void**)&pOh,    g_Oh);
    cudaGetSymbolAddress((void**)&pXN2h,  g_XN2h);
    cudaGetSymbolAddress((void**)&pQKVh,  g_QKVh);
    cudaGetSymbolAddress((void**)&pATTOh, g_ATTOh);
    cudaGetSymbolAddress((void**)&pXN3h,  g_XN3h);
    cudaGetSymbolAddress((void**)&pHIDh,  g_HIDh);
    cudaGetSymbolAddress((void**)&pWh,    g_Wh);

    // 1) merged prologue: LN1 + lvl0(LN2) + weight cvt
    k_pre<<<BLQ + BTP + 272, 128>>>(x, pe_buf, learn_pos, g1, be1, g2, be2,
                                    w_off, w_attn, w_val, w_out, in_w, out_w,
                                    fc1_w, fc2_w, b_off, b_attn);
    // 2) merged projections: offaw (N=384) + val (N=128) -> fp16 [PDL]
    {
        cudaLaunchConfig_t cfg = {};
        cfg.gridDim = dim3(4, (BLQ + 63) / 64);
        cfg.blockDim = dim3(128);
        cfg.dynamicSmemBytes = GEMM_SMEM;
        cfg.stream = 0;
        cfg.attrs = &g_pdlAttr;
        cfg.numAttrs = 1;
        cudaLaunchKernelEx(&cfg, k_projs, b_val);
    }
    // 3) deformable sampling [PDL]
    {
        cudaLaunchConfig_t cfg = {};
        cfg.gridDim = dim3(BLQ / DEF_RPB);
        cfg.blockDim = dim3(128);
        cfg.stream = 0;
        cfg.attrs = &g_pdlAttr;
        cfg.numAttrs = 1;
        cudaLaunchKernelEx(&cfg, k_deform, refp);
    }
    // 4) out-proj + residual(from x, permuted) + concat + fused LN2 [PDL]
    launch_small_pdl(pOh, pWh + WOFF_OUT, b_out, x, pXCAT, BLQ, 128, CC, 3, 0, 1,
                     g2, be2, pXN2h);
    // 5) QKV GEMM (N=384) -> fp16 [PDL, BIG]
    launch_big_pdl(pXN2h, pWh + WOFF_IN, in_b, nullptr, pQKVh, TOK, 384, CC, 0, 1);
    // 6) self-attention [PDL]
    {
        cudaLaunchConfig_t cfg = {};
        cfg.gridDim = dim3(BB * TT, HH);
        cfg.blockDim = dim3(128);
        cfg.stream = 0;
        cfg.attrs = &g_pdlAttr;
        cfg.numAttrs = 1;
        cudaLaunchKernelEx(&cfg, k_attn);
    }
    // 7) attention out-proj + residual + fused LN3 [PDL]
    launch_small_pdl(pATTOh, pWh + WOFF_OUTW, b_out2, pXCAT, pXCAT2, TOK, 128, CC,
                     3, 0, 0, g3, be3, pXN3h);
    // 8) FC1 + GELU (N=512) -> fp16 [PDL, BIG]
    launch_big_pdl(pXN3h, pWh + WOFF_FC1, fc1_b, nullptr, pHIDh, TOK, 512, CC, 2, 1);
    // 9) FC2 + residual -> final output (K=512) [PDL, BIG]
    launch_big_pdl(pHIDh, pWh + WOFF_FC2, fc2_b, pXCAT2, out, TOK, 128, 512, 1, 0);
}

// round 13
// speedup vs baseline: 1.0140x; 1.0140x over previous
#include <cuda_runtime.h>
#include <cuda_fp16.h>
#include <math.h>
#include <stdint.h>

// Problem constants
#define TT   243
#define PP   17
#define LL   4
#define CC   128
#define HH   8
#define NPT  4
#define DHH  16
#define BB   2
#define LQ   (TT*PP*LL)        // 16524
#define BLQ  (BB*LQ)           // 33048
#define NLVL 5
#define BTP  (BB*TT*PP)        // 8262
#define TOK  (BTP*NLVL)        // 41310
#define SS   (PP*NLVL)         // 85

// ---------------- scratch (device globals; no allocations) ----------------
__device__ float  g_XCAT [(size_t)TOK*CC];
__device__ float  g_XCAT2[(size_t)TOK*CC];
__device__ __half g_OFFAWh[(size_t)BLQ*384];
__device__ __half g_Qh   [(size_t)BLQ*CC];
__device__ __half g_XNh  [(size_t)BLQ*CC];
__device__ __half g_VALh [(size_t)BLQ*CC];
__device__ __half g_Oh   [(size_t)BLQ*CC];
__device__ __half g_XN2h [(size_t)TOK*CC];
__device__ __half g_QKVh [(size_t)TOK*384];
__device__ __half g_ATTOh[(size_t)TOK*CC];
__device__ __half g_XN3h [(size_t)TOK*CC];
__device__ __half g_HIDh [(size_t)TOK*512];
#define WOFF_OFF   0
#define WOFF_ATTN  32768
#define WOFF_VAL   49152
#define WOFF_OUT   65536
#define WOFF_IN    81920
#define WOFF_OUTW  131072
#define WOFF_FC1   147456
#define WOFF_FC2   212992
#define WTOTAL     278528
__device__ __half g_Wh[WTOTAL];
__device__ float  g_Bcat[384];

// ---------------- PTX helpers ----------------------------------------------
__device__ __forceinline__ void cpa16(uint32_t dst, const void* src, bool valid) {
    int sz = valid ? 16 : 0;
    asm volatile("cp.async.cg.shared.global [%0], [%1], 16, %2;\n"
                 :: "r"(dst), "l"(src), "r"(sz));
}
#define CP_COMMIT() asm volatile("cp.async.commit_group;\n" ::: "memory")
#define CP_WAIT(n)  asm volatile("cp.async.wait_group %0;\n" :: "n"(n) : "memory")

__device__ __forceinline__ void ldm4(uint32_t* r, uint32_t addr) {
    asm volatile("ldmatrix.sync.aligned.m8n8.x4.shared.b16 {%0,%1,%2,%3}, [%4];\n"
                 : "=r"(r[0]), "=r"(r[1]), "=r"(r[2]), "=r"(r[3]) : "r"(addr));
}
__device__ __forceinline__ void mma16(float* c, const uint32_t* a, const uint32_t* b) {
    asm volatile("mma.sync.aligned.m16n8k16.row.col.f32.f16.f16.f32 "
                 "{%0,%1,%2,%3},{%4,%5,%6,%7},{%8,%9},{%0,%1,%2,%3};\n"
                 : "+f"(c[0]), "+f"(c[1]), "+f"(c[2]), "+f"(c[3])
                 : "r"(a[0]), "r"(a[1]), "r"(a[2]), "r"(a[3]), "r"(b[0]), "r"(b[1]));
}

// permuted destination row for the xcat concat (also the x source row!)
__device__ __forceinline__ int xcat_row(int gm) {
    int b = gm / LQ;
    int rem = gm - b * LQ;
    return (b * (TT * PP) + (rem >> 2)) * 5 + (rem & 3) + 1;
}

// ============================================================================
// BIG GEMM: BM=128, BN=128, BK=64, 256 threads (QKV / FC1 / FC2).
// ============================================================================
#define BIG_STG  32768
#define BIG_SMEM 65536

__device__ __forceinline__ void big_load_stage(
    const __half* __restrict__ A, const __half* __restrict__ W, uint32_t sb,
    int st, int kt, int row0, int col0, int M, int K, int tid)
{
    const int r0 = tid >> 3, ck = tid & 7;
    const uint32_t base = sb + st * BIG_STG;
#pragma unroll
    for (int i = 0; i < 4; i++) {
        int r = r0 + i * 32;
        uint32_t swoff = (uint32_t)(r * 128 + ((ck ^ (r & 7)) * 16));
        int gm = row0 + r;
        cpa16(base + swoff, A + (size_t)gm * K + (size_t)kt * 64 + ck * 8, gm < M);
        cpa16(base + 16384 + swoff,
              W + (size_t)(col0 + r) * K + (size_t)kt * 64 + ck * 8, true);
    }
}

__global__ __launch_bounds__(256, 2) void k_gemm_big(
    const __half* __restrict__ A, const __half* __restrict__ W,
    const float* __restrict__ bias, const float* __restrict__ res,
    void* __restrict__ outp, int M, int N, int K, int epi, int outHalf)
{
    extern __shared__ __align__(1024) char sm[];
    uint32_t sb = (uint32_t)__cvta_generic_to_shared(sm);
    const int tid = threadIdx.x, lane = tid & 31, warp = tid >> 5;
    const int g = lane >> 2, t = lane & 3;
    const int wm = (warp >> 1) * 32, wn = (warp & 1) * 64;
    const int row0 = blockIdx.y * 128, col0 = blockIdx.x * 128;
    const int KT = K >> 6;

    float acc[2][8][4];
#pragma unroll
    for (int mi = 0; mi < 2; mi++)
#pragma unroll
        for (int ni = 0; ni < 8; ni++)
#pragma unroll
            for (int r = 0; r < 4; r++) acc[mi][ni][r] = 0.f;

    big_load_stage(A, W, sb, 0, 0, row0, col0, M, K, tid);
    CP_COMMIT();

    for (int kt = 0; kt < KT; kt++) {
        const int s = kt & 1;
        if (kt + 1 < KT) {
            big_load_stage(A, W, sb, s ^ 1, kt + 1, row0, col0, M, K, tid);
            CP_COMMIT();
            CP_WAIT(1);
        } else {
            CP_WAIT(0);
        }
        __syncthreads();

        const uint32_t aS = sb + s * BIG_STG;
        const uint32_t bS = aS + 16384;
        const int rlow = lane & 15, hi = lane >> 4;
#pragma unroll
        for (int kk = 0; kk < 4; kk++) {
            uint32_t af[2][4];
#pragma unroll
            for (int mi = 0; mi < 2; mi++) {
                int r = wm + mi * 16 + rlow;
                int ck = kk * 2 + hi;
                ldm4(af[mi], aS + (uint32_t)(r * 128 + ((ck ^ (r & 7)) * 16)));
            }
            uint32_t bf[8][2];
#pragma unroll
            for (int nj = 0; nj < 4; nj++) {
                int r = wn + nj * 16 + rlow;
                int ck = kk * 2 + hi;
                uint32_t q[4];
                ldm4(q, bS + (uint32_t)(r * 128 + ((ck ^ (r & 7)) * 16)));
                bf[nj * 2 + 0][0] = q[0]; bf[nj * 2 + 0][1] = q[2];
                bf[nj * 2 + 1][0] = q[1]; bf[nj * 2 + 1][1] = q[3];
            }
#pragma unroll
            for (int mi = 0; mi < 2; mi++)
#pragma unroll
                for (int ni = 0; ni < 8; ni++)
                    mma16(acc[mi][ni], af[mi], bf[ni]);
        }
        __syncthreads();
    }

#pragma unroll
    for (int mi = 0; mi < 2; mi++) {
#pragma unroll
        for (int r = 0; r < 2; r++) {
            const int gm = row0 + wm + mi * 16 + g + r * 8;
            if (gm >= M) continue;
            const float* rp = res + (size_t)gm * N;
#pragma unroll
            for (int ni = 0; ni < 8; ni++) {
                const int gn = col0 + wn + ni * 8 + 2 * t;
                float v0 = acc[mi][ni][r * 2 + 0] + bias[gn];
                float v1 = acc[mi][ni][r * 2 + 1] + bias[gn + 1];
                if (epi == 1) {
                    v0 += rp[gn];
                    v1 += rp[gn + 1];
                } else if (epi == 2) {
                    v0 = 0.5f * v0 * (1.0f + erff(v0 * 0.7071067811865475f));
                    v1 = 0.5f * v1 * (1.0f + erff(v1 * 0.7071067811865475f));
                }
                if (outHalf) {
                    *(__half2*)((__half*)outp + (size_t)gm * N + gn) = __floats2half2_rn(v0, v1);
                } else {
                    *(float2*)((float*)outp + (size_t)gm * N + gn) = make_float2(v0, v1);
                }
            }
        }
    }
}

// ============================================================================
// SMALL GEMM: BM=64, BN=128, BK=64, 128 threads; epi3 = residual + LN fusion.
// ============================================================================
#define STG 24576
#define SREDOFF 49152
#define GEMM_SMEM 50176

__device__ __forceinline__ void gemm_load_stage(
    const __half* __restrict__ A, const __half* __restrict__ W, uint32_t sb,
    int st, int kt, int row0, int col0, int M, int K, int tid)
{
    const int r0 = tid >> 3, ck = tid & 7;
    const uint32_t base = sb + st * STG;
#pragma unroll
    for (int i = 0; i < 4; i++) {
        int r = r0 + i * 16;
        uint32_t swoff = (uint32_t)(r * 128 + ((ck ^ (r & 7)) * 16));
        int gm = row0 + r;
        cpa16(base + swoff, A + (size_t)gm * K + (size_t)kt * 64 + ck * 8, gm < M);
    }
#pragma unroll
    for (int i = 0; i < 8; i++) {
        int r = r0 + i * 16;
        uint32_t swoff = (uint32_t)(r * 128 + ((ck ^ (r & 7)) * 16));
        cpa16(base + 8192 + swoff,
              W + (size_t)(col0 + r) * K + (size_t)kt * 64 + ck * 8, true);
    }
}

__global__ __launch_bounds__(128, 4) void k_gemm_h(
    const __half* __restrict__ A, const __half* __restrict__ W,
    const float* __restrict__ bias, const float* __restrict__ res,
    void* __restrict__ outp, int M, int N, int K, int epi, int outHalf, int perm,
    const float* __restrict__ lnG, const float* __restrict__ lnB,
    __half* __restrict__ out2)
{
    extern __shared__ __align__(1024) char sm[];
    uint32_t sb = (uint32_t)__cvta_generic_to_shared(sm);
    float* sred = (float*)(sm + SREDOFF);
    const int tid = threadIdx.x, lane = tid & 31, warp = tid >> 5;
    const int g = lane >> 2, t = lane & 3;
    const int wm = (warp >> 1) * 32, wn = (warp & 1) * 64;
    const int row0 = blockIdx.y * 64, col0 = blockIdx.x * 128;
    const int KT = K >> 6;

    float acc[2][8][4];
#pragma unroll
    for (int mi = 0; mi < 2; mi++)
#pragma unroll
        for (int ni = 0; ni < 8; ni++)
#pragma unroll
            for (int r = 0; r < 4; r++) acc[mi][ni][r] = 0.f;

    gemm_load_stage(A, W, sb, 0, 0, row0, col0, M, K, tid);
    CP_COMMIT();

    for (int kt = 0; kt < KT; kt++) {
        const int s = kt & 1;
        if (kt + 1 < KT) {
            gemm_load_stage(A, W, sb, s ^ 1, kt + 1, row0, col0, M, K, tid);
            CP_COMMIT();
            CP_WAIT(1);
        } else {
            CP_WAIT(0);
        }
        __syncthreads();

        const uint32_t aS = sb + s * STG;
        const uint32_t bS = aS + 8192;
        const int rlow = lane & 15, hi = lane >> 4;
#pragma unroll
        for (int kk = 0; kk < 4; kk++) {
            uint32_t af[2][4];
#pragma unroll
            for (int mi = 0; mi < 2; mi++) {
                int r = wm + mi * 16 + rlow;
                int ck = kk * 2 + hi;
                ldm4(af[mi], aS + (uint32_t)(r * 128 + ((ck ^ (r & 7)) * 16)));
            }
            uint32_t bf[8][2];
#pragma unroll
            for (int nj = 0; nj < 4; nj++) {
                int r = wn + nj * 16 + rlow;
                int ck = kk * 2 + hi;
                uint32_t q[4];
                ldm4(q, bS + (uint32_t)(r * 128 + ((ck ^ (r & 7)) * 16)));
                bf[nj * 2 + 0][0] = q[0]; bf[nj * 2 + 0][1] = q[2];
                bf[nj * 2 + 1][0] = q[1]; bf[nj * 2 + 1][1] = q[3];
            }
#pragma unroll
            for (int mi = 0; mi < 2; mi++)
#pragma unroll
                for (int ni = 0; ni < 8; ni++)
                    mma16(acc[mi][ni], af[mi], bf[ni]);
        }
        __syncthreads();
    }

#pragma unroll
    for (int mi = 0; mi < 2; mi++) {
#pragma unroll
        for (int r = 0; r < 2; r++) {
            const int gm = row0 + wm + mi * 16 + g + r * 8;
            float psum = 0.f, psq = 0.f;
            if (gm < M) {
                const size_t orow = (epi == 3 && perm) ? (size_t)xcat_row(gm) : (size_t)gm;
                const float* rp = res + orow * N;
#pragma unroll
                for (int ni = 0; ni < 8; ni++) {
                    const int gn = col0 + wn + ni * 8 + 2 * t;
                    float v0 = acc[mi][ni][r * 2 + 0] + bias[gn];
                    float v1 = acc[mi][ni][r * 2 + 1] + bias[gn + 1];
                    if (epi == 1 || epi == 3) {
                        v0 += rp[gn];
                        v1 += rp[gn + 1];
                    } else if (epi == 2) {
                        v0 = 0.5f * v0 * (1.0f + erff(v0 * 0.7071067811865475f));
                        v1 = 0.5f * v1 * (1.0f + erff(v1 * 0.7071067811865475f));
                    }
                    if (outHalf) {
                        *(__half2*)((__half*)outp + orow * N + gn) = __floats2half2_rn(v0, v1);
                    } else {
                        *(float2*)((float*)outp + orow * N + gn) = make_float2(v0, v1);
                    }
                    acc[mi][ni][r * 2 + 0] = v0;
                    acc[mi][ni][r * 2 + 1] = v1;
                    psum += v0 + v1;
                    psq  += v0 * v0 + v1 * v1;
                }
            }
            if (epi == 3) {
                psum += __shfl_xor_sync(0xffffffffu, psum, 1);
                psum += __shfl_xor_sync(0xffffffffu, psum, 2);
                psq  += __shfl_xor_sync(0xffffffffu, psq, 1);
                psq  += __shfl_xor_sync(0xffffffffu, psq, 2);
                if (t == 0) {
                    int lr = wm + mi * 16 + g + r * 8;
                    sred[lr * 4 + (warp & 1) * 2 + 0] = psum;
                    sred[lr * 4 + (warp & 1) * 2 + 1] = psq;
                }
            }
        }
    }
    if (epi == 3) {
        __syncthreads();
#pragma unroll
        for (int mi = 0; mi < 2; mi++) {
#pragma unroll
            for (int r = 0; r < 2; r++) {
                const int gm = row0 + wm + mi * 16 + g + r * 8;
                if (gm >= M) continue;
                const size_t orow = perm ? (size_t)xcat_row(gm) : (size_t)gm;
                const int lr = wm + mi * 16 + g + r * 8;
                float sum = sred[lr * 4 + 0] + sred[lr * 4 + 2];
                float sq  = sred[lr * 4 + 1] + sred[lr * 4 + 3];
                float mean = sum * (1.f / 128.f);
                float var = sq * (1.f / 128.f) - mean * mean;
                float rstd = rsqrtf(var + 1e-5f);
#pragma unroll
                for (int ni = 0; ni < 8; ni++) {
                    const int gn = col0 + wn + ni * 8 + 2 * t;
                    float a0 = (acc[mi][ni][r * 2 + 0] - mean) * rstd * lnG[gn] + lnB[gn];
                    float a1 = (acc[mi][ni][r * 2 + 1] - mean) * rstd * lnG[gn + 1] + lnB[gn + 1];
                    *(__half2*)(out2 + orow * 128 + gn) = __floats2half2_rn(a0, a1);
                }
            }
        }
    }
}

// ============================================================================
// Merged projection GEMM: offaw (N=384, cols 0-2) + val (N=128, col 3).
// ============================================================================
__global__ __launch_bounds__(128, 4) void k_projs(const float* __restrict__ b_val)
{
    extern __shared__ __align__(1024) char sm[];
    uint32_t sb = (uint32_t)__cvta_generic_to_shared(sm);
    const int tid = threadIdx.x, lane = tid & 31, warp = tid >> 5;
    const int g = lane >> 2, t = lane & 3;
    const int wm = (warp >> 1) * 32, wn = (warp & 1) * 64;
    const int row0 = blockIdx.y * 64;

    const __half* A; const __half* W; const float* bias; __half* outp; int N; int col0;
    if (blockIdx.x < 3) {
        A = g_Qh;  W = g_Wh + WOFF_OFF; bias = g_Bcat; outp = g_OFFAWh;
        N = 384; col0 = blockIdx.x * 128;
    } else {
        A = g_XNh; W = g_Wh + WOFF_VAL; bias = b_val;  outp = g_VALh;
        N = 128; col0 = 0;
    }
    const int M = BLQ, K = CC, KT = 2;

    float acc[2][8][4];
#pragma unroll
    for (int mi = 0; mi < 2; mi++)
#pragma unroll
        for (int ni = 0; ni < 8; ni++)
#pragma unroll
            for (int r = 0; r < 4; r++) acc[mi][ni][r] = 0.f;

    gemm_load_stage(A, W, sb, 0, 0, row0, col0, M, K, tid);
    CP_COMMIT();

    for (int kt = 0; kt < KT; kt++) {
        const int s = kt & 1;
        if (kt + 1 < KT) {
            gemm_load_stage(A, W, sb, s ^ 1, kt + 1, row0, col0, M, K, tid);
            CP_COMMIT();
            CP_WAIT(1);
        } else {
            CP_WAIT(0);
        }
        __syncthreads();

        const uint32_t aS = sb + s * STG;
        const uint32_t bS = aS + 8192;
        const int rlow = lane & 15, hi = lane >> 4;
#pragma unroll
        for (int kk = 0; kk < 4; kk++) {
            uint32_t af[2][4];
#pragma unroll
            for (int mi = 0; mi < 2; mi++) {
                int r = wm + mi * 16 + rlow;
                int ck = kk * 2 + hi;
                ldm4(af[mi], aS + (uint32_t)(r * 128 + ((ck ^ (r & 7)) * 16)));
            }
            uint32_t bf[8][2];
#pragma unroll
            for (int nj = 0; nj < 4; nj++) {
                int r = wn + nj * 16 + rlow;
                int ck = kk * 2 + hi;
                uint32_t q[4];
                ldm4(q, bS + (uint32_t)(r * 128 + ((ck ^ (r & 7)) * 16)));
                bf[nj * 2 + 0][0] = q[0]; bf[nj * 2 + 0][1] = q[2];
                bf[nj * 2 + 1][0] = q[1]; bf[nj * 2 + 1][1] = q[3];
            }
#pragma unroll
            for (int mi = 0; mi < 2; mi++)
#pragma unroll
                for (int ni = 0; ni < 8; ni++)
                    mma16(acc[mi][ni], af[mi], bf[ni]);
        }
        __syncthreads();
    }

#pragma unroll
    for (int mi = 0; mi < 2; mi++) {
#pragma unroll
        for (int r = 0; r < 2; r++) {
            const int gm = row0 + wm + mi * 16 + g + r * 8;
            if (gm >= M) continue;
#pragma unroll
            for (int ni = 0; ni < 8; ni++) {
                const int gn = col0 + wn + ni * 8 + 2 * t;
                float v0 = acc[mi][ni][r * 2 + 0] + bias[gn];
                float v1 = acc[mi][ni][r * 2 + 1] + bias[gn + 1];
                *(__half2*)(outp + (size_t)gm * N + gn) = __floats2half2_rn(v0, v1);
            }
        }
    }
}

// ============================================================================
// Merged prologue: ln1 (BLQ blocks) + lvl0 (BTP blocks) + weight cvt (272).
// ============================================================================
__global__ __launch_bounds__(128) void k_pre(
    const float* __restrict__ x, const float* __restrict__ pe,
    const float* __restrict__ lp,
    const float* __restrict__ g1, const float* __restrict__ be1,
    const float* __restrict__ g2, const float* __restrict__ be2,
    const float* __restrict__ w0, const float* __restrict__ w1,
    const float* __restrict__ w2, const float* __restrict__ w3,
    const float* __restrict__ w4, const float* __restrict__ w5,
    const float* __restrict__ w6, const float* __restrict__ w7,
    const float* __restrict__ b_off, const float* __restrict__ b_attn)
{
    const int bid = blockIdx.x;
    const int c = threadIdx.x;

    if (bid < BLQ) {
        int row = bid;
        int b = row / LQ; int lq = row - b * LQ;
        int l = lq & 3; int tp = lq >> 2;
        size_t xi = ((size_t)(b * TT * PP + tp) * NLVL + (l + 1)) * CC + c;
        float v = x[xi];

        __shared__ float sh[8];
        float s = v;
        for (int o = 16; o > 0; o >>= 1) s += __shfl_xor_sync(0xffffffffu, s, o);
        if ((c & 31) == 0) sh[c >> 5] = s;
        __syncthreads();
        float mean = (sh[0] + sh[1] + sh[2] + sh[3]) * (1.f / CC);
        float dv = v - mean;
        float q2 = dv * dv;
        for (int o = 16; o > 0; o >>= 1) q2 += __shfl_xor_sync(0xffffffffu, q2, o);
        if ((c & 31) == 0) sh[4 + (c >> 5)] = q2;
        __syncthreads();
        float var = (sh[4] + sh[5] + sh[6] + sh[7]) * (1.f / CC);
        float xn = dv * rsqrtf(var + 1e-5f) * g1[c] + be1[c];
        g_XNh[(size_t)row * CC + c] = __float2half_rn(xn);
        g_Qh [(size_t)row * CC + c] = __float2half_rn(xn + pe[(size_t)lq * CC + c] + lp[(size_t)lq * CC + c]);
    } else if (bid < BLQ + BTP) {
        int btp = bid - BLQ;
        size_t rowoff = (size_t)btp * NLVL * CC;
        float v = x[rowoff + c];
        g_XCAT[rowoff + c] = v;

        __shared__ float sh2[8];
        float s = v;
        for (int o = 16; o > 0; o >>= 1) s += __shfl_xor_sync(0xffffffffu, s, o);
        if ((c & 31) == 0) sh2[c >> 5] = s;
        __syncthreads();
        float mean = (sh2[0] + sh2[1] + sh2[2] + sh2[3]) * (1.f / CC);
        float dv = v - mean;
        float q2 = dv * dv;
        for (int o = 16; o > 0; o >>= 1) q2 += __shfl_xor_sync(0xffffffffu, q2, o);
        if ((c & 31) == 0) sh2[4 + (c >> 5)] = q2;
        __syncthreads();
        float var = (sh2[4] + sh2[5] + sh2[6] + sh2[7]) * (1.f / CC);
        g_XN2h[rowoff + c] = __float2half_rn(dv * rsqrtf(var + 1e-5f) * g2[c] + be2[c]);
    } else {
        int wb = bid - BLQ - BTP;             // 0..271
        if (wb == 0 && c < 128) {
            g_Bcat[c]       = b_off[c];
            g_Bcat[c + 128] = b_off[c + 128];
            g_Bcat[c + 256] = b_attn[c];
        }
        for (int idx = wb * 128 + c; idx < WTOTAL; idx += 272 * 128) {
            const float* src; int off;
            if      (idx < WOFF_ATTN) { src = w0; off = idx; }
            else if (idx < WOFF_VAL ) { src = w1; off = idx - WOFF_ATTN; }
            else if (idx < WOFF_OUT ) { src = w2; off = idx - WOFF_VAL; }
            else if (idx < WOFF_IN  ) { src = w3; off = idx - WOFF_OUT; }
            else if (idx < WOFF_OUTW) { src = w4; off = idx - WOFF_IN; }
            else if (idx < WOFF_FC1 ) { src = w5; off = idx - WOFF_OUTW; }
            else if (idx < WOFF_FC2 ) { src = w6; off = idx - WOFF_FC1; }
            else                      { src = w7; off = idx - WOFF_FC2; }
            g_Wh[idx] = __float2half_rn(src[off]);
        }
    }
}

// ============================================================================
// Deformable sampling with cp.async-pipelined gathers.
// 16 threads/row, 8 rows/block. Waves of 4 points x 4 corners = 16
// outstanding 16B cp.asyncs per thread, staged in smem, then reduced.
// smem: sOFF 12KB + sG 32KB = 44KB static.
// ============================================================================
#define DEF_RPB 8
__global__ __launch_bounds__(128) void k_deform(const float* __restrict__ refp)
{
    __shared__ float sOFF[DEF_RPB][384];
    __shared__ __align__(16) uint4 sG[4][4][128];   // [pt-in-wave][corner][tid]
    const int row0 = blockIdx.x * DEF_RPB;
    const int tid = threadIdx.x;
    const uint32_t sgb = (uint32_t)__cvta_generic_to_shared(&sG[0][0][tid]);

    for (int idx = tid; idx < DEF_RPB * 192; idx += 128) {
        int rr = idx / 192, c2 = idx - rr * 192;
        float2 v = __half22float2(*(const __half2*)(g_OFFAWh + (size_t)(row0 + rr) * 384 + c2 * 2));
        sOFF[rr][c2 * 2 + 0] = v.x;
        sOFF[rr][c2 * 2 + 1] = v.y;
    }
    __syncthreads();

    const int rr = tid >> 4;
    const int s = tid & 15;
    const int row = row0 + rr;
    const int b = row / LQ; const int lq = row - b * LQ;
    const int tp = lq >> 2; const int p = tp % PP; const int t = tp / PP;
    const int h = s >> 1, dq = s & 1;
    const float refx = refp[(((size_t)b * TT + t) * PP + p) * 2 + 0];
    const float refy = refp[(((size_t)b * TT + t) * PP + p) * 2 + 1];

    const float* awp = &sOFF[rr][256 + h * 16];
    float w[16], mx = -1e30f;
#pragma unroll
    for (int i = 0; i < 16; i++) { w[i] = awp[i]; mx = fmaxf(mx, w[i]); }
    float den = 0.f;
#pragma unroll
    for (int i = 0; i < 16; i++) { w[i] = __expf(w[i] - mx); den += w[i]; }
    float inv = 1.f / den;

    const float*  offp  = &sOFF[rr][h * 32];
    const __half* vbase = g_VALh + (size_t)b * LQ * CC + h * 16 + dq * 8;
    float acc[8];
#pragma unroll
    for (int j = 0; j < 8; j++) acc[j] = 0.f;

    for (int wv = 0; wv < 4; wv++) {
        float cw[4][4];    // [pi][corner] combined bilinear*softmax weights
#pragma unroll
        for (int pi = 0; pi < 4; pi++) {
            const int pt = wv * 4 + pi;
            const int l = pt >> 2;
            float ox = offp[pt * 2 + 0];
            float oy = offp[pt * 2 + 1];
            float fx = refx * PP + ox - 0.5f;
            float fy = refy * TT + oy - 0.5f;
            float x0f = floorf(fx), y0f = floorf(fy);
            int x0 = (int)x0f, y0 = (int)y0f;
            float wx1 = fx - x0f, wy1 = fy - y0f;
            float wx0 = 1.f - wx1, wy0 = 1.f - wy1;
            bool xi0 = (x0 >= 0) && (x0 < PP);
            bool xi1 = (x0 + 1 >= 0) && (x0 + 1 < PP);
            bool yi0 = (y0 >= 0) && (y0 < TT);
            bool yi1 = (y0 + 1 >= 0) && (y0 + 1 < TT);
            float ww = w[pt];
            cw[pi][0] = wy0 * wx0 * ww;
            cw[pi][1] = wy0 * wx1 * ww;
            cw[pi][2] = wy1 * wx0 * ww;
            cw[pi][3] = wy1 * wx1 * ww;
            const uint32_t sp = sgb + (uint32_t)(pi * 4) * 2048;
            cpa16(sp         , vbase + ((size_t)(y0 * PP + x0) * LL + l) * CC,           yi0 && xi0);
            cpa16(sp + 2048  , vbase + ((size_t)(y0 * PP + x0 + 1) * LL + l) * CC,       yi0 && xi1);
            cpa16(sp + 4096  , vbase + ((size_t)((y0 + 1) * PP + x0) * LL + l) * CC,     yi1 && xi0);
            cpa16(sp + 6144  , vbase + ((size_t)((y0 + 1) * PP + x0 + 1) * LL + l) * CC, yi1 && xi1);
        }
        CP_COMMIT();
        CP_WAIT(0);
#pragma unroll
        for (int pi = 0; pi < 4; pi++) {
#pragma unroll
            for (int c = 0; c < 4; c++) {
                uint4 q = sG[pi][c][tid];
                const __half2* hp = (const __half2*)&q;
                float ww = cw[pi][c];
#pragma unroll
                for (int j = 0; j < 4; j++) {
                    float2 f = __half22float2(hp[j]);
                    acc[2 * j + 0] = fmaf(f.x, ww, acc[2 * j + 0]);
                    acc[2 * j + 1] = fmaf(f.y, ww, acc[2 * j + 1]);
                }
            }
        }
    }
    __half2 ho[4];
#pragma unroll
    for (int j = 0; j < 4; j++)
        ho[j] = __floats2half2_rn(acc[2 * j] * inv, acc[2 * j + 1] * inv);
    *(uint4*)(g_Oh + (size_t)row * CC + h * 16 + dq * 8) = *(uint4*)ho;
}

// ---------------- per-(bt,head) self-attention (fp16 QKV) ------------------
__global__ void k_attn()
{
    int bt = blockIdx.x, h = blockIdx.y;
    __shared__ float Qs[SS][DHH], Ks[SS][DHH], Vs[SS][DHH];
    int tid = threadIdx.x;
    for (int i = tid; i < SS * DHH; i += 128) {
        int s = i >> 4, d = i & 15;
        const __half* base = g_QKVh + ((size_t)bt * SS + s) * 384 + h * 16 + d;
        Qs[s][d] = __half2float(base[0]);
        Ks[s][d] = __half2float(base[128]);
        Vs[s][d] = __half2float(base[256]);
    }
    __syncthreads();
    if (tid < SS) {
        float qv[16];
#pragma unroll
        for (int d = 0; d < 16; d++) qv[d] = Qs[tid][d];
        float mx = -1e30f;
        for (int k = 0; k < SS; k++) {
            float sdot = 0.f;
#pragma unroll
            for (int d = 0; d < 16; d++) sdot = fmaf(qv[d], Ks[k][d], sdot);
            mx = fmaxf(mx, sdot * 0.25f);
        }
        float den = 0.f, o[16];
#pragma unroll
        for (int d = 0; d < 16; d++) o[d] = 0.f;
        for (int k = 0; k < SS; k++) {
            float sdot = 0.f;
#pragma unroll
            for (int d = 0; d < 16; d++) sdot = fmaf(qv[d], Ks[k][d], sdot);
            float e = __expf(sdot * 0.25f - mx);
            den += e;
#pragma unroll
            for (int d = 0; d < 16; d++) o[d] = fmaf(e, Vs[k][d], o[d]);
        }
        float inv = 1.f / den;
        __half* outp = g_ATTOh + ((size_t)bt * SS + tid) * CC + h * 16;
#pragma unroll
        for (int d = 0; d < 16; d++) outp[d] = __float2half_rn(o[d] * inv);
    }
}

// ---------------- host launch ----------------------------------------------
static inline void launch_small(const __half* A, const __half* W, const float* bias,
                                const float* res, void* out, int M, int N, int K,
                                int epi, int outHalf, int perm = 0,
                                const float* lnG = nullptr, const float* lnB = nullptr,
                                __half* out2 = nullptr)
{
    dim3 grid(N / 128, (M + 63) / 64);
    k_gemm_h<<<grid, 128, GEMM_SMEM>>>(A, W, bias, res ? res : (const float*)A,
                                       out, M, N, K, epi, outHalf, perm, lnG, lnB, out2);
}
static inline void launch_big(const __half* A, const __half* W, const float* bias,
                              const float* res, void* out, int M, int N, int K,
                              int epi, int outHalf)
{
    dim3 grid(N / 128, (M + 127) / 128);
    k_gemm_big<<<grid, 256, BIG_SMEM>>>(A, W, bias, res ? res : (const float*)A,
                                        out, M, N, K, epi, outHalf);
}

extern "C" void kernel_launch(void* const* d_in, const int* in_sizes, int n_in,
                              void* d_out, int out_size)
{
    (void)in_sizes; (void)n_in; (void)out_size;
    const float* x        = (const float*)d_in[0];
    const float* refp     = (const float*)d_in[1];
    const float* pe_buf   = (const float*)d_in[2];
    const float* learn_pos= (const float*)d_in[3];
    const float* w_off    = (const float*)d_in[4];
    const float* b_off    = (const float*)d_in[5];
    const float* w_attn   = (const float*)d_in[6];
    const float* b_attn   = (const float*)d_in[7];
    const float* w_val    = (const float*)d_in[8];
    const float* b_val    = (const float*)d_in[9];
    const float* w_out    = (const float*)d_in[10];
    const float* b_out    = (const float*)d_in[11];
    const float* in_w     = (const float*)d_in[12];
    const float* in_b     = (const float*)d_in[13];
    const float* out_w    = (const float*)d_in[14];
    const float* b_out2   = (const float*)d_in[15];
    const float* fc1_w    = (const float*)d_in[16];
    const float* fc1_b    = (const float*)d_in[17];
    const float* fc2_w    = (const float*)d_in[18];
    const float* fc2_b    = (const float*)d_in[19];
    const float* g1       = (const float*)d_in[20];
    const float* be1      = (const float*)d_in[21];
    const float* g2       = (const float*)d_in[22];
    const float* be2      = (const float*)d_in[23];
    const float* g3       = (const float*)d_in[24];
    const float* be3      = (const float*)d_in[25];
    float* out = (float*)d_out;

    cudaFuncSetAttribute(k_gemm_h,   cudaFuncAttributeMaxDynamicSharedMemorySize, GEMM_SMEM);
    cudaFuncSetAttribute(k_projs,    cudaFuncAttributeMaxDynamicSharedMemorySize, GEMM_SMEM);
    cudaFuncSetAttribute(k_gemm_big, cudaFuncAttributeMaxDynamicSharedMemorySize, BIG_SMEM);

    float *pXCAT, *pXCAT2;
    __half *pOh, *pXN2h, *pQKVh, *pATTOh, *pXN3h, *pHIDh, *pWh;
    cudaGetSymbolAddress((void**)&pXCAT,  g_XCAT);
    cudaGetSymbolAddress((void**)&pXCAT2, g_XCAT2);
    cudaGetSymbolAddress((void**)&pOh,    g_Oh);
    cudaGetSymbolAddress((void**)&pXN2h,  g_XN2h);
    cudaGetSymbolAddress((void**)&pQKVh,  g_QKVh);
    cudaGetSymbolAddress((void**)&pATTOh, g_ATTOh);
    cudaGetSymbolAddress((void**)&pXN3h,  g_XN3h);
    cudaGetSymbolAddress((void**)&pHIDh,  g_HIDh);
    cudaGetSymbolAddress((void**)&pWh,    g_Wh);

    // 1) merged prologue: LN1 + lvl0(LN2) + weight cvt
    k_pre<<<BLQ + BTP + 272, 128>>>(x, pe_buf, learn_pos, g1, be1, g2, be2,
                                    w_off, w_attn, w_val, w_out, in_w, out_w,
                                    fc1_w, fc2_w, b_off, b_attn);
    // 2) merged projections: offaw (N=384) + val (N=128) -> fp16
    {
        dim3 grid(4, (BLQ + 63) / 64);
        k_projs<<<grid, 128, GEMM_SMEM>>>(b_val);
    }
    // 3) deformable sampling (cp.async pipelined)
    k_deform<<<BLQ / DEF_RPB, 128>>>(refp);
    // 4) out-proj + residual(from x, permuted) + concat + fused LN2 [epi3, perm]
    launch_small(pOh, pWh + WOFF_OUT, b_out, x, pXCAT, BLQ, 128, CC, 3, 0, 1,
                 g2, be2, pXN2h);
    // 5) QKV GEMM (N=384) -> fp16  [BIG]
    launch_big(pXN2h, pWh + WOFF_IN, in_b, nullptr, pQKVh, TOK, 384, CC, 0, 1);
    // 6) self-attention
    k_attn<<<dim3(BB * TT, HH), 128>>>();
    // 7) attention out-proj + residual + fused LN3 [epi3]
    launch_small(pATTOh, pWh + WOFF_OUTW, b_out2, pXCAT, pXCAT2, TOK, 128, CC, 3, 0, 0,
                 g3, be3, pXN3h);
    // 8) FC1 + GELU (N=512) -> fp16 [BIG]
    launch_big(pXN3h, pWh + WOFF_FC1, fc1_b, nullptr, pHIDh, TOK, 512, CC, 2, 1);
    // 9) FC2 + residual -> final output (K=512) [BIG]
    launch_big(pHIDh, pWh + WOFF_FC2, fc2_b, pXCAT2, out, TOK, 128, 512, 1, 0);
}

// round 14
// speedup vs baseline: 1.0273x; 1.0131x over previous
#include <cuda_runtime.h>
#include <cuda_fp16.h>
#include <math.h>
#include <stdint.h>

// Problem constants
#define TT   243
#define PP   17
#define LL   4
#define CC   128
#define HH   8
#define NPT  4
#define DHH  16
#define BB   2
#define LQ   (TT*PP*LL)        // 16524
#define BLQ  (BB*LQ)           // 33048
#define NLVL 5
#define BTP  (BB*TT*PP)        // 8262
#define TOK  (BTP*NLVL)        // 41310
#define SS   (PP*NLVL)         // 85

// ---------------- scratch (device globals; no allocations) ----------------
__device__ float  g_XCAT [(size_t)TOK*CC];
__device__ float  g_XCAT2[(size_t)TOK*CC];
__device__ __half g_OFFAWh[(size_t)BLQ*384];
__device__ __half g_Qh   [(size_t)BLQ*CC];
__device__ __half g_XNh  [(size_t)BLQ*CC];
__device__ __half g_VALh [(size_t)BLQ*CC];
__device__ __half g_Oh   [(size_t)BLQ*CC];
__device__ __half g_XN2h [(size_t)TOK*CC];
__device__ __half g_QKVh [(size_t)TOK*384];
__device__ __half g_ATTOh[(size_t)TOK*CC];
__device__ __half g_XN3h [(size_t)TOK*CC];
__device__ __half g_HIDh [(size_t)TOK*512];
#define WOFF_OFF   0
#define WOFF_ATTN  32768
#define WOFF_VAL   49152
#define WOFF_OUT   65536
#define WOFF_IN    81920
#define WOFF_OUTW  131072
#define WOFF_FC1   147456
#define WOFF_FC2   212992
#define WTOTAL     278528
__device__ __half g_Wh[WTOTAL];
__device__ float  g_Bcat[384];

// ---------------- PTX helpers ----------------------------------------------
__device__ __forceinline__ void cpa16(uint32_t dst, const void* src, bool valid) {
    int sz = valid ? 16 : 0;
    asm volatile("cp.async.cg.shared.global [%0], [%1], 16, %2;\n"
                 :: "r"(dst), "l"(src), "r"(sz));
}
#define CP_COMMIT() asm volatile("cp.async.commit_group;\n" ::: "memory")
#define CP_WAIT(n)  asm volatile("cp.async.wait_group %0;\n" :: "n"(n) : "memory")

__device__ __forceinline__ void ldm4(uint32_t* r, uint32_t addr) {
    asm volatile("ldmatrix.sync.aligned.m8n8.x4.shared.b16 {%0,%1,%2,%3}, [%4];\n"
                 : "=r"(r[0]), "=r"(r[1]), "=r"(r[2]), "=r"(r[3]) : "r"(addr));
}
__device__ __forceinline__ void mma16(float* c, const uint32_t* a, const uint32_t* b) {
    asm volatile("mma.sync.aligned.m16n8k16.row.col.f32.f16.f16.f32 "
                 "{%0,%1,%2,%3},{%4,%5,%6,%7},{%8,%9},{%0,%1,%2,%3};\n"
                 : "+f"(c[0]), "+f"(c[1]), "+f"(c[2]), "+f"(c[3])
                 : "r"(a[0]), "r"(a[1]), "r"(a[2]), "r"(a[3]), "r"(b[0]), "r"(b[1]));
}

// permuted destination row for the xcat concat (also the x source row!)
__device__ __forceinline__ int xcat_row(int gm) {
    int b = gm / LQ;
    int rem = gm - b * LQ;
    return (b * (TT * PP) + (rem >> 2)) * 5 + (rem & 3) + 1;
}

// ============================================================================
// BIG GEMM: BM=128, BN=128, BK=64, 256 threads (QKV / FC1 / FC2).
// ============================================================================
#define BIG_STG  32768
#define BIG_SMEM 65536

__device__ __forceinline__ void big_load_stage(
    const __half* __restrict__ A, const __half* __restrict__ W, uint32_t sb,
    int st, int kt, int row0, int col0, int M, int K, int tid)
{
    const int r0 = tid >> 3, ck = tid & 7;
    const uint32_t base = sb + st * BIG_STG;
#pragma unroll
    for (int i = 0; i < 4; i++) {
        int r = r0 + i * 32;
        uint32_t swoff = (uint32_t)(r * 128 + ((ck ^ (r & 7)) * 16));
        int gm = row0 + r;
        cpa16(base + swoff, A + (size_t)gm * K + (size_t)kt * 64 + ck * 8, gm < M);
        cpa16(base + 16384 + swoff,
              W + (size_t)(col0 + r) * K + (size_t)kt * 64 + ck * 8, true);
    }
}

__global__ __launch_bounds__(256, 2) void k_gemm_big(
    const __half* __restrict__ A, const __half* __restrict__ W,
    const float* __restrict__ bias, const float* __restrict__ res,
    void* __restrict__ outp, int M, int N, int K, int epi, int outHalf)
{
    extern __shared__ __align__(1024) char sm[];
    uint32_t sb = (uint32_t)__cvta_generic_to_shared(sm);
    const int tid = threadIdx.x, lane = tid & 31, warp = tid >> 5;
    const int g = lane >> 2, t = lane & 3;
    const int wm = (warp >> 1) * 32, wn = (warp & 1) * 64;
    const int row0 = blockIdx.y * 128, col0 = blockIdx.x * 128;
    const int KT = K >> 6;

    float acc[2][8][4];
#pragma unroll
    for (int mi = 0; mi < 2; mi++)
#pragma unroll
        for (int ni = 0; ni < 8; ni++)
#pragma unroll
            for (int r = 0; r < 4; r++) acc[mi][ni][r] = 0.f;

    big_load_stage(A, W, sb, 0, 0, row0, col0, M, K, tid);
    CP_COMMIT();

    for (int kt = 0; kt < KT; kt++) {
        const int s = kt & 1;
        if (kt + 1 < KT) {
            big_load_stage(A, W, sb, s ^ 1, kt + 1, row0, col0, M, K, tid);
            CP_COMMIT();
            CP_WAIT(1);
        } else {
            CP_WAIT(0);
        }
        __syncthreads();

        const uint32_t aS = sb + s * BIG_STG;
        const uint32_t bS = aS + 16384;
        const int rlow = lane & 15, hi = lane >> 4;
#pragma unroll
        for (int kk = 0; kk < 4; kk++) {
            uint32_t af[2][4];
#pragma unroll
            for (int mi = 0; mi < 2; mi++) {
                int r = wm + mi * 16 + rlow;
                int ck = kk * 2 + hi;
                ldm4(af[mi], aS + (uint32_t)(r * 128 + ((ck ^ (r & 7)) * 16)));
            }
            uint32_t bf[8][2];
#pragma unroll
            for (int nj = 0; nj < 4; nj++) {
                int r = wn + nj * 16 + rlow;
                int ck = kk * 2 + hi;
                uint32_t q[4];
                ldm4(q, bS + (uint32_t)(r * 128 + ((ck ^ (r & 7)) * 16)));
                bf[nj * 2 + 0][0] = q[0]; bf[nj * 2 + 0][1] = q[2];
                bf[nj * 2 + 1][0] = q[1]; bf[nj * 2 + 1][1] = q[3];
            }
#pragma unroll
            for (int mi = 0; mi < 2; mi++)
#pragma unroll
                for (int ni = 0; ni < 8; ni++)
                    mma16(acc[mi][ni], af[mi], bf[ni]);
        }
        __syncthreads();
    }

#pragma unroll
    for (int mi = 0; mi < 2; mi++) {
#pragma unroll
        for (int r = 0; r < 2; r++) {
            const int gm = row0 + wm + mi * 16 + g + r * 8;
            if (gm >= M) continue;
            const float* rp = res + (size_t)gm * N;
#pragma unroll
            for (int ni = 0; ni < 8; ni++) {
                const int gn = col0 + wn + ni * 8 + 2 * t;
                float v0 = acc[mi][ni][r * 2 + 0] + bias[gn];
                float v1 = acc[mi][ni][r * 2 + 1] + bias[gn + 1];
                if (epi == 1) {
                    v0 += rp[gn];
                    v1 += rp[gn + 1];
                } else if (epi == 2) {
                    v0 = 0.5f * v0 * (1.0f + erff(v0 * 0.7071067811865475f));
                    v1 = 0.5f * v1 * (1.0f + erff(v1 * 0.7071067811865475f));
                }
                if (outHalf) {
                    *(__half2*)((__half*)outp + (size_t)gm * N + gn) = __floats2half2_rn(v0, v1);
                } else {
                    *(float2*)((float*)outp + (size_t)gm * N + gn) = make_float2(v0, v1);
                }
            }
        }
    }
}

// ============================================================================
// SMALL GEMM: BM=64, BN=128, BK=64, 128 threads; epi3 = residual + LN fusion.
// ============================================================================
#define STG 24576
#define SREDOFF 49152
#define GEMM_SMEM 50176

__device__ __forceinline__ void gemm_load_stage(
    const __half* __restrict__ A, const __half* __restrict__ W, uint32_t sb,
    int st, int kt, int row0, int col0, int M, int K, int tid)
{
    const int r0 = tid >> 3, ck = tid & 7;
    const uint32_t base = sb + st * STG;
#pragma unroll
    for (int i = 0; i < 4; i++) {
        int r = r0 + i * 16;
        uint32_t swoff = (uint32_t)(r * 128 + ((ck ^ (r & 7)) * 16));
        int gm = row0 + r;
        cpa16(base + swoff, A + (size_t)gm * K + (size_t)kt * 64 + ck * 8, gm < M);
    }
#pragma unroll
    for (int i = 0; i < 8; i++) {
        int r = r0 + i * 16;
        uint32_t swoff = (uint32_t)(r * 128 + ((ck ^ (r & 7)) * 16));
        cpa16(base + 8192 + swoff,
              W + (size_t)(col0 + r) * K + (size_t)kt * 64 + ck * 8, true);
    }
}

__global__ __launch_bounds__(128, 4) void k_gemm_h(
    const __half* __restrict__ A, const __half* __restrict__ W,
    const float* __restrict__ bias, const float* __restrict__ res,
    void* __restrict__ outp, int M, int N, int K, int epi, int outHalf, int perm,
    const float* __restrict__ lnG, const float* __restrict__ lnB,
    __half* __restrict__ out2)
{
    extern __shared__ __align__(1024) char sm[];
    uint32_t sb = (uint32_t)__cvta_generic_to_shared(sm);
    float* sred = (float*)(sm + SREDOFF);
    const int tid = threadIdx.x, lane = tid & 31, warp = tid >> 5;
    const int g = lane >> 2, t = lane & 3;
    const int wm = (warp >> 1) * 32, wn = (warp & 1) * 64;
    const int row0 = blockIdx.y * 64, col0 = blockIdx.x * 128;
    const int KT = K >> 6;

    float acc[2][8][4];
#pragma unroll
    for (int mi = 0; mi < 2; mi++)
#pragma unroll
        for (int ni = 0; ni < 8; ni++)
#pragma unroll
            for (int r = 0; r < 4; r++) acc[mi][ni][r] = 0.f;

    gemm_load_stage(A, W, sb, 0, 0, row0, col0, M, K, tid);
    CP_COMMIT();

    for (int kt = 0; kt < KT; kt++) {
        const int s = kt & 1;
        if (kt + 1 < KT) {
            gemm_load_stage(A, W, sb, s ^ 1, kt + 1, row0, col0, M, K, tid);
            CP_COMMIT();
            CP_WAIT(1);
        } else {
            CP_WAIT(0);
        }
        __syncthreads();

        const uint32_t aS = sb + s * STG;
        const uint32_t bS = aS + 8192;
        const int rlow = lane & 15, hi = lane >> 4;
#pragma unroll
        for (int kk = 0; kk < 4; kk++) {
            uint32_t af[2][4];
#pragma unroll
            for (int mi = 0; mi < 2; mi++) {
                int r = wm + mi * 16 + rlow;
                int ck = kk * 2 + hi;
                ldm4(af[mi], aS + (uint32_t)(r * 128 + ((ck ^ (r & 7)) * 16)));
            }
            uint32_t bf[8][2];
#pragma unroll
            for (int nj = 0; nj < 4; nj++) {
                int r = wn + nj * 16 + rlow;
                int ck = kk * 2 + hi;
                uint32_t q[4];
                ldm4(q, bS + (uint32_t)(r * 128 + ((ck ^ (r & 7)) * 16)));
                bf[nj * 2 + 0][0] = q[0]; bf[nj * 2 + 0][1] = q[2];
                bf[nj * 2 + 1][0] = q[1]; bf[nj * 2 + 1][1] = q[3];
            }
#pragma unroll
            for (int mi = 0; mi < 2; mi++)
#pragma unroll
                for (int ni = 0; ni < 8; ni++)
                    mma16(acc[mi][ni], af[mi], bf[ni]);
        }
        __syncthreads();
    }

#pragma unroll
    for (int mi = 0; mi < 2; mi++) {
#pragma unroll
        for (int r = 0; r < 2; r++) {
            const int gm = row0 + wm + mi * 16 + g + r * 8;
            float psum = 0.f, psq = 0.f;
            if (gm < M) {
                const size_t orow = (epi == 3 && perm) ? (size_t)xcat_row(gm) : (size_t)gm;
                const float* rp = res + orow * N;
#pragma unroll
                for (int ni = 0; ni < 8; ni++) {
                    const int gn = col0 + wn + ni * 8 + 2 * t;
                    float v0 = acc[mi][ni][r * 2 + 0] + bias[gn];
                    float v1 = acc[mi][ni][r * 2 + 1] + bias[gn + 1];
                    if (epi == 1 || epi == 3) {
                        v0 += rp[gn];
                        v1 += rp[gn + 1];
                    } else if (epi == 2) {
                        v0 = 0.5f * v0 * (1.0f + erff(v0 * 0.7071067811865475f));
                        v1 = 0.5f * v1 * (1.0f + erff(v1 * 0.7071067811865475f));
                    }
                    if (outHalf) {
                        *(__half2*)((__half*)outp + orow * N + gn) = __floats2half2_rn(v0, v1);
                    } else {
                        *(float2*)((float*)outp + orow * N + gn) = make_float2(v0, v1);
                    }
                    acc[mi][ni][r * 2 + 0] = v0;
                    acc[mi][ni][r * 2 + 1] = v1;
                    psum += v0 + v1;
                    psq  += v0 * v0 + v1 * v1;
                }
            }
            if (epi == 3) {
                psum += __shfl_xor_sync(0xffffffffu, psum, 1);
                psum += __shfl_xor_sync(0xffffffffu, psum, 2);
                psq  += __shfl_xor_sync(0xffffffffu, psq, 1);
                psq  += __shfl_xor_sync(0xffffffffu, psq, 2);
                if (t == 0) {
                    int lr = wm + mi * 16 + g + r * 8;
                    sred[lr * 4 + (warp & 1) * 2 + 0] = psum;
                    sred[lr * 4 + (warp & 1) * 2 + 1] = psq;
                }
            }
        }
    }
    if (epi == 3) {
        __syncthreads();
#pragma unroll
        for (int mi = 0; mi < 2; mi++) {
#pragma unroll
            for (int r = 0; r < 2; r++) {
                const int gm = row0 + wm + mi * 16 + g + r * 8;
                if (gm >= M) continue;
                const size_t orow = perm ? (size_t)xcat_row(gm) : (size_t)gm;
                const int lr = wm + mi * 16 + g + r * 8;
                float sum = sred[lr * 4 + 0] + sred[lr * 4 + 2];
                float sq  = sred[lr * 4 + 1] + sred[lr * 4 + 3];
                float mean = sum * (1.f / 128.f);
                float var = sq * (1.f / 128.f) - mean * mean;
                float rstd = rsqrtf(var + 1e-5f);
#pragma unroll
                for (int ni = 0; ni < 8; ni++) {
                    const int gn = col0 + wn + ni * 8 + 2 * t;
                    float a0 = (acc[mi][ni][r * 2 + 0] - mean) * rstd * lnG[gn] + lnB[gn];
                    float a1 = (acc[mi][ni][r * 2 + 1] - mean) * rstd * lnG[gn + 1] + lnB[gn + 1];
                    *(__half2*)(out2 + orow * 128 + gn) = __floats2half2_rn(a0, a1);
                }
            }
        }
    }
}

// ============================================================================
// Merged projection GEMM: offaw (N=384, cols 0-2) + val (N=128, col 3).
// ============================================================================
__global__ __launch_bounds__(128, 4) void k_projs(const float* __restrict__ b_val)
{
    extern __shared__ __align__(1024) char sm[];
    uint32_t sb = (uint32_t)__cvta_generic_to_shared(sm);
    const int tid = threadIdx.x, lane = tid & 31, warp = tid >> 5;
    const int g = lane >> 2, t = lane & 3;
    const int wm = (warp >> 1) * 32, wn = (warp & 1) * 64;
    const int row0 = blockIdx.y * 64;

    const __half* A; const __half* W; const float* bias; __half* outp; int N; int col0;
    if (blockIdx.x < 3) {
        A = g_Qh;  W = g_Wh + WOFF_OFF; bias = g_Bcat; outp = g_OFFAWh;
        N = 384; col0 = blockIdx.x * 128;
    } else {
        A = g_XNh; W = g_Wh + WOFF_VAL; bias = b_val;  outp = g_VALh;
        N = 128; col0 = 0;
    }
    const int M = BLQ, K = CC, KT = 2;

    float acc[2][8][4];
#pragma unroll
    for (int mi = 0; mi < 2; mi++)
#pragma unroll
        for (int ni = 0; ni < 8; ni++)
#pragma unroll
            for (int r = 0; r < 4; r++) acc[mi][ni][r] = 0.f;

    gemm_load_stage(A, W, sb, 0, 0, row0, col0, M, K, tid);
    CP_COMMIT();

    for (int kt = 0; kt < KT; kt++) {
        const int s = kt & 1;
        if (kt + 1 < KT) {
            gemm_load_stage(A, W, sb, s ^ 1, kt + 1, row0, col0, M, K, tid);
            CP_COMMIT();
            CP_WAIT(1);
        } else {
            CP_WAIT(0);
        }
        __syncthreads();

        const uint32_t aS = sb + s * STG;
        const uint32_t bS = aS + 8192;
        const int rlow = lane & 15, hi = lane >> 4;
#pragma unroll
        for (int kk = 0; kk < 4; kk++) {
            uint32_t af[2][4];
#pragma unroll
            for (int mi = 0; mi < 2; mi++) {
                int r = wm + mi * 16 + rlow;
                int ck = kk * 2 + hi;
                ldm4(af[mi], aS + (uint32_t)(r * 128 + ((ck ^ (r & 7)) * 16)));
            }
            uint32_t bf[8][2];
#pragma unroll
            for (int nj = 0; nj < 4; nj++) {
                int r = wn + nj * 16 + rlow;
                int ck = kk * 2 + hi;
                uint32_t q[4];
                ldm4(q, bS + (uint32_t)(r * 128 + ((ck ^ (r & 7)) * 16)));
                bf[nj * 2 + 0][0] = q[0]; bf[nj * 2 + 0][1] = q[2];
                bf[nj * 2 + 1][0] = q[1]; bf[nj * 2 + 1][1] = q[3];
            }
#pragma unroll
            for (int mi = 0; mi < 2; mi++)
#pragma unroll
                for (int ni = 0; ni < 8; ni++)
                    mma16(acc[mi][ni], af[mi], bf[ni]);
        }
        __syncthreads();
    }

#pragma unroll
    for (int mi = 0; mi < 2; mi++) {
#pragma unroll
        for (int r = 0; r < 2; r++) {
            const int gm = row0 + wm + mi * 16 + g + r * 8;
            if (gm >= M) continue;
#pragma unroll
            for (int ni = 0; ni < 8; ni++) {
                const int gn = col0 + wn + ni * 8 + 2 * t;
                float v0 = acc[mi][ni][r * 2 + 0] + bias[gn];
                float v1 = acc[mi][ni][r * 2 + 1] + bias[gn + 1];
                *(__half2*)(outp + (size_t)gm * N + gn) = __floats2half2_rn(v0, v1);
            }
        }
    }
}

// ============================================================================
// Merged prologue: ln1 (BLQ blocks) + lvl0 (BTP blocks) + weight cvt (272).
// ============================================================================
__global__ __launch_bounds__(128) void k_pre(
    const float* __restrict__ x, const float* __restrict__ pe,
    const float* __restrict__ lp,
    const float* __restrict__ g1, const float* __restrict__ be1,
    const float* __restrict__ g2, const float* __restrict__ be2,
    const float* __restrict__ w0, const float* __restrict__ w1,
    const float* __restrict__ w2, const float* __restrict__ w3,
    const float* __restrict__ w4, const float* __restrict__ w5,
    const float* __restrict__ w6, const float* __restrict__ w7,
    const float* __restrict__ b_off, const float* __restrict__ b_attn)
{
    const int bid = blockIdx.x;
    const int c = threadIdx.x;

    if (bid < BLQ) {
        int row = bid;
        int b = row / LQ; int lq = row - b * LQ;
        int l = lq & 3; int tp = lq >> 2;
        size_t xi = ((size_t)(b * TT * PP + tp) * NLVL + (l + 1)) * CC + c;
        float v = x[xi];

        __shared__ float sh[8];
        float s = v;
        for (int o = 16; o > 0; o >>= 1) s += __shfl_xor_sync(0xffffffffu, s, o);
        if ((c & 31) == 0) sh[c >> 5] = s;
        __syncthreads();
        float mean = (sh[0] + sh[1] + sh[2] + sh[3]) * (1.f / CC);
        float dv = v - mean;
        float q2 = dv * dv;
        for (int o = 16; o > 0; o >>= 1) q2 += __shfl_xor_sync(0xffffffffu, q2, o);
        if ((c & 31) == 0) sh[4 + (c >> 5)] = q2;
        __syncthreads();
        float var = (sh[4] + sh[5] + sh[6] + sh[7]) * (1.f / CC);
        float xn = dv * rsqrtf(var + 1e-5f) * g1[c] + be1[c];
        g_XNh[(size_t)row * CC + c] = __float2half_rn(xn);
        g_Qh [(size_t)row * CC + c] = __float2half_rn(xn + pe[(size_t)lq * CC + c] + lp[(size_t)lq * CC + c]);
    } else if (bid < BLQ + BTP) {
        int btp = bid - BLQ;
        size_t rowoff = (size_t)btp * NLVL * CC;
        float v = x[rowoff + c];
        g_XCAT[rowoff + c] = v;

        __shared__ float sh2[8];
        float s = v;
        for (int o = 16; o > 0; o >>= 1) s += __shfl_xor_sync(0xffffffffu, s, o);
        if ((c & 31) == 0) sh2[c >> 5] = s;
        __syncthreads();
        float mean = (sh2[0] + sh2[1] + sh2[2] + sh2[3]) * (1.f / CC);
        float dv = v - mean;
        float q2 = dv * dv;
        for (int o = 16; o > 0; o >>= 1) q2 += __shfl_xor_sync(0xffffffffu, q2, o);
        if ((c & 31) == 0) sh2[4 + (c >> 5)] = q2;
        __syncthreads();
        float var = (sh2[4] + sh2[5] + sh2[6] + sh2[7]) * (1.f / CC);
        g_XN2h[rowoff + c] = __float2half_rn(dv * rsqrtf(var + 1e-5f) * g2[c] + be2[c]);
    } else {
        int wb = bid - BLQ - BTP;             // 0..271
        if (wb == 0 && c < 128) {
            g_Bcat[c]       = b_off[c];
            g_Bcat[c + 128] = b_off[c + 128];
            g_Bcat[c + 256] = b_attn[c];
        }
        for (int idx = wb * 128 + c; idx < WTOTAL; idx += 272 * 128) {
            const float* src; int off;
            if      (idx < WOFF_ATTN) { src = w0; off = idx; }
            else if (idx < WOFF_VAL ) { src = w1; off = idx - WOFF_ATTN; }
            else if (idx < WOFF_OUT ) { src = w2; off = idx - WOFF_VAL; }
            else if (idx < WOFF_IN  ) { src = w3; off = idx - WOFF_OUT; }
            else if (idx < WOFF_OUTW) { src = w4; off = idx - WOFF_IN; }
            else if (idx < WOFF_FC1 ) { src = w5; off = idx - WOFF_OUTW; }
            else if (idx < WOFF_FC2 ) { src = w6; off = idx - WOFF_FC1; }
            else                      { src = w7; off = idx - WOFF_FC2; }
            g_Wh[idx] = __float2half_rn(src[off]);
        }
    }
}

// ============================================================================
// Deformable sampling, software-pipelined gathers:
// 8 waves x 2 points, double-buffered (wait_group 1) so wave i loads overlap
// wave i-1 reduction. smem: sOFF 12KB + sG 2x16KB = 44KB.
// ============================================================================
#define DEF_RPB 8
__global__ __launch_bounds__(128) void k_deform(const float* __restrict__ refp)
{
    __shared__ float sOFF[DEF_RPB][384];
    __shared__ __align__(16) uint4 sG[2][2][4][128];  // [buf][pt-in-wave][corner][tid]
    const int row0 = blockIdx.x * DEF_RPB;
    const int tid = threadIdx.x;
    const uint32_t sgb = (uint32_t)__cvta_generic_to_shared(&sG[0][0][0][tid]);

    for (int idx = tid; idx < DEF_RPB * 192; idx += 128) {
        int rr = idx / 192, c2 = idx - rr * 192;
        float2 v = __half22float2(*(const __half2*)(g_OFFAWh + (size_t)(row0 + rr) * 384 + c2 * 2));
        sOFF[rr][c2 * 2 + 0] = v.x;
        sOFF[rr][c2 * 2 + 1] = v.y;
    }
    __syncthreads();

    const int rr = tid >> 4;
    const int s = tid & 15;
    const int row = row0 + rr;
    const int b = row / LQ; const int lq = row - b * LQ;
    const int tp = lq >> 2; const int p = tp % PP; const int t = tp / PP;
    const int h = s >> 1, dq = s & 1;
    const float refx = refp[(((size_t)b * TT + t) * PP + p) * 2 + 0];
    const float refy = refp[(((size_t)b * TT + t) * PP + p) * 2 + 1];

    const float* awp = &sOFF[rr][256 + h * 16];
    float w[16], mx = -1e30f;
#pragma unroll
    for (int i = 0; i < 16; i++) { w[i] = awp[i]; mx = fmaxf(mx, w[i]); }
    float den = 0.f;
#pragma unroll
    for (int i = 0; i < 16; i++) { w[i] = __expf(w[i] - mx); den += w[i]; }
    float inv = 1.f / den;

    const float*  offp  = &sOFF[rr][h * 32];
    const __half* vbase = g_VALh + (size_t)b * LQ * CC + h * 16 + dq * 8;
    float acc[8];
#pragma unroll
    for (int j = 0; j < 8; j++) acc[j] = 0.f;

    float cw[2][2][4];   // [buf][pt-in-wave][corner]

    // issue a wave: 2 points x 4 corners into buffer `buf`
    auto issue_wave = [&](int wv, int buf) {
#pragma unroll
        for (int pi = 0; pi < 2; pi++) {
            const int pt = wv * 2 + pi;
            const int l = pt >> 2;
            float ox = offp[pt * 2 + 0];
            float oy = offp[pt * 2 + 1];
            float fx = refx * PP + ox - 0.5f;
            float fy = refy * TT + oy - 0.5f;
            float x0f = floorf(fx), y0f = floorf(fy);
            int x0 = (int)x0f, y0 = (int)y0f;
            float wx1 = fx - x0f, wy1 = fy - y0f;
            float wx0 = 1.f - wx1, wy0 = 1.f - wy1;
            bool xi0 = (x0 >= 0) && (x0 < PP);
            bool xi1 = (x0 + 1 >= 0) && (x0 + 1 < PP);
            bool yi0 = (y0 >= 0) && (y0 < TT);
            bool yi1 = (y0 + 1 >= 0) && (y0 + 1 < TT);
            float ww = w[pt];
            cw[buf][pi][0] = wy0 * wx0 * ww;
            cw[buf][pi][1] = wy0 * wx1 * ww;
            cw[buf][pi][2] = wy1 * wx0 * ww;
            cw[buf][pi][3] = wy1 * wx1 * ww;
            const uint32_t sp = sgb + (uint32_t)(buf * 8 + pi * 4) * 2048;
            cpa16(sp        , vbase + ((size_t)(y0 * PP + x0) * LL + l) * CC,           yi0 && xi0);
            cpa16(sp + 2048 , vbase + ((size_t)(y0 * PP + x0 + 1) * LL + l) * CC,       yi0 && xi1);
            cpa16(sp + 4096 , vbase + ((size_t)((y0 + 1) * PP + x0) * LL + l) * CC,     yi1 && xi0);
            cpa16(sp + 6144 , vbase + ((size_t)((y0 + 1) * PP + x0 + 1) * LL + l) * CC, yi1 && xi1);
        }
        CP_COMMIT();
    };
    auto reduce_wave = [&](int buf) {
#pragma unroll
        for (int pi = 0; pi < 2; pi++) {
#pragma unroll
            for (int c = 0; c < 4; c++) {
                uint4 q = sG[buf][pi][c][tid];
                const __half2* hp = (const __half2*)&q;
                float ww = cw[buf][pi][c];
#pragma unroll
                for (int j = 0; j < 4; j++) {
                    float2 f = __half22float2(hp[j]);
                    acc[2 * j + 0] = fmaf(f.x, ww, acc[2 * j + 0]);
                    acc[2 * j + 1] = fmaf(f.y, ww, acc[2 * j + 1]);
                }
            }
        }
    };

    issue_wave(0, 0);
#pragma unroll
    for (int wv = 1; wv < 8; wv++) {
        issue_wave(wv, wv & 1);
        CP_WAIT(1);               // previous wave complete
        reduce_wave((wv - 1) & 1);
    }
    CP_WAIT(0);
    reduce_wave(7 & 1);

    __half2 ho[4];
#pragma unroll
    for (int j = 0; j < 4; j++)
        ho[j] = __floats2half2_rn(acc[2 * j] * inv, acc[2 * j + 1] * inv);
    *(uint4*)(g_Oh + (size_t)row * CC + h * 16 + dq * 8) = *(uint4*)ho;
}

// ---------------- per-(bt,head) self-attention (fp16 QKV) ------------------
__global__ void k_attn()
{
    int bt = blockIdx.x, h = blockIdx.y;
    __shared__ float Qs[SS][DHH], Ks[SS][DHH], Vs[SS][DHH];
    int tid = threadIdx.x;
    for (int i = tid; i < SS * DHH; i += 128) {
        int s = i >> 4, d = i & 15;
        const __half* base = g_QKVh + ((size_t)bt * SS + s) * 384 + h * 16 + d;
        Qs[s][d] = __half2float(base[0]);
        Ks[s][d] = __half2float(base[128]);
        Vs[s][d] = __half2float(base[256]);
    }
    __syncthreads();
    if (tid < SS) {
        float qv[16];
#pragma unroll
        for (int d = 0; d < 16; d++) qv[d] = Qs[tid][d];
        float mx = -1e30f;
        for (int k = 0; k < SS; k++) {
            float sdot = 0.f;
#pragma unroll
            for (int d = 0; d < 16; d++) sdot = fmaf(qv[d], Ks[k][d], sdot);
            mx = fmaxf(mx, sdot * 0.25f);
        }
        float den = 0.f, o[16];
#pragma unroll
        for (int d = 0; d < 16; d++) o[d] = 0.f;
        for (int k = 0; k < SS; k++) {
            float sdot = 0.f;
#pragma unroll
            for (int d = 0; d < 16; d++) sdot = fmaf(qv[d], Ks[k][d], sdot);
            float e = __expf(sdot * 0.25f - mx);
            den += e;
#pragma unroll
            for (int d = 0; d < 16; d++) o[d] = fmaf(e, Vs[k][d], o[d]);
        }
        float inv = 1.f / den;
        __half* outp = g_ATTOh + ((size_t)bt * SS + tid) * CC + h * 16;
#pragma unroll
        for (int d = 0; d < 16; d++) outp[d] = __float2half_rn(o[d] * inv);
    }
}

// ---------------- host launch ----------------------------------------------
static inline void launch_small(const __half* A, const __half* W, const float* bias,
                                const float* res, void* out, int M, int N, int K,
                                int epi, int outHalf, int perm = 0,
                                const float* lnG = nullptr, const float* lnB = nullptr,
                                __half* out2 = nullptr)
{
    dim3 grid(N / 128, (M + 63) / 64);
    k_gemm_h<<<grid, 128, GEMM_SMEM>>>(A, W, bias, res ? res : (const float*)A,
                                       out, M, N, K, epi, outHalf, perm, lnG, lnB, out2);
}
static inline void launch_big(const __half* A, const __half* W, const float* bias,
                              const float* res, void* out, int M, int N, int K,
                              int epi, int outHalf)
{
    dim3 grid(N / 128, (M + 127) / 128);
    k_gemm_big<<<grid, 256, BIG_SMEM>>>(A, W, bias, res ? res : (const float*)A,
                                        out, M, N, K, epi, outHalf);
}

extern "C" void kernel_launch(void* const* d_in, const int* in_sizes, int n_in,
                              void* d_out, int out_size)
{
    (void)in_sizes; (void)n_in; (void)out_size;
    const float* x        = (const float*)d_in[0];
    const float* refp     = (const float*)d_in[1];
    const float* pe_buf   = (const float*)d_in[2];
    const float* learn_pos= (const float*)d_in[3];
    const float* w_off    = (const float*)d_in[4];
    const float* b_off    = (const float*)d_in[5];
    const float* w_attn   = (const float*)d_in[6];
    const float* b_attn   = (const float*)d_in[7];
    const float* w_val    = (const float*)d_in[8];
    const float* b_val    = (const float*)d_in[9];
    const float* w_out    = (const float*)d_in[10];
    const float* b_out    = (const float*)d_in[11];
    const float* in_w     = (const float*)d_in[12];
    const float* in_b     = (const float*)d_in[13];
    const float* out_w    = (const float*)d_in[14];
    const float* b_out2   = (const float*)d_in[15];
    const float* fc1_w    = (const float*)d_in[16];
    const float* fc1_b    = (const float*)d_in[17];
    const float* fc2_w    = (const float*)d_in[18];
    const float* fc2_b    = (const float*)d_in[19];
    const float* g1       = (const float*)d_in[20];
    const float* be1      = (const float*)d_in[21];
    const float* g2       = (const float*)d_in[22];
    const float* be2      = (const float*)d_in[23];
    const float* g3       = (const float*)d_in[24];
    const float* be3      = (const float*)d_in[25];
    float* out = (float*)d_out;

    cudaFuncSetAttribute(k_gemm_h,   cudaFuncAttributeMaxDynamicSharedMemorySize, GEMM_SMEM);
    cudaFuncSetAttribute(k_projs,    cudaFuncAttributeMaxDynamicSharedMemorySize, GEMM_SMEM);
    cudaFuncSetAttribute(k_gemm_big, cudaFuncAttributeMaxDynamicSharedMemorySize, BIG_SMEM);

    float *pXCAT, *pXCAT2;
    __half *pOh, *pXN2h, *pQKVh, *pATTOh, *pXN3h, *pHIDh, *pWh;
    cudaGetSymbolAddress((void**)&pXCAT,  g_XCAT);
    cudaGetSymbolAddress((void**)&pXCAT2, g_XCAT2);
    cudaGetSymbolAddress((void**)&pOh,    g_Oh);
    cudaGetSymbolAddress((void**)&pXN2h,  g_XN2h);
    cudaGetSymbolAddress((void**)&pQKVh,  g_QKVh);
    cudaGetSymbolAddress((void**)&pATTOh, g_ATTOh);
    cudaGetSymbolAddress((void**)&pXN3h,  g_XN3h);
    cudaGetSymbolAddress((void**)&pHIDh,  g_HIDh);
    cudaGetSymbolAddress((void**)&pWh,    g_Wh);

    // 1) merged prologue: LN1 + lvl0(LN2) + weight cvt
    k_pre<<<BLQ + BTP + 272, 128>>>(x, pe_buf, learn_pos, g1, be1, g2, be2,
                                    w_off, w_attn, w_val, w_out, in_w, out_w,
                                    fc1_w, fc2_w, b_off, b_attn);
    // 2) merged projections: offaw (N=384) + val (N=128) -> fp16
    {
        dim3 grid(4, (BLQ + 63) / 64);
        k_projs<<<grid, 128, GEMM_SMEM>>>(b_val);
    }
    // 3) deformable sampling (pipelined waves)
    k_deform<<<BLQ / DEF_RPB, 128>>>(refp);
    // 4) out-proj + residual(from x, permuted) + concat + fused LN2 [epi3, perm]
    launch_small(pOh, pWh + WOFF_OUT, b_out, x, pXCAT, BLQ, 128, CC, 3, 0, 1,
                 g2, be2, pXN2h);
    // 5) QKV GEMM (N=384) -> fp16  [BIG]
    launch_big(pXN2h, pWh + WOFF_IN, in_b, nullptr, pQKVh, TOK, 384, CC, 0, 1);
    // 6) self-attention
    k_attn<<<dim3(BB * TT, HH), 128>>>();
    // 7) attention out-proj + residual + fused LN3 [epi3]
    launch_small(pATTOh, pWh + WOFF_OUTW, b_out2, pXCAT, pXCAT2, TOK, 128, CC, 3, 0, 0,
                 g3, be3, pXN3h);
    // 8) FC1 + GELU (N=512) -> fp16 [BIG]
    launch_big(pXN3h, pWh + WOFF_FC1, fc1_b, nullptr, pHIDh, TOK, 512, CC, 2, 1);
    // 9) FC2 + residual -> final output (K=512) [BIG]
    launch_big(pHIDh, pWh + WOFF_FC2, fc2_b, pXCAT2, out, TOK, 128, 512, 1, 0);
}

// round 15
// speedup vs baseline: 1.0316x; 1.0042x over previous
#include <cuda_runtime.h>
#include <cuda_fp16.h>
#include <math.h>
#include <stdint.h>

// Problem constants
#define TT   243
#define PP   17
#define LL   4
#define CC   128
#define HH   8
#define NPT  4
#define DHH  16
#define BB   2
#define LQ   (TT*PP*LL)        // 16524
#define BLQ  (BB*LQ)           // 33048
#define NLVL 5
#define BTP  (BB*TT*PP)        // 8262
#define TOK  (BTP*NLVL)        // 41310
#define SS   (PP*NLVL)         // 85

// ---------------- scratch (device globals; no allocations) ----------------
__device__ float  g_XCAT [(size_t)TOK*CC];
__device__ float  g_XCAT2[(size_t)TOK*CC];
__device__ __half g_OFFAWh[(size_t)BLQ*384];
__device__ __half g_Qh   [(size_t)BLQ*CC];
__device__ __half g_XNh  [(size_t)BLQ*CC];
__device__ __half g_VALh [(size_t)BLQ*CC];
__device__ __half g_Oh   [(size_t)BLQ*CC];
__device__ __half g_XN2h [(size_t)TOK*CC];
__device__ __half g_QKVh [(size_t)TOK*384];
__device__ __half g_ATTOh[(size_t)TOK*CC];
__device__ __half g_XN3h [(size_t)TOK*CC];
__device__ __half g_HIDh [(size_t)TOK*512];
#define WOFF_OFF   0
#define WOFF_ATTN  32768
#define WOFF_VAL   49152
#define WOFF_OUT   65536
#define WOFF_IN    81920
#define WOFF_OUTW  131072
#define WOFF_FC1   147456
#define WOFF_FC2   212992
#define WTOTAL     278528
__device__ __half g_Wh[WTOTAL];
__device__ float  g_Bcat[384];

// ---------------- PTX helpers ----------------------------------------------
__device__ __forceinline__ void cpa16(uint32_t dst, const void* src, bool valid) {
    int sz = valid ? 16 : 0;
    asm volatile("cp.async.cg.shared.global [%0], [%1], 16, %2;\n"
                 :: "r"(dst), "l"(src), "r"(sz));
}
#define CP_COMMIT() asm volatile("cp.async.commit_group;\n" ::: "memory")
#define CP_WAIT(n)  asm volatile("cp.async.wait_group %0;\n" :: "n"(n) : "memory")

__device__ __forceinline__ void ldm4(uint32_t* r, uint32_t addr) {
    asm volatile("ldmatrix.sync.aligned.m8n8.x4.shared.b16 {%0,%1,%2,%3}, [%4];\n"
                 : "=r"(r[0]), "=r"(r[1]), "=r"(r[2]), "=r"(r[3]) : "r"(addr));
}
__device__ __forceinline__ void mma16(float* c, const uint32_t* a, const uint32_t* b) {
    asm volatile("mma.sync.aligned.m16n8k16.row.col.f32.f16.f16.f32 "
                 "{%0,%1,%2,%3},{%4,%5,%6,%7},{%8,%9},{%0,%1,%2,%3};\n"
                 : "+f"(c[0]), "+f"(c[1]), "+f"(c[2]), "+f"(c[3])
                 : "r"(a[0]), "r"(a[1]), "r"(a[2]), "r"(a[3]), "r"(b[0]), "r"(b[1]));
}

// permuted destination row for the xcat concat (also the x source row!)
__device__ __forceinline__ int xcat_row(int gm) {
    int b = gm / LQ;
    int rem = gm - b * LQ;
    return (b * (TT * PP) + (rem >> 2)) * 5 + (rem & 3) + 1;
}

// ============================================================================
// BIG GEMM: BM=128, BN=128, BK=64, 256 threads (QKV / FC1 / FC2).
// ============================================================================
#define BIG_STG  32768
#define BIG_SMEM 65536

__device__ __forceinline__ void big_load_stage(
    const __half* __restrict__ A, const __half* __restrict__ W, uint32_t sb,
    int st, int kt, int row0, int col0, int M, int K, int tid)
{
    const int r0 = tid >> 3, ck = tid & 7;
    const uint32_t base = sb + st * BIG_STG;
#pragma unroll
    for (int i = 0; i < 4; i++) {
        int r = r0 + i * 32;
        uint32_t swoff = (uint32_t)(r * 128 + ((ck ^ (r & 7)) * 16));
        int gm = row0 + r;
        cpa16(base + swoff, A + (size_t)gm * K + (size_t)kt * 64 + ck * 8, gm < M);
        cpa16(base + 16384 + swoff,
              W + (size_t)(col0 + r) * K + (size_t)kt * 64 + ck * 8, true);
    }
}

__global__ __launch_bounds__(256, 2) void k_gemm_big(
    const __half* __restrict__ A, const __half* __restrict__ W,
    const float* __restrict__ bias, const float* __restrict__ res,
    void* __restrict__ outp, int M, int N, int K, int epi, int outHalf)
{
    extern __shared__ __align__(1024) char sm[];
    uint32_t sb = (uint32_t)__cvta_generic_to_shared(sm);
    const int tid = threadIdx.x, lane = tid & 31, warp = tid >> 5;
    const int g = lane >> 2, t = lane & 3;
    const int wm = (warp >> 1) * 32, wn = (warp & 1) * 64;
    const int row0 = blockIdx.y * 128, col0 = blockIdx.x * 128;
    const int KT = K >> 6;

    float acc[2][8][4];
#pragma unroll
    for (int mi = 0; mi < 2; mi++)
#pragma unroll
        for (int ni = 0; ni < 8; ni++)
#pragma unroll
            for (int r = 0; r < 4; r++) acc[mi][ni][r] = 0.f;

    big_load_stage(A, W, sb, 0, 0, row0, col0, M, K, tid);
    CP_COMMIT();

    for (int kt = 0; kt < KT; kt++) {
        const int s = kt & 1;
        if (kt + 1 < KT) {
            big_load_stage(A, W, sb, s ^ 1, kt + 1, row0, col0, M, K, tid);
            CP_COMMIT();
            CP_WAIT(1);
        } else {
            CP_WAIT(0);
        }
        __syncthreads();

        const uint32_t aS = sb + s * BIG_STG;
        const uint32_t bS = aS + 16384;
        const int rlow = lane & 15, hi = lane >> 4;
#pragma unroll
        for (int kk = 0; kk < 4; kk++) {
            uint32_t af[2][4];
#pragma unroll
            for (int mi = 0; mi < 2; mi++) {
                int r = wm + mi * 16 + rlow;
                int ck = kk * 2 + hi;
                ldm4(af[mi], aS + (uint32_t)(r * 128 + ((ck ^ (r & 7)) * 16)));
            }
            uint32_t bf[8][2];
#pragma unroll
            for (int nj = 0; nj < 4; nj++) {
                int r = wn + nj * 16 + rlow;
                int ck = kk * 2 + hi;
                uint32_t q[4];
                ldm4(q, bS + (uint32_t)(r * 128 + ((ck ^ (r & 7)) * 16)));
                bf[nj * 2 + 0][0] = q[0]; bf[nj * 2 + 0][1] = q[2];
                bf[nj * 2 + 1][0] = q[1]; bf[nj * 2 + 1][1] = q[3];
            }
#pragma unroll
            for (int mi = 0; mi < 2; mi++)
#pragma unroll
                for (int ni = 0; ni < 8; ni++)
                    mma16(acc[mi][ni], af[mi], bf[ni]);
        }
        __syncthreads();
    }

#pragma unroll
    for (int mi = 0; mi < 2; mi++) {
#pragma unroll
        for (int r = 0; r < 2; r++) {
            const int gm = row0 + wm + mi * 16 + g + r * 8;
            if (gm >= M) continue;
            const float* rp = res + (size_t)gm * N;
#pragma unroll
            for (int ni = 0; ni < 8; ni++) {
                const int gn = col0 + wn + ni * 8 + 2 * t;
                float v0 = acc[mi][ni][r * 2 + 0] + bias[gn];
                float v1 = acc[mi][ni][r * 2 + 1] + bias[gn + 1];
                if (epi == 1) {
                    v0 += rp[gn];
                    v1 += rp[gn + 1];
                } else if (epi == 2) {
                    v0 = 0.5f * v0 * (1.0f + erff(v0 * 0.7071067811865475f));
                    v1 = 0.5f * v1 * (1.0f + erff(v1 * 0.7071067811865475f));
                }
                if (outHalf) {
                    *(__half2*)((__half*)outp + (size_t)gm * N + gn) = __floats2half2_rn(v0, v1);
                } else {
                    *(float2*)((float*)outp + (size_t)gm * N + gn) = make_float2(v0, v1);
                }
            }
        }
    }
}

// ============================================================================
// SMALL GEMM: BM=64, BN=128, BK=64, 128 threads; epi3 = residual + LN fusion.
// ============================================================================
#define STG 24576
#define SREDOFF 49152
#define GEMM_SMEM 50176

__device__ __forceinline__ void gemm_load_stage(
    const __half* __restrict__ A, const __half* __restrict__ W, uint32_t sb,
    int st, int kt, int row0, int col0, int M, int K, int tid)
{
    const int r0 = tid >> 3, ck = tid & 7;
    const uint32_t base = sb + st * STG;
#pragma unroll
    for (int i = 0; i < 4; i++) {
        int r = r0 + i * 16;
        uint32_t swoff = (uint32_t)(r * 128 + ((ck ^ (r & 7)) * 16));
        int gm = row0 + r;
        cpa16(base + swoff, A + (size_t)gm * K + (size_t)kt * 64 + ck * 8, gm < M);
    }
#pragma unroll
    for (int i = 0; i < 8; i++) {
        int r = r0 + i * 16;
        uint32_t swoff = (uint32_t)(r * 128 + ((ck ^ (r & 7)) * 16));
        cpa16(base + 8192 + swoff,
              W + (size_t)(col0 + r) * K + (size_t)kt * 64 + ck * 8, true);
    }
}

__global__ __launch_bounds__(128, 4) void k_gemm_h(
    const __half* __restrict__ A, const __half* __restrict__ W,
    const float* __restrict__ bias, const float* __restrict__ res,
    void* __restrict__ outp, int M, int N, int K, int epi, int outHalf, int perm,
    const float* __restrict__ lnG, const float* __restrict__ lnB,
    __half* __restrict__ out2)
{
    extern __shared__ __align__(1024) char sm[];
    uint32_t sb = (uint32_t)__cvta_generic_to_shared(sm);
    float* sred = (float*)(sm + SREDOFF);
    const int tid = threadIdx.x, lane = tid & 31, warp = tid >> 5;
    const int g = lane >> 2, t = lane & 3;
    const int wm = (warp >> 1) * 32, wn = (warp & 1) * 64;
    const int row0 = blockIdx.y * 64, col0 = blockIdx.x * 128;
    const int KT = K >> 6;

    float acc[2][8][4];
#pragma unroll
    for (int mi = 0; mi < 2; mi++)
#pragma unroll
        for (int ni = 0; ni < 8; ni++)
#pragma unroll
            for (int r = 0; r < 4; r++) acc[mi][ni][r] = 0.f;

    gemm_load_stage(A, W, sb, 0, 0, row0, col0, M, K, tid);
    CP_COMMIT();

    for (int kt = 0; kt < KT; kt++) {
        const int s = kt & 1;
        if (kt + 1 < KT) {
            gemm_load_stage(A, W, sb, s ^ 1, kt + 1, row0, col0, M, K, tid);
            CP_COMMIT();
            CP_WAIT(1);
        } else {
            CP_WAIT(0);
        }
        __syncthreads();

        const uint32_t aS = sb + s * STG;
        const uint32_t bS = aS + 8192;
        const int rlow = lane & 15, hi = lane >> 4;
#pragma unroll
        for (int kk = 0; kk < 4; kk++) {
            uint32_t af[2][4];
#pragma unroll
            for (int mi = 0; mi < 2; mi++) {
                int r = wm + mi * 16 + rlow;
                int ck = kk * 2 + hi;
                ldm4(af[mi], aS + (uint32_t)(r * 128 + ((ck ^ (r & 7)) * 16)));
            }
            uint32_t bf[8][2];
#pragma unroll
            for (int nj = 0; nj < 4; nj++) {
                int r = wn + nj * 16 + rlow;
                int ck = kk * 2 + hi;
                uint32_t q[4];
                ldm4(q, bS + (uint32_t)(r * 128 + ((ck ^ (r & 7)) * 16)));
                bf[nj * 2 + 0][0] = q[0]; bf[nj * 2 + 0][1] = q[2];
                bf[nj * 2 + 1][0] = q[1]; bf[nj * 2 + 1][1] = q[3];
            }
#pragma unroll
            for (int mi = 0; mi < 2; mi++)
#pragma unroll
                for (int ni = 0; ni < 8; ni++)
                    mma16(acc[mi][ni], af[mi], bf[ni]);
        }
        __syncthreads();
    }

#pragma unroll
    for (int mi = 0; mi < 2; mi++) {
#pragma unroll
        for (int r = 0; r < 2; r++) {
            const int gm = row0 + wm + mi * 16 + g + r * 8;
            float psum = 0.f, psq = 0.f;
            if (gm < M) {
                const size_t orow = (epi == 3 && perm) ? (size_t)xcat_row(gm) : (size_t)gm;
                const float* rp = res + orow * N;
#pragma unroll
                for (int ni = 0; ni < 8; ni++) {
                    const int gn = col0 + wn + ni * 8 + 2 * t;
                    float v0 = acc[mi][ni][r * 2 + 0] + bias[gn];
                    float v1 = acc[mi][ni][r * 2 + 1] + bias[gn + 1];
                    if (epi == 1 || epi == 3) {
                        v0 += rp[gn];
                        v1 += rp[gn + 1];
                    } else if (epi == 2) {
                        v0 = 0.5f * v0 * (1.0f + erff(v0 * 0.7071067811865475f));
                        v1 = 0.5f * v1 * (1.0f + erff(v1 * 0.7071067811865475f));
                    }
                    if (outHalf) {
                        *(__half2*)((__half*)outp + orow * N + gn) = __floats2half2_rn(v0, v1);
                    } else {
                        *(float2*)((float*)outp + orow * N + gn) = make_float2(v0, v1);
                    }
                    acc[mi][ni][r * 2 + 0] = v0;
                    acc[mi][ni][r * 2 + 1] = v1;
                    psum += v0 + v1;
                    psq  += v0 * v0 + v1 * v1;
                }
            }
            if (epi == 3) {
                psum += __shfl_xor_sync(0xffffffffu, psum, 1);
                psum += __shfl_xor_sync(0xffffffffu, psum, 2);
                psq  += __shfl_xor_sync(0xffffffffu, psq, 1);
                psq  += __shfl_xor_sync(0xffffffffu, psq, 2);
                if (t == 0) {
                    int lr = wm + mi * 16 + g + r * 8;
                    sred[lr * 4 + (warp & 1) * 2 + 0] = psum;
                    sred[lr * 4 + (warp & 1) * 2 + 1] = psq;
                }
            }
        }
    }
    if (epi == 3) {
        __syncthreads();
#pragma unroll
        for (int mi = 0; mi < 2; mi++) {
#pragma unroll
            for (int r = 0; r < 2; r++) {
                const int gm = row0 + wm + mi * 16 + g + r * 8;
                if (gm >= M) continue;
                const size_t orow = perm ? (size_t)xcat_row(gm) : (size_t)gm;
                const int lr = wm + mi * 16 + g + r * 8;
                float sum = sred[lr * 4 + 0] + sred[lr * 4 + 2];
                float sq  = sred[lr * 4 + 1] + sred[lr * 4 + 3];
                float mean = sum * (1.f / 128.f);
                float var = sq * (1.f / 128.f) - mean * mean;
                float rstd = rsqrtf(var + 1e-5f);
#pragma unroll
                for (int ni = 0; ni < 8; ni++) {
                    const int gn = col0 + wn + ni * 8 + 2 * t;
                    float a0 = (acc[mi][ni][r * 2 + 0] - mean) * rstd * lnG[gn] + lnB[gn];
                    float a1 = (acc[mi][ni][r * 2 + 1] - mean) * rstd * lnG[gn + 1] + lnB[gn + 1];
                    *(__half2*)(out2 + orow * 128 + gn) = __floats2half2_rn(a0, a1);
                }
            }
        }
    }
}

// ============================================================================
// Merged projection GEMM: offaw (N=384, cols 0-2) + val (N=128, col 3).
// ============================================================================
__global__ __launch_bounds__(128, 4) void k_projs(const float* __restrict__ b_val)
{
    extern __shared__ __align__(1024) char sm[];
    uint32_t sb = (uint32_t)__cvta_generic_to_shared(sm);
    const int tid = threadIdx.x, lane = tid & 31, warp = tid >> 5;
    const int g = lane >> 2, t = lane & 3;
    const int wm = (warp >> 1) * 32, wn = (warp & 1) * 64;
    const int row0 = blockIdx.y * 64;

    const __half* A; const __half* W; const float* bias; __half* outp; int N; int col0;
    if (blockIdx.x < 3) {
        A = g_Qh;  W = g_Wh + WOFF_OFF; bias = g_Bcat; outp = g_OFFAWh;
        N = 384; col0 = blockIdx.x * 128;
    } else {
        A = g_XNh; W = g_Wh + WOFF_VAL; bias = b_val;  outp = g_VALh;
        N = 128; col0 = 0;
    }
    const int M = BLQ, K = CC, KT = 2;

    float acc[2][8][4];
#pragma unroll
    for (int mi = 0; mi < 2; mi++)
#pragma unroll
        for (int ni = 0; ni < 8; ni++)
#pragma unroll
            for (int r = 0; r < 4; r++) acc[mi][ni][r] = 0.f;

    gemm_load_stage(A, W, sb, 0, 0, row0, col0, M, K, tid);
    CP_COMMIT();

    for (int kt = 0; kt < KT; kt++) {
        const int s = kt & 1;
        if (kt + 1 < KT) {
            gemm_load_stage(A, W, sb, s ^ 1, kt + 1, row0, col0, M, K, tid);
            CP_COMMIT();
            CP_WAIT(1);
        } else {
            CP_WAIT(0);
        }
        __syncthreads();

        const uint32_t aS = sb + s * STG;
        const uint32_t bS = aS + 8192;
        const int rlow = lane & 15, hi = lane >> 4;
#pragma unroll
        for (int kk = 0; kk < 4; kk++) {
            uint32_t af[2][4];
#pragma unroll
            for (int mi = 0; mi < 2; mi++) {
                int r = wm + mi * 16 + rlow;
                int ck = kk * 2 + hi;
                ldm4(af[mi], aS + (uint32_t)(r * 128 + ((ck ^ (r & 7)) * 16)));
            }
            uint32_t bf[8][2];
#pragma unroll
            for (int nj = 0; nj < 4; nj++) {
                int r = wn + nj * 16 + rlow;
                int ck = kk * 2 + hi;
                uint32_t q[4];
                ldm4(q, bS + (uint32_t)(r * 128 + ((ck ^ (r & 7)) * 16)));
                bf[nj * 2 + 0][0] = q[0]; bf[nj * 2 + 0][1] = q[2];
                bf[nj * 2 + 1][0] = q[1]; bf[nj * 2 + 1][1] = q[3];
            }
#pragma unroll
            for (int mi = 0; mi < 2; mi++)
#pragma unroll
                for (int ni = 0; ni < 8; ni++)
                    mma16(acc[mi][ni], af[mi], bf[ni]);
        }
        __syncthreads();
    }

#pragma unroll
    for (int mi = 0; mi < 2; mi++) {
#pragma unroll
        for (int r = 0; r < 2; r++) {
            const int gm = row0 + wm + mi * 16 + g + r * 8;
            if (gm >= M) continue;
#pragma unroll
            for (int ni = 0; ni < 8; ni++) {
                const int gn = col0 + wn + ni * 8 + 2 * t;
                float v0 = acc[mi][ni][r * 2 + 0] + bias[gn];
                float v1 = acc[mi][ni][r * 2 + 1] + bias[gn + 1];
                *(__half2*)(outp + (size_t)gm * N + gn) = __floats2half2_rn(v0, v1);
            }
        }
    }
}

// ============================================================================
// Merged prologue: ln1 (BLQ blocks) + lvl0 (BTP blocks) + weight cvt (272).
// ============================================================================
__global__ __launch_bounds__(128) void k_pre(
    const float* __restrict__ x, const float* __restrict__ pe,
    const float* __restrict__ lp,
    const float* __restrict__ g1, const float* __restrict__ be1,
    const float* __restrict__ g2, const float* __restrict__ be2,
    const float* __restrict__ w0, const float* __restrict__ w1,
    const float* __restrict__ w2, const float* __restrict__ w3,
    const float* __restrict__ w4, const float* __restrict__ w5,
    const float* __restrict__ w6, const float* __restrict__ w7,
    const float* __restrict__ b_off, const float* __restrict__ b_attn)
{
    const int bid = blockIdx.x;
    const int c = threadIdx.x;

    if (bid < BLQ) {
        int row = bid;
        int b = row / LQ; int lq = row - b * LQ;
        int l = lq & 3; int tp = lq >> 2;
        size_t xi = ((size_t)(b * TT * PP + tp) * NLVL + (l + 1)) * CC + c;
        float v = x[xi];

        __shared__ float sh[8];
        float s = v;
        for (int o = 16; o > 0; o >>= 1) s += __shfl_xor_sync(0xffffffffu, s, o);
        if ((c & 31) == 0) sh[c >> 5] = s;
        __syncthreads();
        float mean = (sh[0] + sh[1] + sh[2] + sh[3]) * (1.f / CC);
        float dv = v - mean;
        float q2 = dv * dv;
        for (int o = 16; o > 0; o >>= 1) q2 += __shfl_xor_sync(0xffffffffu, q2, o);
        if ((c & 31) == 0) sh[4 + (c >> 5)] = q2;
        __syncthreads();
        float var = (sh[4] + sh[5] + sh[6] + sh[7]) * (1.f / CC);
        float xn = dv * rsqrtf(var + 1e-5f) * g1[c] + be1[c];
        g_XNh[(size_t)row * CC + c] = __float2half_rn(xn);
        g_Qh [(size_t)row * CC + c] = __float2half_rn(xn + pe[(size_t)lq * CC + c] + lp[(size_t)lq * CC + c]);
    } else if (bid < BLQ + BTP) {
        int btp = bid - BLQ;
        size_t rowoff = (size_t)btp * NLVL * CC;
        float v = x[rowoff + c];
        g_XCAT[rowoff + c] = v;

        __shared__ float sh2[8];
        float s = v;
        for (int o = 16; o > 0; o >>= 1) s += __shfl_xor_sync(0xffffffffu, s, o);
        if ((c & 31) == 0) sh2[c >> 5] = s;
        __syncthreads();
        float mean = (sh2[0] + sh2[1] + sh2[2] + sh2[3]) * (1.f / CC);
        float dv = v - mean;
        float q2 = dv * dv;
        for (int o = 16; o > 0; o >>= 1) q2 += __shfl_xor_sync(0xffffffffu, q2, o);
        if ((c & 31) == 0) sh2[4 + (c >> 5)] = q2;
        __syncthreads();
        float var = (sh2[4] + sh2[5] + sh2[6] + sh2[7]) * (1.f / CC);
        g_XN2h[rowoff + c] = __float2half_rn(dv * rsqrtf(var + 1e-5f) * g2[c] + be2[c]);
    } else {
        int wb = bid - BLQ - BTP;             // 0..271
        if (wb == 0 && c < 128) {
            g_Bcat[c]       = b_off[c];
            g_Bcat[c + 128] = b_off[c + 128];
            g_Bcat[c + 256] = b_attn[c];
        }
        for (int idx = wb * 128 + c; idx < WTOTAL; idx += 272 * 128) {
            const float* src; int off;
            if      (idx < WOFF_ATTN) { src = w0; off = idx; }
            else if (idx < WOFF_VAL ) { src = w1; off = idx - WOFF_ATTN; }
            else if (idx < WOFF_OUT ) { src = w2; off = idx - WOFF_VAL; }
            else if (idx < WOFF_IN  ) { src = w3; off = idx - WOFF_OUT; }
            else if (idx < WOFF_OUTW) { src = w4; off = idx - WOFF_IN; }
            else if (idx < WOFF_FC1 ) { src = w5; off = idx - WOFF_OUTW; }
            else if (idx < WOFF_FC2 ) { src = w6; off = idx - WOFF_FC1; }
            else                      { src = w7; off = idx - WOFF_FC2; }
            g_Wh[idx] = __float2half_rn(src[off]);
        }
    }
}

// ============================================================================
// Deformable sampling, software-pipelined gathers:
// 8 waves x 2 points, double-buffered (wait_group 1) so wave i loads overlap
// wave i-1 reduction. smem: sOFF 12KB + sG 2x16KB = 44KB.
// ============================================================================
#define DEF_RPB 8
__global__ __launch_bounds__(128) void k_deform(const float* __restrict__ refp)
{
    __shared__ float sOFF[DEF_RPB][384];
    __shared__ __align__(16) uint4 sG[2][2][4][128];  // [buf][pt-in-wave][corner][tid]
    const int row0 = blockIdx.x * DEF_RPB;
    const int tid = threadIdx.x;
    const uint32_t sgb = (uint32_t)__cvta_generic_to_shared(&sG[0][0][0][tid]);

    for (int idx = tid; idx < DEF_RPB * 192; idx += 128) {
        int rr = idx / 192, c2 = idx - rr * 192;
        float2 v = __half22float2(*(const __half2*)(g_OFFAWh + (size_t)(row0 + rr) * 384 + c2 * 2));
        sOFF[rr][c2 * 2 + 0] = v.x;
        sOFF[rr][c2 * 2 + 1] = v.y;
    }
    __syncthreads();

    const int rr = tid >> 4;
    const int s = tid & 15;
    const int row = row0 + rr;
    const int b = row / LQ; const int lq = row - b * LQ;
    const int tp = lq >> 2; const int p = tp % PP; const int t = tp / PP;
    const int h = s >> 1, dq = s & 1;
    const float refx = refp[(((size_t)b * TT + t) * PP + p) * 2 + 0];
    const float refy = refp[(((size_t)b * TT + t) * PP + p) * 2 + 1];

    const float* awp = &sOFF[rr][256 + h * 16];
    float w[16], mx = -1e30f;
#pragma unroll
    for (int i = 0; i < 16; i++) { w[i] = awp[i]; mx = fmaxf(mx, w[i]); }
    float den = 0.f;
#pragma unroll
    for (int i = 0; i < 16; i++) { w[i] = __expf(w[i] - mx); den += w[i]; }
    float inv = 1.f / den;

    const float*  offp  = &sOFF[rr][h * 32];
    const __half* vbase = g_VALh + (size_t)b * LQ * CC + h * 16 + dq * 8;
    float acc[8];
#pragma unroll
    for (int j = 0; j < 8; j++) acc[j] = 0.f;

    float cw[2][2][4];   // [buf][pt-in-wave][corner]

    // issue a wave: 2 points x 4 corners into buffer `buf`
    auto issue_wave = [&](int wv, int buf) {
#pragma unroll
        for (int pi = 0; pi < 2; pi++) {
            const int pt = wv * 2 + pi;
            const int l = pt >> 2;
            float ox = offp[pt * 2 + 0];
            float oy = offp[pt * 2 + 1];
            float fx = refx * PP + ox - 0.5f;
            float fy = refy * TT + oy - 0.5f;
            float x0f = floorf(fx), y0f = floorf(fy);
            int x0 = (int)x0f, y0 = (int)y0f;
            float wx1 = fx - x0f, wy1 = fy - y0f;
            float wx0 = 1.f - wx1, wy0 = 1.f - wy1;
            bool xi0 = (x0 >= 0) && (x0 < PP);
            bool xi1 = (x0 + 1 >= 0) && (x0 + 1 < PP);
            bool yi0 = (y0 >= 0) && (y0 < TT);
            bool yi1 = (y0 + 1 >= 0) && (y0 + 1 < TT);
            float ww = w[pt];
            cw[buf][pi][0] = wy0 * wx0 * ww;
            cw[buf][pi][1] = wy0 * wx1 * ww;
            cw[buf][pi][2] = wy1 * wx0 * ww;
            cw[buf][pi][3] = wy1 * wx1 * ww;
            const uint32_t sp = sgb + (uint32_t)(buf * 8 + pi * 4) * 2048;
            cpa16(sp        , vbase + ((size_t)(y0 * PP + x0) * LL + l) * CC,           yi0 && xi0);
            cpa16(sp + 2048 , vbase + ((size_t)(y0 * PP + x0 + 1) * LL + l) * CC,       yi0 && xi1);
            cpa16(sp + 4096 , vbase + ((size_t)((y0 + 1) * PP + x0) * LL + l) * CC,     yi1 && xi0);
            cpa16(sp + 6144 , vbase + ((size_t)((y0 + 1) * PP + x0 + 1) * LL + l) * CC, yi1 && xi1);
        }
        CP_COMMIT();
    };
    auto reduce_wave = [&](int buf) {
#pragma unroll
        for (int pi = 0; pi < 2; pi++) {
#pragma unroll
            for (int c = 0; c < 4; c++) {
                uint4 q = sG[buf][pi][c][tid];
                const __half2* hp = (const __half2*)&q;
                float ww = cw[buf][pi][c];
#pragma unroll
                for (int j = 0; j < 4; j++) {
                    float2 f = __half22float2(hp[j]);
                    acc[2 * j + 0] = fmaf(f.x, ww, acc[2 * j + 0]);
                    acc[2 * j + 1] = fmaf(f.y, ww, acc[2 * j + 1]);
                }
            }
        }
    };

    issue_wave(0, 0);
#pragma unroll
    for (int wv = 1; wv < 8; wv++) {
        issue_wave(wv, wv & 1);
        CP_WAIT(1);               // previous wave complete
        reduce_wave((wv - 1) & 1);
    }
    CP_WAIT(0);
    reduce_wave(7 & 1);

    __half2 ho[4];
#pragma unroll
    for (int j = 0; j < 4; j++)
        ho[j] = __floats2half2_rn(acc[2 * j] * inv, acc[2 * j + 1] * inv);
    *(uint4*)(g_Oh + (size_t)row * CC + h * 16 + dq * 8) = *(uint4*)ho;
}

// ---------------- per-(bt,head) self-attention (fp16 QKV) ------------------
__global__ void k_attn()
{
    int bt = blockIdx.x, h = blockIdx.y;
    __shared__ float Qs[SS][DHH], Ks[SS][DHH], Vs[SS][DHH];
    int tid = threadIdx.x;
    for (int i = tid; i < SS * DHH; i += 128) {
        int s = i >> 4, d = i & 15;
        const __half* base = g_QKVh + ((size_t)bt * SS + s) * 384 + h * 16 + d;
        Qs[s][d] = __half2float(base[0]);
        Ks[s][d] = __half2float(base[128]);
        Vs[s][d] = __half2float(base[256]);
    }
    __syncthreads();
    if (tid < SS) {
        float qv[16];
#pragma unroll
        for (int d = 0; d < 16; d++) qv[d] = Qs[tid][d];
        float mx = -1e30f;
        for (int k = 0; k < SS; k++) {
            float sdot = 0.f;
#pragma unroll
            for (int d = 0; d < 16; d++) sdot = fmaf(qv[d], Ks[k][d], sdot);
            mx = fmaxf(mx, sdot * 0.25f);
        }
        float den = 0.f, o[16];
#pragma unroll
        for (int d = 0; d < 16; d++) o[d] = 0.f;
        for (int k = 0; k < SS; k++) {
            float sdot = 0.f;
#pragma unroll
            for (int d = 0; d < 16; d++) sdot = fmaf(qv[d], Ks[k][d], sdot);
            float e = __expf(sdot * 0.25f - mx);
            den += e;
#pragma unroll
            for (int d = 0; d < 16; d++) o[d] = fmaf(e, Vs[k][d], o[d]);
        }
        float inv = 1.f / den;
        __half* outp = g_ATTOh + ((size_t)bt * SS + tid) * CC + h * 16;
#pragma unroll
        for (int d = 0; d < 16; d++) outp[d] = __float2half_rn(o[d] * inv);
    }
}

// ---------------- host launch ----------------------------------------------
static inline void launch_small(const __half* A, const __half* W, const float* bias,
                                const float* res, void* out, int M, int N, int K,
                                int epi, int outHalf, int perm = 0,
                                const float* lnG = nullptr, const float* lnB = nullptr,
                                __half* out2 = nullptr)
{
    dim3 grid(N / 128, (M + 63) / 64);
    k_gemm_h<<<grid, 128, GEMM_SMEM>>>(A, W, bias, res ? res : (const float*)A,
                                       out, M, N, K, epi, outHalf, perm, lnG, lnB, out2);
}
static inline void launch_big(const __half* A, const __half* W, const float* bias,
                              const float* res, void* out, int M, int N, int K,
                              int epi, int outHalf)
{
    dim3 grid(N / 128, (M + 127) / 128);
    k_gemm_big<<<grid, 256, BIG_SMEM>>>(A, W, bias, res ? res : (const float*)A,
                                        out, M, N, K, epi, outHalf);
}

extern "C" void kernel_launch(void* const* d_in, const int* in_sizes, int n_in,
                              void* d_out, int out_size)
{
    (void)in_sizes; (void)n_in; (void)out_size;
    const float* x        = (const float*)d_in[0];
    const float* refp     = (const float*)d_in[1];
    const float* pe_buf   = (const float*)d_in[2];
    const float* learn_pos= (const float*)d_in[3];
    const float* w_off    = (const float*)d_in[4];
    const float* b_off    = (const float*)d_in[5];
    const float* w_attn   = (const float*)d_in[6];
    const float* b_attn   = (const float*)d_in[7];
    const float* w_val    = (const float*)d_in[8];
    const float* b_val    = (const float*)d_in[9];
    const float* w_out    = (const float*)d_in[10];
    const float* b_out    = (const float*)d_in[11];
    const float* in_w     = (const float*)d_in[12];
    const float* in_b     = (const float*)d_in[13];
    const float* out_w    = (const float*)d_in[14];
    const float* b_out2   = (const float*)d_in[15];
    const float* fc1_w    = (const float*)d_in[16];
    const float* fc1_b    = (const float*)d_in[17];
    const float* fc2_w    = (const float*)d_in[18];
    const float* fc2_b    = (const float*)d_in[19];
    const float* g1       = (const float*)d_in[20];
    const float* be1      = (const float*)d_in[21];
    const float* g2       = (const float*)d_in[22];
    const float* be2      = (const float*)d_in[23];
    const float* g3       = (const float*)d_in[24];
    const float* be3      = (const float*)d_in[25];
    float* out = (float*)d_out;

    cudaFuncSetAttribute(k_gemm_h,   cudaFuncAttributeMaxDynamicSharedMemorySize, GEMM_SMEM);
    cudaFuncSetAttribute(k_projs,    cudaFuncAttributeMaxDynamicSharedMemorySize, GEMM_SMEM);
    cudaFuncSetAttribute(k_gemm_big, cudaFuncAttributeMaxDynamicSharedMemorySize, BIG_SMEM);

    float *pXCAT, *pXCAT2;
    __half *pOh, *pXN2h, *pQKVh, *pATTOh, *pXN3h, *pHIDh, *pWh;
    cudaGetSymbolAddress((void**)&pXCAT,  g_XCAT);
    cudaGetSymbolAddress((void**)&pXCAT2, g_XCAT2);
    cudaGetSymbolAddress((void**)&pOh,    g_Oh);
    cudaGetSymbolAddress((void**)&pXN2h,  g_XN2h);
    cudaGetSymbolAddress((void**)&pQKVh,  g_QKVh);
    cudaGetSymbolAddress((void**)&pATTOh, g_ATTOh);
    cudaGetSymbolAddress((void**)&pXN3h,  g_XN3h);
    cudaGetSymbolAddress((void**)&pHIDh,  g_HIDh);
    cudaGetSymbolAddress((void**)&pWh,    g_Wh);

    // 1) merged prologue: LN1 + lvl0(LN2) + weight cvt
    k_pre<<<BLQ + BTP + 272, 128>>>(x, pe_buf, learn_pos, g1, be1, g2, be2,
                                    w_off, w_attn, w_val, w_out, in_w, out_w,
                                    fc1_w, fc2_w, b_off, b_attn);
    // 2) merged projections: offaw (N=384) + val (N=128) -> fp16
    {
        dim3 grid(4, (BLQ + 63) / 64);
        k_projs<<<grid, 128, GEMM_SMEM>>>(b_val);
    }
    // 3) deformable sampling (pipelined waves)
    k_deform<<<BLQ / DEF_RPB, 128>>>(refp);
    // 4) out-proj + residual(from x, permuted) + concat + fused LN2 [epi3, perm]
    launch_small(pOh, pWh + WOFF_OUT, b_out, x, pXCAT, BLQ, 128, CC, 3, 0, 1,
                 g2, be2, pXN2h);
    // 5) QKV GEMM (N=384) -> fp16  [BIG]
    launch_big(pXN2h, pWh + WOFF_IN, in_b, nullptr, pQKVh, TOK, 384, CC, 0, 1);
    // 6) self-attention
    k_attn<<<dim3(BB * TT, HH), 128>>>();
    // 7) attention out-proj + residual + fused LN3 [epi3]
    launch_small(pATTOh, pWh + WOFF_OUTW, b_out2, pXCAT, pXCAT2, TOK, 128, CC, 3, 0, 0,
                 g3, be3, pXN3h);
    // 8) FC1 + GELU (N=512) -> fp16 [BIG]
    launch_big(pXN3h, pWh + WOFF_FC1, fc1_b, nullptr, pHIDh, TOK, 512, CC, 2, 1);
    // 9) FC2 + residual -> final output (K=512) [BIG]
    launch_big(pHIDh, pWh + WOFF_FC2, fc2_b, pXCAT2, out, TOK, 128, 512, 1, 0);
}

// round 16
// speedup vs baseline: 1.0757x; 1.0427x over previous
#include <cuda_runtime.h>
#include <cuda_fp16.h>
#include <math.h>
#include <stdint.h>

// Problem constants
#define TT   243
#define PP   17
#define LL   4
#define CC   128
#define HH   8
#define NPT  4
#define DHH  16
#define BB   2
#define LQ   (TT*PP*LL)        // 16524
#define BLQ  (BB*LQ)           // 33048
#define NLVL 5
#define BTP  (BB*TT*PP)        // 8262
#define TOK  (BTP*NLVL)        // 41310
#define SS   (PP*NLVL)         // 85

// ---------------- scratch (device globals; no allocations) ----------------
__device__ float  g_XCAT [(size_t)TOK*CC];
__device__ float  g_XCAT2[(size_t)TOK*CC];
__device__ __half g_OFFAWh[(size_t)BLQ*384];
__device__ __half g_Qh   [(size_t)BLQ*CC];
__device__ __half g_XNh  [(size_t)BLQ*CC];
__device__ __half g_VALh [(size_t)BLQ*CC];
__device__ __half g_Oh   [(size_t)BLQ*CC];
__device__ __half g_XN2h [(size_t)TOK*CC];
__device__ __half g_QKVh [(size_t)TOK*384];
__device__ __half g_ATTOh[(size_t)TOK*CC];
__device__ __half g_XN3h [(size_t)TOK*CC];
__device__ __half g_HIDh [(size_t)TOK*512];
#define WOFF_OFF   0
#define WOFF_ATTN  32768
#define WOFF_VAL   49152
#define WOFF_OUT   65536
#define WOFF_IN    81920
#define WOFF_OUTW  131072
#define WOFF_FC1   147456
#define WOFF_FC2   212992
#define WTOTAL     278528
__device__ __half g_Wh[WTOTAL];
__device__ float  g_Bcat[384];

// ---------------- PTX helpers ----------------------------------------------
__device__ __forceinline__ void cpa16(uint32_t dst, const void* src, bool valid) {
    int sz = valid ? 16 : 0;
    asm volatile("cp.async.cg.shared.global [%0], [%1], 16, %2;\n"
                 :: "r"(dst), "l"(src), "r"(sz));
}
#define CP_COMMIT() asm volatile("cp.async.commit_group;\n" ::: "memory")
#define CP_WAIT(n)  asm volatile("cp.async.wait_group %0;\n" :: "n"(n) : "memory")

__device__ __forceinline__ void ldm4(uint32_t* r, uint32_t addr) {
    asm volatile("ldmatrix.sync.aligned.m8n8.x4.shared.b16 {%0,%1,%2,%3}, [%4];\n"
                 : "=r"(r[0]), "=r"(r[1]), "=r"(r[2]), "=r"(r[3]) : "r"(addr));
}
__device__ __forceinline__ void mma16(float* c, const uint32_t* a, const uint32_t* b) {
    asm volatile("mma.sync.aligned.m16n8k16.row.col.f32.f16.f16.f32 "
                 "{%0,%1,%2,%3},{%4,%5,%6,%7},{%8,%9},{%0,%1,%2,%3};\n"
                 : "+f"(c[0]), "+f"(c[1]), "+f"(c[2]), "+f"(c[3])
                 : "r"(a[0]), "r"(a[1]), "r"(a[2]), "r"(a[3]), "r"(b[0]), "r"(b[1]));
}

// permuted destination row for the xcat concat (also the x source row!)
__device__ __forceinline__ int xcat_row(int gm) {
    int b = gm / LQ;
    int rem = gm - b * LQ;
    return (b * (TT * PP) + (rem >> 2)) * 5 + (rem & 3) + 1;
}

// ============================================================================
// BIG GEMM: BM=128, BN=128, BK=64, 256 threads (QKV / FC1 / FC2).
// ============================================================================
#define BIG_STG  32768
#define BIG_SMEM 65536

__device__ __forceinline__ void big_load_stage(
    const __half* __restrict__ A, const __half* __restrict__ W, uint32_t sb,
    int st, int kt, int row0, int col0, int M, int K, int tid)
{
    const int r0 = tid >> 3, ck = tid & 7;
    const uint32_t base = sb + st * BIG_STG;
#pragma unroll
    for (int i = 0; i < 4; i++) {
        int r = r0 + i * 32;
        uint32_t swoff = (uint32_t)(r * 128 + ((ck ^ (r & 7)) * 16));
        int gm = row0 + r;
        cpa16(base + swoff, A + (size_t)gm * K + (size_t)kt * 64 + ck * 8, gm < M);
        cpa16(base + 16384 + swoff,
              W + (size_t)(col0 + r) * K + (size_t)kt * 64 + ck * 8, true);
    }
}

__global__ __launch_bounds__(256, 2) void k_gemm_big(
    const __half* __restrict__ A, const __half* __restrict__ W,
    const float* __restrict__ bias, const float* __restrict__ res,
    void* __restrict__ outp, int M, int N, int K, int epi, int outHalf)
{
    extern __shared__ __align__(1024) char sm[];
    uint32_t sb = (uint32_t)__cvta_generic_to_shared(sm);
    const int tid = threadIdx.x, lane = tid & 31, warp = tid >> 5;
    const int g = lane >> 2, t = lane & 3;
    const int wm = (warp >> 1) * 32, wn = (warp & 1) * 64;
    const int row0 = blockIdx.y * 128, col0 = blockIdx.x * 128;
    const int KT = K >> 6;

    float acc[2][8][4];
#pragma unroll
    for (int mi = 0; mi < 2; mi++)
#pragma unroll
        for (int ni = 0; ni < 8; ni++)
#pragma unroll
            for (int r = 0; r < 4; r++) acc[mi][ni][r] = 0.f;

    big_load_stage(A, W, sb, 0, 0, row0, col0, M, K, tid);
    CP_COMMIT();

    for (int kt = 0; kt < KT; kt++) {
        const int s = kt & 1;
        if (kt + 1 < KT) {
            big_load_stage(A, W, sb, s ^ 1, kt + 1, row0, col0, M, K, tid);
            CP_COMMIT();
            CP_WAIT(1);
        } else {
            CP_WAIT(0);
        }
        __syncthreads();

        const uint32_t aS = sb + s * BIG_STG;
        const uint32_t bS = aS + 16384;
        const int rlow = lane & 15, hi = lane >> 4;
#pragma unroll
        for (int kk = 0; kk < 4; kk++) {
            uint32_t af[2][4];
#pragma unroll
            for (int mi = 0; mi < 2; mi++) {
                int r = wm + mi * 16 + rlow;
                int ck = kk * 2 + hi;
                ldm4(af[mi], aS + (uint32_t)(r * 128 + ((ck ^ (r & 7)) * 16)));
            }
            uint32_t bf[8][2];
#pragma unroll
            for (int nj = 0; nj < 4; nj++) {
                int r = wn + nj * 16 + rlow;
                int ck = kk * 2 + hi;
                uint32_t q[4];
                ldm4(q, bS + (uint32_t)(r * 128 + ((ck ^ (r & 7)) * 16)));
                bf[nj * 2 + 0][0] = q[0]; bf[nj * 2 + 0][1] = q[2];
                bf[nj * 2 + 1][0] = q[1]; bf[nj * 2 + 1][1] = q[3];
            }
#pragma unroll
            for (int mi = 0; mi < 2; mi++)
#pragma unroll
                for (int ni = 0; ni < 8; ni++)
                    mma16(acc[mi][ni], af[mi], bf[ni]);
        }
        __syncthreads();
    }

#pragma unroll
    for (int mi = 0; mi < 2; mi++) {
#pragma unroll
        for (int r = 0; r < 2; r++) {
            const int gm = row0 + wm + mi * 16 + g + r * 8;
            if (gm >= M) continue;
            const float* rp = res + (size_t)gm * N;
#pragma unroll
            for (int ni = 0; ni < 8; ni++) {
                const int gn = col0 + wn + ni * 8 + 2 * t;
                float v0 = acc[mi][ni][r * 2 + 0] + bias[gn];
                float v1 = acc[mi][ni][r * 2 + 1] + bias[gn + 1];
                if (epi == 1) {
                    v0 += rp[gn];
                    v1 += rp[gn + 1];
                } else if (epi == 2) {
                    v0 = 0.5f * v0 * (1.0f + erff(v0 * 0.7071067811865475f));
                    v1 = 0.5f * v1 * (1.0f + erff(v1 * 0.7071067811865475f));
                }
                if (outHalf) {
                    *(__half2*)((__half*)outp + (size_t)gm * N + gn) = __floats2half2_rn(v0, v1);
                } else {
                    *(float2*)((float*)outp + (size_t)gm * N + gn) = make_float2(v0, v1);
                }
            }
        }
    }
}

// ============================================================================
// SMALL GEMM: BM=64, BN=128, BK=64, 128 threads; epi3 = residual + LN fusion.
// ============================================================================
#define STG 24576
#define SREDOFF 49152
#define GEMM_SMEM 50176

__device__ __forceinline__ void gemm_load_stage(
    const __half* __restrict__ A, const __half* __restrict__ W, uint32_t sb,
    int st, int kt, int row0, int col0, int M, int K, int tid)
{
    const int r0 = tid >> 3, ck = tid & 7;
    const uint32_t base = sb + st * STG;
#pragma unroll
    for (int i = 0; i < 4; i++) {
        int r = r0 + i * 16;
        uint32_t swoff = (uint32_t)(r * 128 + ((ck ^ (r & 7)) * 16));
        int gm = row0 + r;
        cpa16(base + swoff, A + (size_t)gm * K + (size_t)kt * 64 + ck * 8, gm < M);
    }
#pragma unroll
    for (int i = 0; i < 8; i++) {
        int r = r0 + i * 16;
        uint32_t swoff = (uint32_t)(r * 128 + ((ck ^ (r & 7)) * 16));
        cpa16(base + 8192 + swoff,
              W + (size_t)(col0 + r) * K + (size_t)kt * 64 + ck * 8, true);
    }
}

__global__ __launch_bounds__(128, 4) void k_gemm_h(
    const __half* __restrict__ A, const __half* __restrict__ W,
    const float* __restrict__ bias, const float* __restrict__ res,
    void* __restrict__ outp, int M, int N, int K, int epi, int outHalf, int perm,
    const float* __restrict__ lnG, const float* __restrict__ lnB,
    __half* __restrict__ out2)
{
    extern __shared__ __align__(1024) char sm[];
    uint32_t sb = (uint32_t)__cvta_generic_to_shared(sm);
    float* sred = (float*)(sm + SREDOFF);
    const int tid = threadIdx.x, lane = tid & 31, warp = tid >> 5;
    const int g = lane >> 2, t = lane & 3;
    const int wm = (warp >> 1) * 32, wn = (warp & 1) * 64;
    const int row0 = blockIdx.y * 64, col0 = blockIdx.x * 128;
    const int KT = K >> 6;

    float acc[2][8][4];
#pragma unroll
    for (int mi = 0; mi < 2; mi++)
#pragma unroll
        for (int ni = 0; ni < 8; ni++)
#pragma unroll
            for (int r = 0; r < 4; r++) acc[mi][ni][r] = 0.f;

    gemm_load_stage(A, W, sb, 0, 0, row0, col0, M, K, tid);
    CP_COMMIT();

    for (int kt = 0; kt < KT; kt++) {
        const int s = kt & 1;
        if (kt + 1 < KT) {
            gemm_load_stage(A, W, sb, s ^ 1, kt + 1, row0, col0, M, K, tid);
            CP_COMMIT();
            CP_WAIT(1);
        } else {
            CP_WAIT(0);
        }
        __syncthreads();

        const uint32_t aS = sb + s * STG;
        const uint32_t bS = aS + 8192;
        const int rlow = lane & 15, hi = lane >> 4;
#pragma unroll
        for (int kk = 0; kk < 4; kk++) {
            uint32_t af[2][4];
#pragma unroll
            for (int mi = 0; mi < 2; mi++) {
                int r = wm + mi * 16 + rlow;
                int ck = kk * 2 + hi;
                ldm4(af[mi], aS + (uint32_t)(r * 128 + ((ck ^ (r & 7)) * 16)));
            }
            uint32_t bf[8][2];
#pragma unroll
            for (int nj = 0; nj < 4; nj++) {
                int r = wn + nj * 16 + rlow;
                int ck = kk * 2 + hi;
                uint32_t q[4];
                ldm4(q, bS + (uint32_t)(r * 128 + ((ck ^ (r & 7)) * 16)));
                bf[nj * 2 + 0][0] = q[0]; bf[nj * 2 + 0][1] = q[2];
                bf[nj * 2 + 1][0] = q[1]; bf[nj * 2 + 1][1] = q[3];
            }
#pragma unroll
            for (int mi = 0; mi < 2; mi++)
#pragma unroll
                for (int ni = 0; ni < 8; ni++)
                    mma16(acc[mi][ni], af[mi], bf[ni]);
        }
        __syncthreads();
    }

#pragma unroll
    for (int mi = 0; mi < 2; mi++) {
#pragma unroll
        for (int r = 0; r < 2; r++) {
            const int gm = row0 + wm + mi * 16 + g + r * 8;
            float psum = 0.f, psq = 0.f;
            if (gm < M) {
                const size_t orow = (epi == 3 && perm) ? (size_t)xcat_row(gm) : (size_t)gm;
                const float* rp = res + orow * N;
#pragma unroll
                for (int ni = 0; ni < 8; ni++) {
                    const int gn = col0 + wn + ni * 8 + 2 * t;
                    float v0 = acc[mi][ni][r * 2 + 0] + bias[gn];
                    float v1 = acc[mi][ni][r * 2 + 1] + bias[gn + 1];
                    if (epi == 1 || epi == 3) {
                        v0 += rp[gn];
                        v1 += rp[gn + 1];
                    } else if (epi == 2) {
                        v0 = 0.5f * v0 * (1.0f + erff(v0 * 0.7071067811865475f));
                        v1 = 0.5f * v1 * (1.0f + erff(v1 * 0.7071067811865475f));
                    }
                    if (outHalf) {
                        *(__half2*)((__half*)outp + orow * N + gn) = __floats2half2_rn(v0, v1);
                    } else {
                        *(float2*)((float*)outp + orow * N + gn) = make_float2(v0, v1);
                    }
                    acc[mi][ni][r * 2 + 0] = v0;
                    acc[mi][ni][r * 2 + 1] = v1;
                    psum += v0 + v1;
                    psq  += v0 * v0 + v1 * v1;
                }
            }
            if (epi == 3) {
                psum += __shfl_xor_sync(0xffffffffu, psum, 1);
                psum += __shfl_xor_sync(0xffffffffu, psum, 2);
                psq  += __shfl_xor_sync(0xffffffffu, psq, 1);
                psq  += __shfl_xor_sync(0xffffffffu, psq, 2);
                if (t == 0) {
                    int lr = wm + mi * 16 + g + r * 8;
                    sred[lr * 4 + (warp & 1) * 2 + 0] = psum;
                    sred[lr * 4 + (warp & 1) * 2 + 1] = psq;
                }
            }
        }
    }
    if (epi == 3) {
        __syncthreads();
#pragma unroll
        for (int mi = 0; mi < 2; mi++) {
#pragma unroll
            for (int r = 0; r < 2; r++) {
                const int gm = row0 + wm + mi * 16 + g + r * 8;
                if (gm >= M) continue;
                const size_t orow = perm ? (size_t)xcat_row(gm) : (size_t)gm;
                const int lr = wm + mi * 16 + g + r * 8;
                float sum = sred[lr * 4 + 0] + sred[lr * 4 + 2];
                float sq  = sred[lr * 4 + 1] + sred[lr * 4 + 3];
                float mean = sum * (1.f / 128.f);
                float var = sq * (1.f / 128.f) - mean * mean;
                float rstd = rsqrtf(var + 1e-5f);
#pragma unroll
                for (int ni = 0; ni < 8; ni++) {
                    const int gn = col0 + wn + ni * 8 + 2 * t;
                    float a0 = (acc[mi][ni][r * 2 + 0] - mean) * rstd * lnG[gn] + lnB[gn];
                    float a1 = (acc[mi][ni][r * 2 + 1] - mean) * rstd * lnG[gn + 1] + lnB[gn + 1];
                    *(__half2*)(out2 + orow * 128 + gn) = __floats2half2_rn(a0, a1);
                }
            }
        }
    }
}

// ============================================================================
// Merged projection GEMM: offaw (N=384, cols 0-2) + val (N=128, col 3).
// ============================================================================
__global__ __launch_bounds__(128, 4) void k_projs(const float* __restrict__ b_val)
{
    extern __shared__ __align__(1024) char sm[];
    uint32_t sb = (uint32_t)__cvta_generic_to_shared(sm);
    const int tid = threadIdx.x, lane = tid & 31, warp = tid >> 5;
    const int g = lane >> 2, t = lane & 3;
    const int wm = (warp >> 1) * 32, wn = (warp & 1) * 64;
    const int row0 = blockIdx.y * 64;

    const __half* A; const __half* W; const float* bias; __half* outp; int N; int col0;
    if (blockIdx.x < 3) {
        A = g_Qh;  W = g_Wh + WOFF_OFF; bias = g_Bcat; outp = g_OFFAWh;
        N = 384; col0 = blockIdx.x * 128;
    } else {
        A = g_XNh; W = g_Wh + WOFF_VAL; bias = b_val;  outp = g_VALh;
        N = 128; col0 = 0;
    }
    const int M = BLQ, K = CC, KT = 2;

    float acc[2][8][4];
#pragma unroll
    for (int mi = 0; mi < 2; mi++)
#pragma unroll
        for (int ni = 0; ni < 8; ni++)
#pragma unroll
            for (int r = 0; r < 4; r++) acc[mi][ni][r] = 0.f;

    gemm_load_stage(A, W, sb, 0, 0, row0, col0, M, K, tid);
    CP_COMMIT();

    for (int kt = 0; kt < KT; kt++) {
        const int s = kt & 1;
        if (kt + 1 < KT) {
            gemm_load_stage(A, W, sb, s ^ 1, kt + 1, row0, col0, M, K, tid);
            CP_COMMIT();
            CP_WAIT(1);
        } else {
            CP_WAIT(0);
        }
        __syncthreads();

        const uint32_t aS = sb + s * STG;
        const uint32_t bS = aS + 8192;
        const int rlow = lane & 15, hi = lane >> 4;
#pragma unroll
        for (int kk = 0; kk < 4; kk++) {
            uint32_t af[2][4];
#pragma unroll
            for (int mi = 0; mi < 2; mi++) {
                int r = wm + mi * 16 + rlow;
                int ck = kk * 2 + hi;
                ldm4(af[mi], aS + (uint32_t)(r * 128 + ((ck ^ (r & 7)) * 16)));
            }
            uint32_t bf[8][2];
#pragma unroll
            for (int nj = 0; nj < 4; nj++) {
                int r = wn + nj * 16 + rlow;
                int ck = kk * 2 + hi;
                uint32_t q[4];
                ldm4(q, bS + (uint32_t)(r * 128 + ((ck ^ (r & 7)) * 16)));
                bf[nj * 2 + 0][0] = q[0]; bf[nj * 2 + 0][1] = q[2];
                bf[nj * 2 + 1][0] = q[1]; bf[nj * 2 + 1][1] = q[3];
            }
#pragma unroll
            for (int mi = 0; mi < 2; mi++)
#pragma unroll
                for (int ni = 0; ni < 8; ni++)
                    mma16(acc[mi][ni], af[mi], bf[ni]);
        }
        __syncthreads();
    }

#pragma unroll
    for (int mi = 0; mi < 2; mi++) {
#pragma unroll
        for (int r = 0; r < 2; r++) {
            const int gm = row0 + wm + mi * 16 + g + r * 8;
            if (gm >= M) continue;
#pragma unroll
            for (int ni = 0; ni < 8; ni++) {
                const int gn = col0 + wn + ni * 8 + 2 * t;
                float v0 = acc[mi][ni][r * 2 + 0] + bias[gn];
                float v1 = acc[mi][ni][r * 2 + 1] + bias[gn + 1];
                *(__half2*)(outp + (size_t)gm * N + gn) = __floats2half2_rn(v0, v1);
            }
        }
    }
}

// ============================================================================
// Merged prologue: ln1 (BLQ blocks) + lvl0 (BTP blocks) + weight cvt (272).
// ============================================================================
__global__ __launch_bounds__(128) void k_pre(
    const float* __restrict__ x, const float* __restrict__ pe,
    const float* __restrict__ lp,
    const float* __restrict__ g1, const float* __restrict__ be1,
    const float* __restrict__ g2, const float* __restrict__ be2,
    const float* __restrict__ w0, const float* __restrict__ w1,
    const float* __restrict__ w2, const float* __restrict__ w3,
    const float* __restrict__ w4, const float* __restrict__ w5,
    const float* __restrict__ w6, const float* __restrict__ w7,
    const float* __restrict__ b_off, const float* __restrict__ b_attn)
{
    const int bid = blockIdx.x;
    const int c = threadIdx.x;

    if (bid < BLQ) {
        int row = bid;
        int b = row / LQ; int lq = row - b * LQ;
        int l = lq & 3; int tp = lq >> 2;
        size_t xi = ((size_t)(b * TT * PP + tp) * NLVL + (l + 1)) * CC + c;
        float v = x[xi];

        __shared__ float sh[8];
        float s = v;
        for (int o = 16; o > 0; o >>= 1) s += __shfl_xor_sync(0xffffffffu, s, o);
        if ((c & 31) == 0) sh[c >> 5] = s;
        __syncthreads();
        float mean = (sh[0] + sh[1] + sh[2] + sh[3]) * (1.f / CC);
        float dv = v - mean;
        float q2 = dv * dv;
        for (int o = 16; o > 0; o >>= 1) q2 += __shfl_xor_sync(0xffffffffu, q2, o);
        if ((c & 31) == 0) sh[4 + (c >> 5)] = q2;
        __syncthreads();
        float var = (sh[4] + sh[5] + sh[6] + sh[7]) * (1.f / CC);
        float xn = dv * rsqrtf(var + 1e-5f) * g1[c] + be1[c];
        g_XNh[(size_t)row * CC + c] = __float2half_rn(xn);
        g_Qh [(size_t)row * CC + c] = __float2half_rn(xn + pe[(size_t)lq * CC + c] + lp[(size_t)lq * CC + c]);
    } else if (bid < BLQ + BTP) {
        int btp = bid - BLQ;
        size_t rowoff = (size_t)btp * NLVL * CC;
        float v = x[rowoff + c];
        g_XCAT[rowoff + c] = v;

        __shared__ float sh2[8];
        float s = v;
        for (int o = 16; o > 0; o >>= 1) s += __shfl_xor_sync(0xffffffffu, s, o);
        if ((c & 31) == 0) sh2[c >> 5] = s;
        __syncthreads();
        float mean = (sh2[0] + sh2[1] + sh2[2] + sh2[3]) * (1.f / CC);
        float dv = v - mean;
        float q2 = dv * dv;
        for (int o = 16; o > 0; o >>= 1) q2 += __shfl_xor_sync(0xffffffffu, q2, o);
        if ((c & 31) == 0) sh2[4 + (c >> 5)] = q2;
        __syncthreads();
        float var = (sh2[4] + sh2[5] + sh2[6] + sh2[7]) * (1.f / CC);
        g_XN2h[rowoff + c] = __float2half_rn(dv * rsqrtf(var + 1e-5f) * g2[c] + be2[c]);
    } else {
        int wb = bid - BLQ - BTP;             // 0..271
        if (wb == 0 && c < 128) {
            g_Bcat[c]       = b_off[c];
            g_Bcat[c + 128] = b_off[c + 128];
            g_Bcat[c + 256] = b_attn[c];
        }
        for (int idx = wb * 128 + c; idx < WTOTAL; idx += 272 * 128) {
            const float* src; int off;
            if      (idx < WOFF_ATTN) { src = w0; off = idx; }
            else if (idx < WOFF_VAL ) { src = w1; off = idx - WOFF_ATTN; }
            else if (idx < WOFF_OUT ) { src = w2; off = idx - WOFF_VAL; }
            else if (idx < WOFF_IN  ) { src = w3; off = idx - WOFF_OUT; }
            else if (idx < WOFF_OUTW) { src = w4; off = idx - WOFF_IN; }
            else if (idx < WOFF_FC1 ) { src = w5; off = idx - WOFF_OUTW; }
            else if (idx < WOFF_FC2 ) { src = w6; off = idx - WOFF_FC1; }
            else                      { src = w7; off = idx - WOFF_FC2; }
            g_Wh[idx] = __float2half_rn(src[off]);
        }
    }
}

// ============================================================================
// Deformable sampling v3: depth-3 pipeline, 16 single-point waves, 4 buffers.
// Per-thread offset/weight loads straight from global (vectorized), no sOFF.
// smem: sG 4 x 4corners x 128thr x 16B = 32KB static -> 7 blocks/SM.
// ============================================================================
#define DEF_RPB 8
__global__ __launch_bounds__(128) void k_deform(const float* __restrict__ refp)
{
    __shared__ __align__(16) uint4 sG[4][4][128];   // [buf][corner][tid]
    const int row0 = blockIdx.x * DEF_RPB;
    const int tid = threadIdx.x;
    const uint32_t sgb = (uint32_t)__cvta_generic_to_shared(&sG[0][0][tid]);

    const int rr = tid >> 4;
    const int s = tid & 15;
    const int row = row0 + rr;
    const int b = row / LQ; const int lq = row - b * LQ;
    const int tp = lq >> 2; const int p = tp % PP; const int t = tp / PP;
    const int h = s >> 1, dq = s & 1;
    const float refx = refp[(((size_t)b * TT + t) * PP + p) * 2 + 0];
    const float refy = refp[(((size_t)b * TT + t) * PP + p) * 2 + 1];

    // per-thread vectorized offset + attn-weight loads (64B + 32B aligned)
    float offs[32], w[16];
    {
        const uint4* op = (const uint4*)(g_OFFAWh + (size_t)row * 384 + h * 32);
#pragma unroll
        for (int i = 0; i < 4; i++) {
            uint4 q = op[i];
            const __half2* hp = (const __half2*)&q;
#pragma unroll
            for (int j = 0; j < 4; j++) {
                float2 f = __half22float2(hp[j]);
                offs[i * 8 + 2 * j + 0] = f.x;
                offs[i * 8 + 2 * j + 1] = f.y;
            }
        }
        const uint4* ap = (const uint4*)(g_OFFAWh + (size_t)row * 384 + 256 + h * 16);
#pragma unroll
        for (int i = 0; i < 2; i++) {
            uint4 q = ap[i];
            const __half2* hp = (const __half2*)&q;
#pragma unroll
            for (int j = 0; j < 4; j++) {
                float2 f = __half22float2(hp[j]);
                w[i * 8 + 2 * j + 0] = f.x;
                w[i * 8 + 2 * j + 1] = f.y;
            }
        }
    }
    float mx = -1e30f;
#pragma unroll
    for (int i = 0; i < 16; i++) mx = fmaxf(mx, w[i]);
    float den = 0.f;
#pragma unroll
    for (int i = 0; i < 16; i++) { w[i] = __expf(w[i] - mx); den += w[i]; }
    float inv = 1.f / den;

    const __half* vbase = g_VALh + (size_t)b * LQ * CC + h * 16 + dq * 8;
    float acc[8];
#pragma unroll
    for (int j = 0; j < 8; j++) acc[j] = 0.f;

    float cw[4][4];   // [buf][corner] combined weights

    auto issue_wave = [&](int pt, int buf) {
        const int l = pt >> 2;
        float ox = offs[pt * 2 + 0];
        float oy = offs[pt * 2 + 1];
        float fx = refx * PP + ox - 0.5f;
        float fy = refy * TT + oy - 0.5f;
        float x0f = floorf(fx), y0f = floorf(fy);
        int x0 = (int)x0f, y0 = (int)y0f;
        float wx1 = fx - x0f, wy1 = fy - y0f;
        float wx0 = 1.f - wx1, wy0 = 1.f - wy1;
        bool xi0 = (x0 >= 0) && (x0 < PP);
        bool xi1 = (x0 + 1 >= 0) && (x0 + 1 < PP);
        bool yi0 = (y0 >= 0) && (y0 < TT);
        bool yi1 = (y0 + 1 >= 0) && (y0 + 1 < TT);
        float ww = w[pt];
        cw[buf][0] = wy0 * wx0 * ww;
        cw[buf][1] = wy0 * wx1 * ww;
        cw[buf][2] = wy1 * wx0 * ww;
        cw[buf][3] = wy1 * wx1 * ww;
        const uint32_t sp = sgb + (uint32_t)(buf * 4) * 2048;
        cpa16(sp        , vbase + ((size_t)(y0 * PP + x0) * LL + l) * CC,           yi0 && xi0);
        cpa16(sp + 2048 , vbase + ((size_t)(y0 * PP + x0 + 1) * LL + l) * CC,       yi0 && xi1);
        cpa16(sp + 4096 , vbase + ((size_t)((y0 + 1) * PP + x0) * LL + l) * CC,     yi1 && xi0);
        cpa16(sp + 6144 , vbase + ((size_t)((y0 + 1) * PP + x0 + 1) * LL + l) * CC, yi1 && xi1);
        CP_COMMIT();
    };
    auto reduce_wave = [&](int buf) {
#pragma unroll
        for (int c = 0; c < 4; c++) {
            uint4 q = sG[buf][c][tid];
            const __half2* hp = (const __half2*)&q;
            float ww = cw[buf][c];
#pragma unroll
            for (int j = 0; j < 4; j++) {
                float2 f = __half22float2(hp[j]);
                acc[2 * j + 0] = fmaf(f.x, ww, acc[2 * j + 0]);
                acc[2 * j + 1] = fmaf(f.y, ww, acc[2 * j + 1]);
            }
        }
    };

    issue_wave(0, 0);
    issue_wave(1, 1);
    issue_wave(2, 2);
#pragma unroll
    for (int pt = 0; pt < 13; pt++) {
        issue_wave(pt + 3, (pt + 3) & 3);
        CP_WAIT(3);
        reduce_wave(pt & 3);
    }
    CP_WAIT(2); reduce_wave(13 & 3);
    CP_WAIT(1); reduce_wave(14 & 3);
    CP_WAIT(0); reduce_wave(15 & 3);

    __half2 ho[4];
#pragma unroll
    for (int j = 0; j < 4; j++)
        ho[j] = __floats2half2_rn(acc[2 * j] * inv, acc[2 * j + 1] * inv);
    *(uint4*)(g_Oh + (size_t)row * CC + h * 16 + dq * 8) = *(uint4*)ho;
}

// ---------------- per-(bt,head) self-attention (fp16 QKV) ------------------
__global__ void k_attn()
{
    int bt = blockIdx.x, h = blockIdx.y;
    __shared__ float Qs[SS][DHH], Ks[SS][DHH], Vs[SS][DHH];
    int tid = threadIdx.x;
    for (int i = tid; i < SS * DHH; i += 128) {
        int s = i >> 4, d = i & 15;
        const __half* base = g_QKVh + ((size_t)bt * SS + s) * 384 + h * 16 + d;
        Qs[s][d] = __half2float(base[0]);
        Ks[s][d] = __half2float(base[128]);
        Vs[s][d] = __half2float(base[256]);
    }
    __syncthreads();
    if (tid < SS) {
        float qv[16];
#pragma unroll
        for (int d = 0; d < 16; d++) qv[d] = Qs[tid][d];
        float mx = -1e30f;
        for (int k = 0; k < SS; k++) {
            float sdot = 0.f;
#pragma unroll
            for (int d = 0; d < 16; d++) sdot = fmaf(qv[d], Ks[k][d], sdot);
            mx = fmaxf(mx, sdot * 0.25f);
        }
        float den = 0.f, o[16];
#pragma unroll
        for (int d = 0; d < 16; d++) o[d] = 0.f;
        for (int k = 0; k < SS; k++) {
            float sdot = 0.f;
#pragma unroll
            for (int d = 0; d < 16; d++) sdot = fmaf(qv[d], Ks[k][d], sdot);
            float e = __expf(sdot * 0.25f - mx);
            den += e;
#pragma unroll
            for (int d = 0; d < 16; d++) o[d] = fmaf(e, Vs[k][d], o[d]);
        }
        float inv = 1.f / den;
        __half* outp = g_ATTOh + ((size_t)bt * SS + tid) * CC + h * 16;
#pragma unroll
        for (int d = 0; d < 16; d++) outp[d] = __float2half_rn(o[d] * inv);
    }
}

// ---------------- host launch ----------------------------------------------
static inline void launch_small(const __half* A, const __half* W, const float* bias,
                                const float* res, void* out, int M, int N, int K,
                                int epi, int outHalf, int perm = 0,
                                const float* lnG = nullptr, const float* lnB = nullptr,
                                __half* out2 = nullptr)
{
    dim3 grid(N / 128, (M + 63) / 64);
    k_gemm_h<<<grid, 128, GEMM_SMEM>>>(A, W, bias, res ? res : (const float*)A,
                                       out, M, N, K, epi, outHalf, perm, lnG, lnB, out2);
}
static inline void launch_big(const __half* A, const __half* W, const float* bias,
                              const float* res, void* out, int M, int N, int K,
                              int epi, int outHalf)
{
    dim3 grid(N / 128, (M + 127) / 128);
    k_gemm_big<<<grid, 256, BIG_SMEM>>>(A, W, bias, res ? res : (const float*)A,
                                        out, M, N, K, epi, outHalf);
}

extern "C" void kernel_launch(void* const* d_in, const int* in_sizes, int n_in,
                              void* d_out, int out_size)
{
    (void)in_sizes; (void)n_in; (void)out_size;
    const float* x        = (const float*)d_in[0];
    const float* refp     = (const float*)d_in[1];
    const float* pe_buf   = (const float*)d_in[2];
    const float* learn_pos= (const float*)d_in[3];
    const float* w_off    = (const float*)d_in[4];
    const float* b_off    = (const float*)d_in[5];
    const float* w_attn   = (const float*)d_in[6];
    const float* b_attn   = (const float*)d_in[7];
    const float* w_val    = (const float*)d_in[8];
    const float* b_val    = (const float*)d_in[9];
    const float* w_out    = (const float*)d_in[10];
    const float* b_out    = (const float*)d_in[11];
    const float* in_w     = (const float*)d_in[12];
    const float* in_b     = (const float*)d_in[13];
    const float* out_w    = (const float*)d_in[14];
    const float* b_out2   = (const float*)d_in[15];
    const float* fc1_w    = (const float*)d_in[16];
    const float* fc1_b    = (const float*)d_in[17];
    const float* fc2_w    = (const float*)d_in[18];
    const float* fc2_b    = (const float*)d_in[19];
    const float* g1       = (const float*)d_in[20];
    const float* be1      = (const float*)d_in[21];
    const float* g2       = (const float*)d_in[22];
    const float* be2      = (const float*)d_in[23];
    const float* g3       = (const float*)d_in[24];
    const float* be3      = (const float*)d_in[25];
    float* out = (float*)d_out;

    cudaFuncSetAttribute(k_gemm_h,   cudaFuncAttributeMaxDynamicSharedMemorySize, GEMM_SMEM);
    cudaFuncSetAttribute(k_projs,    cudaFuncAttributeMaxDynamicSharedMemorySize, GEMM_SMEM);
    cudaFuncSetAttribute(k_gemm_big, cudaFuncAttributeMaxDynamicSharedMemorySize, BIG_SMEM);

    float *pXCAT, *pXCAT2;
    __half *pOh, *pXN2h, *pQKVh, *pATTOh, *pXN3h, *pHIDh, *pWh;
    cudaGetSymbolAddress((void**)&pXCAT,  g_XCAT);
    cudaGetSymbolAddress((void**)&pXCAT2, g_XCAT2);
    cudaGetSymbolAddress((void**)&pOh,    g_Oh);
    cudaGetSymbolAddress((void**)&pXN2h,  g_XN2h);
    cudaGetSymbolAddress((void**)&pQKVh,  g_QKVh);
    cudaGetSymbolAddress((void**)&pATTOh, g_ATTOh);
    cudaGetSymbolAddress((void**)&pXN3h,  g_XN3h);
    cudaGetSymbolAddress((void**)&pHIDh,  g_HIDh);
    cudaGetSymbolAddress((void**)&pWh,    g_Wh);

    // 1) merged prologue: LN1 + lvl0(LN2) + weight cvt
    k_pre<<<BLQ + BTP + 272, 128>>>(x, pe_buf, learn_pos, g1, be1, g2, be2,
                                    w_off, w_attn, w_val, w_out, in_w, out_w,
                                    fc1_w, fc2_w, b_off, b_attn);
    // 2) merged projections: offaw (N=384) + val (N=128) -> fp16
    {
        dim3 grid(4, (BLQ + 63) / 64);
        k_projs<<<grid, 128, GEMM_SMEM>>>(b_val);
    }
    // 3) deformable sampling (depth-3 pipeline)
    k_deform<<<BLQ / DEF_RPB, 128>>>(refp);
    // 4) out-proj + residual(from x, permuted) + concat + fused LN2 [epi3, perm]
    launch_small(pOh, pWh + WOFF_OUT, b_out, x, pXCAT, BLQ, 128, CC, 3, 0, 1,
                 g2, be2, pXN2h);
    // 5) QKV GEMM (N=384) -> fp16  [BIG]
    launch_big(pXN2h, pWh + WOFF_IN, in_b, nullptr, pQKVh, TOK, 384, CC, 0, 1);
    // 6) self-attention
    k_attn<<<dim3(BB * TT, HH), 128>>>();
    // 7) attention out-proj + residual + fused LN3 [epi3]
    launch_small(pATTOh, pWh + WOFF_OUTW, b_out2, pXCAT, pXCAT2, TOK, 128, CC, 3, 0, 0,
                 g3, be3, pXN3h);
    // 8) FC1 + GELU (N=512) -> fp16 [BIG]
    launch_big(pXN3h, pWh + WOFF_FC1, fc1_b, nullptr, pHIDh, TOK, 512, CC, 2, 1);
    // 9) FC2 + residual -> final output (K=512) [BIG]
    launch_big(pHIDh, pWh + WOFF_FC2, fc2_b, pXCAT2, out, TOK, 128, 512, 1, 0);
}

// round 17
// speedup vs baseline: 1.0977x; 1.0204x over previous
#include <cuda_runtime.h>
#include <cuda_fp16.h>
#include <math.h>
#include <stdint.h>

// Problem constants
#define TT   243
#define PP   17
#define LL   4
#define CC   128
#define HH   8
#define NPT  4
#define DHH  16
#define BB   2
#define LQ   (TT*PP*LL)        // 16524
#define BLQ  (BB*LQ)           // 33048
#define NLVL 5
#define BTP  (BB*TT*PP)        // 8262
#define TOK  (BTP*NLVL)        // 41310
#define SS   (PP*NLVL)         // 85

// ---------------- scratch (device globals; no allocations) ----------------
__device__ __half g_XCATh [(size_t)TOK*CC];   // residual chain, fp16
__device__ __half g_XCAT2h[(size_t)TOK*CC];
__device__ __half g_OFFAWh[(size_t)BLQ*384];
__device__ __half g_Qh   [(size_t)BLQ*CC];
__device__ __half g_XNh  [(size_t)BLQ*CC];
__device__ __half g_VALh [(size_t)BLQ*CC];
__device__ __half g_Oh   [(size_t)BLQ*CC];
__device__ __half g_XN2h [(size_t)TOK*CC];
__device__ __half g_QKVh [(size_t)TOK*384];
__device__ __half g_ATTOh[(size_t)TOK*CC];
__device__ __half g_XN3h [(size_t)TOK*CC];
__device__ __half g_HIDh [(size_t)TOK*512];
#define WOFF_OFF   0
#define WOFF_ATTN  32768
#define WOFF_VAL   49152
#define WOFF_OUT   65536
#define WOFF_IN    81920
#define WOFF_OUTW  131072
#define WOFF_FC1   147456
#define WOFF_FC2   212992
#define WTOTAL     278528
__device__ __half g_Wh[WTOTAL];
__device__ float  g_Bcat[384];

// ---------------- PTX helpers ----------------------------------------------
__device__ __forceinline__ void cpa16(uint32_t dst, const void* src, bool valid) {
    int sz = valid ? 16 : 0;
    asm volatile("cp.async.cg.shared.global [%0], [%1], 16, %2;\n"
                 :: "r"(dst), "l"(src), "r"(sz));
}
#define CP_COMMIT() asm volatile("cp.async.commit_group;\n" ::: "memory")
#define CP_WAIT(n)  asm volatile("cp.async.wait_group %0;\n" :: "n"(n) : "memory")

__device__ __forceinline__ void ldm4(uint32_t* r, uint32_t addr) {
    asm volatile("ldmatrix.sync.aligned.m8n8.x4.shared.b16 {%0,%1,%2,%3}, [%4];\n"
                 : "=r"(r[0]), "=r"(r[1]), "=r"(r[2]), "=r"(r[3]) : "r"(addr));
}
__device__ __forceinline__ void mma16(float* c, const uint32_t* a, const uint32_t* b) {
    asm volatile("mma.sync.aligned.m16n8k16.row.col.f32.f16.f16.f32 "
                 "{%0,%1,%2,%3},{%4,%5,%6,%7},{%8,%9},{%0,%1,%2,%3};\n"
                 : "+f"(c[0]), "+f"(c[1]), "+f"(c[2]), "+f"(c[3])
                 : "r"(a[0]), "r"(a[1]), "r"(a[2]), "r"(a[3]), "r"(b[0]), "r"(b[1]));
}

// residual fetch: fp32 or fp16 source, returns fp32 pair
__device__ __forceinline__ float2 res2(const void* res, size_t rowoff, int gn, int resHalf) {
    if (resHalf) {
        return __half22float2(*(const __half2*)((const __half*)res + rowoff + gn));
    }
    return *(const float2*)((const float*)res + rowoff + gn);
}

// permuted destination row for the xcat concat (also the x source row!)
__device__ __forceinline__ int xcat_row(int gm) {
    int b = gm / LQ;
    int rem = gm - b * LQ;
    return (b * (TT * PP) + (rem >> 2)) * 5 + (rem & 3) + 1;
}

// ============================================================================
// BIG GEMM: BM=128, BN=128, BK=64, 256 threads (QKV / FC1 / FC2).
// ============================================================================
#define BIG_STG  32768
#define BIG_SMEM 65536

__device__ __forceinline__ void big_load_stage(
    const __half* __restrict__ A, const __half* __restrict__ W, uint32_t sb,
    int st, int kt, int row0, int col0, int M, int K, int tid)
{
    const int r0 = tid >> 3, ck = tid & 7;
    const uint32_t base = sb + st * BIG_STG;
#pragma unroll
    for (int i = 0; i < 4; i++) {
        int r = r0 + i * 32;
        uint32_t swoff = (uint32_t)(r * 128 + ((ck ^ (r & 7)) * 16));
        int gm = row0 + r;
        cpa16(base + swoff, A + (size_t)gm * K + (size_t)kt * 64 + ck * 8, gm < M);
        cpa16(base + 16384 + swoff,
              W + (size_t)(col0 + r) * K + (size_t)kt * 64 + ck * 8, true);
    }
}

__global__ __launch_bounds__(256, 2) void k_gemm_big(
    const __half* __restrict__ A, const __half* __restrict__ W,
    const float* __restrict__ bias, const void* __restrict__ res,
    void* __restrict__ outp, int M, int N, int K, int epi, int outHalf, int resHalf)
{
    extern __shared__ __align__(1024) char sm[];
    uint32_t sb = (uint32_t)__cvta_generic_to_shared(sm);
    const int tid = threadIdx.x, lane = tid & 31, warp = tid >> 5;
    const int g = lane >> 2, t = lane & 3;
    const int wm = (warp >> 1) * 32, wn = (warp & 1) * 64;
    const int row0 = blockIdx.y * 128, col0 = blockIdx.x * 128;
    const int KT = K >> 6;

    float acc[2][8][4];
#pragma unroll
    for (int mi = 0; mi < 2; mi++)
#pragma unroll
        for (int ni = 0; ni < 8; ni++)
#pragma unroll
            for (int r = 0; r < 4; r++) acc[mi][ni][r] = 0.f;

    big_load_stage(A, W, sb, 0, 0, row0, col0, M, K, tid);
    CP_COMMIT();

    for (int kt = 0; kt < KT; kt++) {
        const int s = kt & 1;
        if (kt + 1 < KT) {
            big_load_stage(A, W, sb, s ^ 1, kt + 1, row0, col0, M, K, tid);
            CP_COMMIT();
            CP_WAIT(1);
        } else {
            CP_WAIT(0);
        }
        __syncthreads();

        const uint32_t aS = sb + s * BIG_STG;
        const uint32_t bS = aS + 16384;
        const int rlow = lane & 15, hi = lane >> 4;
#pragma unroll
        for (int kk = 0; kk < 4; kk++) {
            uint32_t af[2][4];
#pragma unroll
            for (int mi = 0; mi < 2; mi++) {
                int r = wm + mi * 16 + rlow;
                int ck = kk * 2 + hi;
                ldm4(af[mi], aS + (uint32_t)(r * 128 + ((ck ^ (r & 7)) * 16)));
            }
            uint32_t bf[8][2];
#pragma unroll
            for (int nj = 0; nj < 4; nj++) {
                int r = wn + nj * 16 + rlow;
                int ck = kk * 2 + hi;
                uint32_t q[4];
                ldm4(q, bS + (uint32_t)(r * 128 + ((ck ^ (r & 7)) * 16)));
                bf[nj * 2 + 0][0] = q[0]; bf[nj * 2 + 0][1] = q[2];
                bf[nj * 2 + 1][0] = q[1]; bf[nj * 2 + 1][1] = q[3];
            }
#pragma unroll
            for (int mi = 0; mi < 2; mi++)
#pragma unroll
                for (int ni = 0; ni < 8; ni++)
                    mma16(acc[mi][ni], af[mi], bf[ni]);
        }
        __syncthreads();
    }

#pragma unroll
    for (int mi = 0; mi < 2; mi++) {
#pragma unroll
        for (int r = 0; r < 2; r++) {
            const int gm = row0 + wm + mi * 16 + g + r * 8;
            if (gm >= M) continue;
            const size_t rowoff = (size_t)gm * N;
#pragma unroll
            for (int ni = 0; ni < 8; ni++) {
                const int gn = col0 + wn + ni * 8 + 2 * t;
                float v0 = acc[mi][ni][r * 2 + 0] + bias[gn];
                float v1 = acc[mi][ni][r * 2 + 1] + bias[gn + 1];
                if (epi == 1) {
                    float2 rr2 = res2(res, rowoff, gn, resHalf);
                    v0 += rr2.x;
                    v1 += rr2.y;
                } else if (epi == 2) {
                    v0 = 0.5f * v0 * (1.0f + erff(v0 * 0.7071067811865475f));
                    v1 = 0.5f * v1 * (1.0f + erff(v1 * 0.7071067811865475f));
                }
                if (outHalf) {
                    *(__half2*)((__half*)outp + rowoff + gn) = __floats2half2_rn(v0, v1);
                } else {
                    *(float2*)((float*)outp + rowoff + gn) = make_float2(v0, v1);
                }
            }
        }
    }
}

// ============================================================================
// SMALL GEMM: BM=64, BN=128, BK=64, 128 threads; epi3 = residual + LN fusion.
// ============================================================================
#define STG 24576
#define SREDOFF 49152
#define GEMM_SMEM 50176

__device__ __forceinline__ void gemm_load_stage(
    const __half* __restrict__ A, const __half* __restrict__ W, uint32_t sb,
    int st, int kt, int row0, int col0, int M, int K, int tid)
{
    const int r0 = tid >> 3, ck = tid & 7;
    const uint32_t base = sb + st * STG;
#pragma unroll
    for (int i = 0; i < 4; i++) {
        int r = r0 + i * 16;
        uint32_t swoff = (uint32_t)(r * 128 + ((ck ^ (r & 7)) * 16));
        int gm = row0 + r;
        cpa16(base + swoff, A + (size_t)gm * K + (size_t)kt * 64 + ck * 8, gm < M);
    }
#pragma unroll
    for (int i = 0; i < 8; i++) {
        int r = r0 + i * 16;
        uint32_t swoff = (uint32_t)(r * 128 + ((ck ^ (r & 7)) * 16));
        cpa16(base + 8192 + swoff,
              W + (size_t)(col0 + r) * K + (size_t)kt * 64 + ck * 8, true);
    }
}

__global__ __launch_bounds__(128, 4) void k_gemm_h(
    const __half* __restrict__ A, const __half* __restrict__ W,
    const float* __restrict__ bias, const void* __restrict__ res,
    void* __restrict__ outp, int M, int N, int K, int epi, int outHalf, int perm,
    int resHalf,
    const float* __restrict__ lnG, const float* __restrict__ lnB,
    __half* __restrict__ out2)
{
    extern __shared__ __align__(1024) char sm[];
    uint32_t sb = (uint32_t)__cvta_generic_to_shared(sm);
    float* sred = (float*)(sm + SREDOFF);
    const int tid = threadIdx.x, lane = tid & 31, warp = tid >> 5;
    const int g = lane >> 2, t = lane & 3;
    const int wm = (warp >> 1) * 32, wn = (warp & 1) * 64;
    const int row0 = blockIdx.y * 64, col0 = blockIdx.x * 128;
    const int KT = K >> 6;

    float acc[2][8][4];
#pragma unroll
    for (int mi = 0; mi < 2; mi++)
#pragma unroll
        for (int ni = 0; ni < 8; ni++)
#pragma unroll
            for (int r = 0; r < 4; r++) acc[mi][ni][r] = 0.f;

    gemm_load_stage(A, W, sb, 0, 0, row0, col0, M, K, tid);
    CP_COMMIT();

    for (int kt = 0; kt < KT; kt++) {
        const int s = kt & 1;
        if (kt + 1 < KT) {
            gemm_load_stage(A, W, sb, s ^ 1, kt + 1, row0, col0, M, K, tid);
            CP_COMMIT();
            CP_WAIT(1);
        } else {
            CP_WAIT(0);
        }
        __syncthreads();

        const uint32_t aS = sb + s * STG;
        const uint32_t bS = aS + 8192;
        const int rlow = lane & 15, hi = lane >> 4;
#pragma unroll
        for (int kk = 0; kk < 4; kk++) {
            uint32_t af[2][4];
#pragma unroll
            for (int mi = 0; mi < 2; mi++) {
                int r = wm + mi * 16 + rlow;
                int ck = kk * 2 + hi;
                ldm4(af[mi], aS + (uint32_t)(r * 128 + ((ck ^ (r & 7)) * 16)));
            }
            uint32_t bf[8][2];
#pragma unroll
            for (int nj = 0; nj < 4; nj++) {
                int r = wn + nj * 16 + rlow;
                int ck = kk * 2 + hi;
                uint32_t q[4];
                ldm4(q, bS + (uint32_t)(r * 128 + ((ck ^ (r & 7)) * 16)));
                bf[nj * 2 + 0][0] = q[0]; bf[nj * 2 + 0][1] = q[2];
                bf[nj * 2 + 1][0] = q[1]; bf[nj * 2 + 1][1] = q[3];
            }
#pragma unroll
            for (int mi = 0; mi < 2; mi++)
#pragma unroll
                for (int ni = 0; ni < 8; ni++)
                    mma16(acc[mi][ni], af[mi], bf[ni]);
        }
        __syncthreads();
    }

#pragma unroll
    for (int mi = 0; mi < 2; mi++) {
#pragma unroll
        for (int r = 0; r < 2; r++) {
            const int gm = row0 + wm + mi * 16 + g + r * 8;
            float psum = 0.f, psq = 0.f;
            if (gm < M) {
                const size_t orow = (epi == 3 && perm) ? (size_t)xcat_row(gm) : (size_t)gm;
                const size_t rowoff = orow * N;
#pragma unroll
                for (int ni = 0; ni < 8; ni++) {
                    const int gn = col0 + wn + ni * 8 + 2 * t;
                    float v0 = acc[mi][ni][r * 2 + 0] + bias[gn];
                    float v1 = acc[mi][ni][r * 2 + 1] + bias[gn + 1];
                    if (epi == 1 || epi == 3) {
                        float2 rr2 = res2(res, rowoff, gn, resHalf);
                        v0 += rr2.x;
                        v1 += rr2.y;
                    } else if (epi == 2) {
                        v0 = 0.5f * v0 * (1.0f + erff(v0 * 0.7071067811865475f));
                        v1 = 0.5f * v1 * (1.0f + erff(v1 * 0.7071067811865475f));
                    }
                    if (outHalf) {
                        *(__half2*)((__half*)outp + rowoff + gn) = __floats2half2_rn(v0, v1);
                    } else {
                        *(float2*)((float*)outp + rowoff + gn) = make_float2(v0, v1);
                    }
                    acc[mi][ni][r * 2 + 0] = v0;
                    acc[mi][ni][r * 2 + 1] = v1;
                    psum += v0 + v1;
                    psq  += v0 * v0 + v1 * v1;
                }
            }
            if (epi == 3) {
                psum += __shfl_xor_sync(0xffffffffu, psum, 1);
                psum += __shfl_xor_sync(0xffffffffu, psum, 2);
                psq  += __shfl_xor_sync(0xffffffffu, psq, 1);
                psq  += __shfl_xor_sync(0xffffffffu, psq, 2);
                if (t == 0) {
                    int lr = wm + mi * 16 + g + r * 8;
                    sred[lr * 4 + (warp & 1) * 2 + 0] = psum;
                    sred[lr * 4 + (warp & 1) * 2 + 1] = psq;
                }
            }
        }
    }
    if (epi == 3) {
        __syncthreads();
#pragma unroll
        for (int mi = 0; mi < 2; mi++) {
#pragma unroll
            for (int r = 0; r < 2; r++) {
                const int gm = row0 + wm + mi * 16 + g + r * 8;
                if (gm >= M) continue;
                const size_t orow = perm ? (size_t)xcat_row(gm) : (size_t)gm;
                const int lr = wm + mi * 16 + g + r * 8;
                float sum = sred[lr * 4 + 0] + sred[lr * 4 + 2];
                float sq  = sred[lr * 4 + 1] + sred[lr * 4 + 3];
                float mean = sum * (1.f / 128.f);
                float var = sq * (1.f / 128.f) - mean * mean;
                float rstd = rsqrtf(var + 1e-5f);
#pragma unroll
                for (int ni = 0; ni < 8; ni++) {
                    const int gn = col0 + wn + ni * 8 + 2 * t;
                    float a0 = (acc[mi][ni][r * 2 + 0] - mean) * rstd * lnG[gn] + lnB[gn];
                    float a1 = (acc[mi][ni][r * 2 + 1] - mean) * rstd * lnG[gn + 1] + lnB[gn + 1];
                    *(__half2*)(out2 + orow * 128 + gn) = __floats2half2_rn(a0, a1);
                }
            }
        }
    }
}

// ============================================================================
// Merged projection GEMM: offaw (N=384, cols 0-2) + val (N=128, col 3).
// ============================================================================
__global__ __launch_bounds__(128, 4) void k_projs(const float* __restrict__ b_val)
{
    extern __shared__ __align__(1024) char sm[];
    uint32_t sb = (uint32_t)__cvta_generic_to_shared(sm);
    const int tid = threadIdx.x, lane = tid & 31, warp = tid >> 5;
    const int g = lane >> 2, t = lane & 3;
    const int wm = (warp >> 1) * 32, wn = (warp & 1) * 64;
    const int row0 = blockIdx.y * 64;

    const __half* A; const __half* W; const float* bias; __half* outp; int N; int col0;
    if (blockIdx.x < 3) {
        A = g_Qh;  W = g_Wh + WOFF_OFF; bias = g_Bcat; outp = g_OFFAWh;
        N = 384; col0 = blockIdx.x * 128;
    } else {
        A = g_XNh; W = g_Wh + WOFF_VAL; bias = b_val;  outp = g_VALh;
        N = 128; col0 = 0;
    }
    const int M = BLQ, K = CC, KT = 2;

    float acc[2][8][4];
#pragma unroll
    for (int mi = 0; mi < 2; mi++)
#pragma unroll
        for (int ni = 0; ni < 8; ni++)
#pragma unroll
            for (int r = 0; r < 4; r++) acc[mi][ni][r] = 0.f;

    gemm_load_stage(A, W, sb, 0, 0, row0, col0, M, K, tid);
    CP_COMMIT();

    for (int kt = 0; kt < KT; kt++) {
        const int s = kt & 1;
        if (kt + 1 < KT) {
            gemm_load_stage(A, W, sb, s ^ 1, kt + 1, row0, col0, M, K, tid);
            CP_COMMIT();
            CP_WAIT(1);
        } else {
            CP_WAIT(0);
        }
        __syncthreads();

        const uint32_t aS = sb + s * STG;
        const uint32_t bS = aS + 8192;
        const int rlow = lane & 15, hi = lane >> 4;
#pragma unroll
        for (int kk = 0; kk < 4; kk++) {
            uint32_t af[2][4];
#pragma unroll
            for (int mi = 0; mi < 2; mi++) {
                int r = wm + mi * 16 + rlow;
                int ck = kk * 2 + hi;
                ldm4(af[mi], aS + (uint32_t)(r * 128 + ((ck ^ (r & 7)) * 16)));
            }
            uint32_t bf[8][2];
#pragma unroll
            for (int nj = 0; nj < 4; nj++) {
                int r = wn + nj * 16 + rlow;
                int ck = kk * 2 + hi;
                uint32_t q[4];
                ldm4(q, bS + (uint32_t)(r * 128 + ((ck ^ (r & 7)) * 16)));
                bf[nj * 2 + 0][0] = q[0]; bf[nj * 2 + 0][1] = q[2];
                bf[nj * 2 + 1][0] = q[1]; bf[nj * 2 + 1][1] = q[3];
            }
#pragma unroll
            for (int mi = 0; mi < 2; mi++)
#pragma unroll
                for (int ni = 0; ni < 8; ni++)
                    mma16(acc[mi][ni], af[mi], bf[ni]);
        }
        __syncthreads();
    }

#pragma unroll
    for (int mi = 0; mi < 2; mi++) {
#pragma unroll
        for (int r = 0; r < 2; r++) {
            const int gm = row0 + wm + mi * 16 + g + r * 8;
            if (gm >= M) continue;
#pragma unroll
            for (int ni = 0; ni < 8; ni++) {
                const int gn = col0 + wn + ni * 8 + 2 * t;
                float v0 = acc[mi][ni][r * 2 + 0] + bias[gn];
                float v1 = acc[mi][ni][r * 2 + 1] + bias[gn + 1];
                *(__half2*)(outp + (size_t)gm * N + gn) = __floats2half2_rn(v0, v1);
            }
        }
    }
}

// ============================================================================
// Merged prologue: ln1 (BLQ blocks) + lvl0 (BTP blocks) + weight cvt (272).
// ============================================================================
__global__ __launch_bounds__(128) void k_pre(
    const float* __restrict__ x, const float* __restrict__ pe,
    const float* __restrict__ lp,
    const float* __restrict__ g1, const float* __restrict__ be1,
    const float* __restrict__ g2, const float* __restrict__ be2,
    const float* __restrict__ w0, const float* __restrict__ w1,
    const float* __restrict__ w2, const float* __restrict__ w3,
    const float* __restrict__ w4, const float* __restrict__ w5,
    const float* __restrict__ w6, const float* __restrict__ w7,
    const float* __restrict__ b_off, const float* __restrict__ b_attn)
{
    const int bid = blockIdx.x;
    const int c = threadIdx.x;

    if (bid < BLQ) {
        int row = bid;
        int b = row / LQ; int lq = row - b * LQ;
        int l = lq & 3; int tp = lq >> 2;
        size_t xi = ((size_t)(b * TT * PP + tp) * NLVL + (l + 1)) * CC + c;
        float v = x[xi];

        __shared__ float sh[8];
        float s = v;
        for (int o = 16; o > 0; o >>= 1) s += __shfl_xor_sync(0xffffffffu, s, o);
        if ((c & 31) == 0) sh[c >> 5] = s;
        __syncthreads();
        float mean = (sh[0] + sh[1] + sh[2] + sh[3]) * (1.f / CC);
        float dv = v - mean;
        float q2 = dv * dv;
        for (int o = 16; o > 0; o >>= 1) q2 += __shfl_xor_sync(0xffffffffu, q2, o);
        if ((c & 31) == 0) sh[4 + (c >> 5)] = q2;
        __syncthreads();
        float var = (sh[4] + sh[5] + sh[6] + sh[7]) * (1.f / CC);
        float xn = dv * rsqrtf(var + 1e-5f) * g1[c] + be1[c];
        g_XNh[(size_t)row * CC + c] = __float2half_rn(xn);
        g_Qh [(size_t)row * CC + c] = __float2half_rn(xn + pe[(size_t)lq * CC + c] + lp[(size_t)lq * CC + c]);
    } else if (bid < BLQ + BTP) {
        int btp = bid - BLQ;
        size_t rowoff = (size_t)btp * NLVL * CC;
        float v = x[rowoff + c];
        g_XCATh[rowoff + c] = __float2half_rn(v);

        __shared__ float sh2[8];
        float s = v;
        for (int o = 16; o > 0; o >>= 1) s += __shfl_xor_sync(0xffffffffu, s, o);
        if ((c & 31) == 0) sh2[c >> 5] = s;
        __syncthreads();
        float mean = (sh2[0] + sh2[1] + sh2[2] + sh2[3]) * (1.f / CC);
        float dv = v - mean;
        float q2 = dv * dv;
        for (int o = 16; o > 0; o >>= 1) q2 += __shfl_xor_sync(0xffffffffu, q2, o);
        if ((c & 31) == 0) sh2[4 + (c >> 5)] = q2;
        __syncthreads();
        float var = (sh2[4] + sh2[5] + sh2[6] + sh2[7]) * (1.f / CC);
        g_XN2h[rowoff + c] = __float2half_rn(dv * rsqrtf(var + 1e-5f) * g2[c] + be2[c]);
    } else {
        int wb = bid - BLQ - BTP;             // 0..271
        if (wb == 0 && c < 128) {
            g_Bcat[c]       = b_off[c];
            g_Bcat[c + 128] = b_off[c + 128];
            g_Bcat[c + 256] = b_attn[c];
        }
        for (int idx = wb * 128 + c; idx < WTOTAL; idx += 272 * 128) {
            const float* src; int off;
            if      (idx < WOFF_ATTN) { src = w0; off = idx; }
            else if (idx < WOFF_VAL ) { src = w1; off = idx - WOFF_ATTN; }
            else if (idx < WOFF_OUT ) { src = w2; off = idx - WOFF_VAL; }
            else if (idx < WOFF_IN  ) { src = w3; off = idx - WOFF_OUT; }
            else if (idx < WOFF_OUTW) { src = w4; off = idx - WOFF_IN; }
            else if (idx < WOFF_FC1 ) { src = w5; off = idx - WOFF_OUTW; }
            else if (idx < WOFF_FC2 ) { src = w6; off = idx - WOFF_FC1; }
            else                      { src = w7; off = idx - WOFF_FC2; }
            g_Wh[idx] = __float2half_rn(src[off]);
        }
    }
}

// ============================================================================
// Deformable sampling v4: depth-4 pipeline, 16 single-point waves, 5 buffers.
// smem: sG 5 x 4corners x 128thr x 16B = 40KB static -> 5 blocks/SM.
// ============================================================================
#define DEF_RPB 8
__global__ __launch_bounds__(128) void k_deform(const float* __restrict__ refp)
{
    __shared__ __align__(16) uint4 sG[5][4][128];   // [buf][corner][tid]
    const int row0 = blockIdx.x * DEF_RPB;
    const int tid = threadIdx.x;
    const uint32_t sgb = (uint32_t)__cvta_generic_to_shared(&sG[0][0][tid]);

    const int rr = tid >> 4;
    const int s = tid & 15;
    const int row = row0 + rr;
    const int b = row / LQ; const int lq = row - b * LQ;
    const int tp = lq >> 2; const int p = tp % PP; const int t = tp / PP;
    const int h = s >> 1, dq = s & 1;
    const float refx = refp[(((size_t)b * TT + t) * PP + p) * 2 + 0];
    const float refy = refp[(((size_t)b * TT + t) * PP + p) * 2 + 1];

    float offs[32], w[16];
    {
        const uint4* op = (const uint4*)(g_OFFAWh + (size_t)row * 384 + h * 32);
#pragma unroll
        for (int i = 0; i < 4; i++) {
            uint4 q = op[i];
            const __half2* hp = (const __half2*)&q;
#pragma unroll
            for (int j = 0; j < 4; j++) {
                float2 f = __half22float2(hp[j]);
                offs[i * 8 + 2 * j + 0] = f.x;
                offs[i * 8 + 2 * j + 1] = f.y;
            }
        }
        const uint4* ap = (const uint4*)(g_OFFAWh + (size_t)row * 384 + 256 + h * 16);
#pragma unroll
        for (int i = 0; i < 2; i++) {
            uint4 q = ap[i];
            const __half2* hp = (const __half2*)&q;
#pragma unroll
            for (int j = 0; j < 4; j++) {
                float2 f = __half22float2(hp[j]);
                w[i * 8 + 2 * j + 0] = f.x;
                w[i * 8 + 2 * j + 1] = f.y;
            }
        }
    }
    float mx = -1e30f;
#pragma unroll
    for (int i = 0; i < 16; i++) mx = fmaxf(mx, w[i]);
    float den = 0.f;
#pragma unroll
    for (int i = 0; i < 16; i++) { w[i] = __expf(w[i] - mx); den += w[i]; }
    float inv = 1.f / den;

    const __half* vbase = g_VALh + (size_t)b * LQ * CC + h * 16 + dq * 8;
    float acc[8];
#pragma unroll
    for (int j = 0; j < 8; j++) acc[j] = 0.f;

    float cw[5][4];   // [buf][corner]

    auto issue_wave = [&](int pt, int buf) {
        const int l = pt >> 2;
        float ox = offs[pt * 2 + 0];
        float oy = offs[pt * 2 + 1];
        float fx = refx * PP + ox - 0.5f;
        float fy = refy * TT + oy - 0.5f;
        float x0f = floorf(fx), y0f = floorf(fy);
        int x0 = (int)x0f, y0 = (int)y0f;
        float wx1 = fx - x0f, wy1 = fy - y0f;
        float wx0 = 1.f - wx1, wy0 = 1.f - wy1;
        bool xi0 = (x0 >= 0) && (x0 < PP);
        bool xi1 = (x0 + 1 >= 0) && (x0 + 1 < PP);
        bool yi0 = (y0 >= 0) && (y0 < TT);
        bool yi1 = (y0 + 1 >= 0) && (y0 + 1 < TT);
        float ww = w[pt];
        cw[buf][0] = wy0 * wx0 * ww;
        cw[buf][1] = wy0 * wx1 * ww;
        cw[buf][2] = wy1 * wx0 * ww;
        cw[buf][3] = wy1 * wx1 * ww;
        const uint32_t sp = sgb + (uint32_t)(buf * 4) * 2048;
        cpa16(sp        , vbase + ((size_t)(y0 * PP + x0) * LL + l) * CC,           yi0 && xi0);
        cpa16(sp + 2048 , vbase + ((size_t)(y0 * PP + x0 + 1) * LL + l) * CC,       yi0 && xi1);
        cpa16(sp + 4096 , vbase + ((size_t)((y0 + 1) * PP + x0) * LL + l) * CC,     yi1 && xi0);
        cpa16(sp + 6144 , vbase + ((size_t)((y0 + 1) * PP + x0 + 1) * LL + l) * CC, yi1 && xi1);
        CP_COMMIT();
    };
    auto reduce_wave = [&](int buf) {
#pragma unroll
        for (int c = 0; c < 4; c++) {
            uint4 q = sG[buf][c][tid];
            const __half2* hp = (const __half2*)&q;
            float ww = cw[buf][c];
#pragma unroll
            for (int j = 0; j < 4; j++) {
                float2 f = __half22float2(hp[j]);
                acc[2 * j + 0] = fmaf(f.x, ww, acc[2 * j + 0]);
                acc[2 * j + 1] = fmaf(f.y, ww, acc[2 * j + 1]);
            }
        }
    };

    // buffers cycle mod 5; waves pt use buf pt % 5
    issue_wave(0, 0);
    issue_wave(1, 1);
    issue_wave(2, 2);
    issue_wave(3, 3);
#pragma unroll
    for (int pt = 0; pt < 12; pt++) {
        issue_wave(pt + 4, (pt + 4) % 5);
        CP_WAIT(4);
        reduce_wave(pt % 5);
    }
    CP_WAIT(3); reduce_wave(12 % 5);
    CP_WAIT(2); reduce_wave(13 % 5);
    CP_WAIT(1); reduce_wave(14 % 5);
    CP_WAIT(0); reduce_wave(15 % 5);

    __half2 ho[4];
#pragma unroll
    for (int j = 0; j < 4; j++)
        ho[j] = __floats2half2_rn(acc[2 * j] * inv, acc[2 * j + 1] * inv);
    *(uint4*)(g_Oh + (size_t)row * CC + h * 16 + dq * 8) = *(uint4*)ho;
}

// ---------------- per-(bt,head) self-attention (fp16 QKV) ------------------
__global__ void k_attn()
{
    int bt = blockIdx.x, h = blockIdx.y;
    __shared__ float Qs[SS][DHH], Ks[SS][DHH], Vs[SS][DHH];
    int tid = threadIdx.x;
    for (int i = tid; i < SS * DHH; i += 128) {
        int s = i >> 4, d = i & 15;
        const __half* base = g_QKVh + ((size_t)bt * SS + s) * 384 + h * 16 + d;
        Qs[s][d] = __half2float(base[0]);
        Ks[s][d] = __half2float(base[128]);
        Vs[s][d] = __half2float(base[256]);
    }
    __syncthreads();
    if (tid < SS) {
        float qv[16];
#pragma unroll
        for (int d = 0; d < 16; d++) qv[d] = Qs[tid][d];
        float mx = -1e30f;
        for (int k = 0; k < SS; k++) {
            float sdot = 0.f;
#pragma unroll
            for (int d = 0; d < 16; d++) sdot = fmaf(qv[d], Ks[k][d], sdot);
            mx = fmaxf(mx, sdot * 0.25f);
        }
        float den = 0.f, o[16];
#pragma unroll
        for (int d = 0; d < 16; d++) o[d] = 0.f;
        for (int k = 0; k < SS; k++) {
            float sdot = 0.f;
#pragma unroll
            for (int d = 0; d < 16; d++) sdot = fmaf(qv[d], Ks[k][d], sdot);
            float e = __expf(sdot * 0.25f - mx);
            den += e;
#pragma unroll
            for (int d = 0; d < 16; d++) o[d] = fmaf(e, Vs[k][d], o[d]);
        }
        float inv = 1.f / den;
        __half* outp = g_ATTOh + ((size_t)bt * SS + tid) * CC + h * 16;
#pragma unroll
        for (int d = 0; d < 16; d++) outp[d] = __float2half_rn(o[d] * inv);
    }
}

// ---------------- host launch ----------------------------------------------
static inline void launch_small(const __half* A, const __half* W, const float* bias,
                                const void* res, void* out, int M, int N, int K,
                                int epi, int outHalf, int perm = 0, int resHalf = 0,
                                const float* lnG = nullptr, const float* lnB = nullptr,
                                __half* out2 = nullptr)
{
    dim3 grid(N / 128, (M + 63) / 64);
    k_gemm_h<<<grid, 128, GEMM_SMEM>>>(A, W, bias, res ? res : (const void*)A,
                                       out, M, N, K, epi, outHalf, perm, resHalf,
                                       lnG, lnB, out2);
}
static inline void launch_big(const __half* A, const __half* W, const float* bias,
                              const void* res, void* out, int M, int N, int K,
                              int epi, int outHalf, int resHalf = 0)
{
    dim3 grid(N / 128, (M + 127) / 128);
    k_gemm_big<<<grid, 256, BIG_SMEM>>>(A, W, bias, res ? res : (const void*)A,
                                        out, M, N, K, epi, outHalf, resHalf);
}

extern "C" void kernel_launch(void* const* d_in, const int* in_sizes, int n_in,
                              void* d_out, int out_size)
{
    (void)in_sizes; (void)n_in; (void)out_size;
    const float* x        = (const float*)d_in[0];
    const float* refp     = (const float*)d_in[1];
    const float* pe_buf   = (const float*)d_in[2];
    const float* learn_pos= (const float*)d_in[3];
    const float* w_off    = (const float*)d_in[4];
    const float* b_off    = (const float*)d_in[5];
    const float* w_attn   = (const float*)d_in[6];
    const float* b_attn   = (const float*)d_in[7];
    const float* w_val    = (const float*)d_in[8];
    const float* b_val    = (const float*)d_in[9];
    const float* w_out    = (const float*)d_in[10];
    const float* b_out    = (const float*)d_in[11];
    const float* in_w     = (const float*)d_in[12];
    const float* in_b     = (const float*)d_in[13];
    const float* out_w    = (const float*)d_in[14];
    const float* b_out2   = (const float*)d_in[15];
    const float* fc1_w    = (const float*)d_in[16];
    const float* fc1_b    = (const float*)d_in[17];
    const float* fc2_w    = (const float*)d_in[18];
    const float* fc2_b    = (const float*)d_in[19];
    const float* g1       = (const float*)d_in[20];
    const float* be1      = (const float*)d_in[21];
    const float* g2       = (const float*)d_in[22];
    const float* be2      = (const float*)d_in[23];
    const float* g3       = (const float*)d_in[24];
    const float* be3      = (const float*)d_in[25];
    float* out = (float*)d_out;

    cudaFuncSetAttribute(k_gemm_h,   cudaFuncAttributeMaxDynamicSharedMemorySize, GEMM_SMEM);
    cudaFuncSetAttribute(k_projs,    cudaFuncAttributeMaxDynamicSharedMemorySize, GEMM_SMEM);
    cudaFuncSetAttribute(k_gemm_big, cudaFuncAttributeMaxDynamicSharedMemorySize, BIG_SMEM);

    __half *pXCATh, *pXCAT2h, *pOh, *pXN2h, *pQKVh, *pATTOh, *pXN3h, *pHIDh, *pWh;
    cudaGetSymbolAddress((void**)&pXCATh,  g_XCATh);
    cudaGetSymbolAddress((void**)&pXCAT2h, g_XCAT2h);
    cudaGetSymbolAddress((void**)&pOh,     g_Oh);
    cudaGetSymbolAddress((void**)&pXN2h,   g_XN2h);
    cudaGetSymbolAddress((void**)&pQKVh,   g_QKVh);
    cudaGetSymbolAddress((void**)&pATTOh,  g_ATTOh);
    cudaGetSymbolAddress((void**)&pXN3h,   g_XN3h);
    cudaGetSymbolAddress((void**)&pHIDh,   g_HIDh);
    cudaGetSymbolAddress((void**)&pWh,     g_Wh);

    // 1) merged prologue: LN1 + lvl0(LN2) + weight cvt
    k_pre<<<BLQ + BTP + 272, 128>>>(x, pe_buf, learn_pos, g1, be1, g2, be2,
                                    w_off, w_attn, w_val, w_out, in_w, out_w,
                                    fc1_w, fc2_w, b_off, b_attn);
    // 2) merged projections: offaw (N=384) + val (N=128) -> fp16
    {
        dim3 grid(4, (BLQ + 63) / 64);
        k_projs<<<grid, 128, GEMM_SMEM>>>(b_val);
    }
    // 3) deformable sampling (depth-4 pipeline)
    k_deform<<<BLQ / DEF_RPB, 128>>>(refp);
    // 4) out-proj + residual(from x fp32, permuted) + concat + fused LN2
    //    -> XCATh (fp16) + XN2h (fp16)
    launch_small(pOh, pWh + WOFF_OUT, b_out, x, pXCATh, BLQ, 128, CC, 3, 1, 1, 0,
                 g2, be2, pXN2h);
    // 5) QKV GEMM (N=384) -> fp16  [BIG]
    launch_big(pXN2h, pWh + WOFF_IN, in_b, nullptr, pQKVh, TOK, 384, CC, 0, 1);
    // 6) self-attention
    k_attn<<<dim3(BB * TT, HH), 128>>>();
    // 7) attention out-proj + residual(XCATh fp16) + fused LN3 -> XCAT2h + XN3h
    launch_small(pATTOh, pWh + WOFF_OUTW, b_out2, pXCATh, pXCAT2h, TOK, 128, CC,
                 3, 1, 0, 1, g3, be3, pXN3h);
    // 8) FC1 + GELU (N=512) -> fp16 [BIG]
    launch_big(pXN3h, pWh + WOFF_FC1, fc1_b, nullptr, pHIDh, TOK, 512, CC, 2, 1);
    // 9) FC2 + residual(XCAT2h fp16) -> final fp32 output (K=512) [BIG]
    launch_big(pHIDh, pWh + WOFF_FC2, fc2_b, pXCAT2h, out, TOK, 128, 512, 1, 0, 1);
}